// round 7
// baseline (speedup 1.0000x reference)
#include <cuda_runtime.h>
#include <math.h>
#include <stdint.h>

// ---------------- problem constants ----------------
#define QLEN   512
#define MEMLEN 512
#define KLEN   1024
#define BSZ    8
#define NH     16
#define DH     64
#define DM     1024
#define DI     4096
#define NL     6
#define NTOK   32000
#define HD     1024
#define ROWS   (QLEN*BSZ)   // 4096
#define KROWS  (KLEN*BSZ)   // 8192
#define SCALE  0.125f

// ---------------- scratch ----------------
__device__ float g_core [ROWS  * DM];
__device__ float g_qrw  [ROWS  * DM];
__device__ float g_qrr  [ROWS  * DM];
__device__ float g_kv   [KROWS * 2 * HD];
__device__ float g_pos  [KLEN  * DM];
__device__ float g_rk   [KLEN  * DM];
__device__ float g_sc   [(size_t)BSZ * NH * QLEN * KLEN];
__device__ float g_bd   [(size_t)NH * ROWS * KLEN];
__device__ float g_vec  [ROWS * DM];
__device__ float g_tmp  [ROWS * DM];
__device__ float g_ffh  [ROWS * DI];
__device__ float g_logit[(size_t)ROWS * NTOK];

// ---------------- helpers ----------------
__device__ __forceinline__ uint32_t f2tf32(float x) {
    uint32_t r;
    asm("cvt.rna.tf32.f32 %0, %1;" : "=r"(r) : "f"(x));
    return r;
}

__device__ __forceinline__ void mma_tf32(float* d, const uint32_t* a, const uint32_t* b) {
    asm volatile(
        "mma.sync.aligned.m16n8k8.row.col.f32.tf32.tf32.f32 "
        "{%0,%1,%2,%3}, {%4,%5,%6,%7}, {%8,%9}, {%0,%1,%2,%3};\n"
        : "+f"(d[0]), "+f"(d[1]), "+f"(d[2]), "+f"(d[3])
        : "r"(a[0]), "r"(a[1]), "r"(a[2]), "r"(a[3]), "r"(b[0]), "r"(b[1]));
}

__device__ __forceinline__ void cp16(float* sdst, const float* gsrc) {
    uint32_t s = (uint32_t)__cvta_generic_to_shared(sdst);
    asm volatile("cp.async.cg.shared.global [%0], [%1], 16;\n" :: "r"(s), "l"(gsrc));
}
#define CP_COMMIT() asm volatile("cp.async.commit_group;\n")
#define CP_WAIT1()  asm volatile("cp.async.wait_group 1;\n")

// ---------------- 3xTF32 tensor-core GEMM ----------------
// CTA tile 128xNTILE, K-step 32, 2-stage cp.async double buffer.
// NTILE=128: 512 threads, 16 warps (4x4), warp tile 32x32.
// NTILE=64 : 256 threads,  8 warps (4x2), warp tile 32x32.
// TB=0: B is KxN (NN). TB=1: B is NxK (NT).
// All dims must be exact tile multiples (true for this model): no bounds checks.
// epi: 0 none, 1 +bias, 2 relu(+bias), 3 dual-out (C=acc+bias, C2=acc+bias2)
#define APITCH 36
#define SSTR   4608

template <int TB, int NTILE>
__global__ void __launch_bounds__((NTILE == 128) ? 512 : 256)
tgemm(const float* __restrict__ A, const float* __restrict__ B, float* __restrict__ C,
      int K, int lda, int ldb, int ldc,
      long sA1, long sA2, long sB1, long sB2, long sC1, long sC2, int batch2,
      const float* __restrict__ bias, int epi,
      float* __restrict__ C2, const float* __restrict__ bias2)
{
    constexpr int THREADS = (NTILE == 128) ? 512 : 256;
    constexpr int NW_N    = NTILE / 32;           // warps along n
    constexpr int BPITCH  = (TB == 0) ? ((NTILE == 128) ? 136 : 72) : APITCH;
    constexpr int ITA     = 1024 / THREADS;       // A float4s per thread
    constexpr int ITB     = (TB == 1) ? (NTILE * 8 / THREADS) : (NTILE * 8 / THREADS);
    constexpr int NQ      = NTILE / 4;            // NN quads per k-row

    extern __shared__ float sm[];
    float* const Asm[2] = { sm,            sm + SSTR };
    float* const Bsm[2] = { sm + 2 * SSTR, sm + 3 * SSTR };

    const int bz = blockIdx.z;
    const int b1 = bz / batch2, b2 = bz % batch2;
    A += (long)b1 * sA1 + (long)b2 * sA2;
    B += (long)b1 * sB1 + (long)b2 * sB2;
    C += (long)b1 * sC1 + (long)b2 * sC2;

    const int m0 = blockIdx.y * 128;
    const int n0 = blockIdx.x * NTILE;
    const int tid = threadIdx.x;
    const int warp = tid >> 5, lane = tid & 31;
    const int wm = warp / NW_N, wn = warp % NW_N;
    const int g = lane >> 2, c = lane & 3;

    float acc[2][4][4];
#pragma unroll
    for (int mt = 0; mt < 2; mt++)
#pragma unroll
        for (int nt = 0; nt < 4; nt++)
#pragma unroll
            for (int e = 0; e < 4; e++) acc[mt][nt][e] = 0.f;

    const int KT = K >> 5;

    auto issue = [&](int kt, int stage) {
        const int k0 = kt << 5;
#pragma unroll
        for (int i = 0; i < ITA; i++) {
            const int idx = tid + i * THREADS;
            const int r = idx >> 3, q = idx & 7;
            cp16(&Asm[stage][r * APITCH + q * 4],
                 A + (long)(m0 + r) * lda + k0 + q * 4);
        }
        if (TB == 1) {
#pragma unroll
            for (int i = 0; i < ITB; i++) {
                const int idx = tid + i * THREADS;
                const int r = idx >> 3, q = idx & 7;
                cp16(&Bsm[stage][r * APITCH + q * 4],
                     B + (long)(n0 + r) * ldb + k0 + q * 4);
            }
        } else {
#pragma unroll
            for (int i = 0; i < ITB; i++) {
                const int idx = tid + i * THREADS;
                const int k = idx / NQ, q = idx % NQ;
                cp16(&Bsm[stage][k * BPITCH + q * 4],
                     B + (long)(k0 + k) * ldb + n0 + q * 4);
            }
        }
    };

    issue(0, 0); CP_COMMIT();
    if (KT > 1) issue(1, 1);
    CP_COMMIT();

    for (int kt = 0; kt < KT; kt++) {
        CP_WAIT1();
        __syncthreads();
        const float* As = Asm[kt & 1];
        const float* Bs = Bsm[kt & 1];

#pragma unroll
        for (int kb8 = 0; kb8 < 4; kb8++) {
            const int kb = kb8 * 8;
            uint32_t afh[2][4], afl[2][4], bfh[4][2], bfl[4][2];
#pragma unroll
            for (int mt = 0; mt < 2; mt++) {
                const int r0 = wm * 32 + mt * 16 + g;
                float x0 = As[r0 * APITCH + kb + c];
                float x1 = As[(r0 + 8) * APITCH + kb + c];
                float x2 = As[r0 * APITCH + kb + c + 4];
                float x3 = As[(r0 + 8) * APITCH + kb + c + 4];
                uint32_t h0 = f2tf32(x0), h1 = f2tf32(x1), h2 = f2tf32(x2), h3 = f2tf32(x3);
                afh[mt][0] = h0; afh[mt][1] = h1; afh[mt][2] = h2; afh[mt][3] = h3;
                afl[mt][0] = f2tf32(x0 - __uint_as_float(h0));
                afl[mt][1] = f2tf32(x1 - __uint_as_float(h1));
                afl[mt][2] = f2tf32(x2 - __uint_as_float(h2));
                afl[mt][3] = f2tf32(x3 - __uint_as_float(h3));
            }
#pragma unroll
            for (int nt = 0; nt < 4; nt++) {
                const int rn = wn * 32 + nt * 8 + g;
                float y0, y1;
                if (TB == 1) {
                    y0 = Bs[rn * APITCH + kb + c];
                    y1 = Bs[rn * APITCH + kb + c + 4];
                } else {
                    y0 = Bs[(kb + c) * BPITCH + rn];
                    y1 = Bs[(kb + c + 4) * BPITCH + rn];
                }
                uint32_t h0 = f2tf32(y0), h1 = f2tf32(y1);
                bfh[nt][0] = h0; bfh[nt][1] = h1;
                bfl[nt][0] = f2tf32(y0 - __uint_as_float(h0));
                bfl[nt][1] = f2tf32(y1 - __uint_as_float(h1));
            }
#pragma unroll
            for (int mt = 0; mt < 2; mt++)
#pragma unroll
                for (int nt = 0; nt < 4; nt++) {
                    mma_tf32(acc[mt][nt], afh[mt], bfh[nt]);
                    mma_tf32(acc[mt][nt], afh[mt], bfl[nt]);
                    mma_tf32(acc[mt][nt], afl[mt], bfh[nt]);
                }
        }
        __syncthreads();
        if (kt + 2 < KT) issue(kt + 2, kt & 1);
        CP_COMMIT();
    }

    // ---- epilogue (no bounds checks: exact multiples) ----
#pragma unroll
    for (int mt = 0; mt < 2; mt++) {
        const int row0 = m0 + wm * 32 + mt * 16 + g;
#pragma unroll
        for (int nt = 0; nt < 4; nt++) {
            const int col = n0 + wn * 32 + nt * 8 + c * 2;
            if (epi == 3) {
                float b0 = bias[col],  b1v = bias[col + 1];
                float d0 = bias2[col], d1v = bias2[col + 1];
#pragma unroll
                for (int half = 0; half < 2; half++) {
                    const int row = row0 + half * 8;
                    float2 o1 = { acc[mt][nt][half * 2] + b0,  acc[mt][nt][half * 2 + 1] + b1v };
                    float2 o2 = { acc[mt][nt][half * 2] + d0,  acc[mt][nt][half * 2 + 1] + d1v };
                    *(float2*)(C  + (long)row * ldc + col) = o1;
                    *(float2*)(C2 + (long)row * ldc + col) = o2;
                }
            } else {
                float b0 = 0.f, b1v = 0.f;
                if (epi >= 1) { b0 = bias[col]; b1v = bias[col + 1]; }
#pragma unroll
                for (int half = 0; half < 2; half++) {
                    const int row = row0 + half * 8;
                    float v0 = acc[mt][nt][half * 2 + 0] + b0;
                    float v1 = acc[mt][nt][half * 2 + 1] + b1v;
                    if (epi == 2) { v0 = fmaxf(v0, 0.f); v1 = fmaxf(v1, 0.f); }
                    float2 o = {v0, v1};
                    *(float2*)(C + (long)row * ldc + col) = o;
                }
            }
        }
    }
}

// ---------------- element-wise / reduction kernels ----------------

__global__ void embed_kernel(const int* __restrict__ data, const float* __restrict__ embW,
                             float* __restrict__ core)
{
    long idx = (long)blockIdx.x * 256 + threadIdx.x;
    if (idx >= (long)ROWS * DM) return;
    int r = (int)(idx >> 10), d = (int)(idx & 1023);
    core[idx] = embW[(long)data[r] * DM + d];
}

__global__ void pos_kernel(float* __restrict__ pos)
{
    long idx = (long)blockIdx.x * 256 + threadIdx.x;
    if (idx >= (long)KLEN * DM) return;
    int j = (int)(idx >> 10), d = (int)(idx & 1023);
    float p = (float)(KLEN - 1 - j);
    int t = (d < 512) ? d : d - 512;
    float invf = expf(-((2.0f * (float)t) / (float)DM) * logf(10000.0f));
    float a = p * invf;
    pos[idx] = (d < 512) ? sinf(a) : cosf(a);
}

__global__ void attn_softmax_kernel(float* __restrict__ sc, const float* __restrict__ bd)
{
    const int i = blockIdx.x, n = blockIdx.y, b = blockIdx.z;
    const int t = threadIdx.x;
    float* row = sc + ((((long)b * NH + n) * QLEN + i) * KLEN);
    const float* bdr = bd + (((long)n * ROWS + (i * BSZ + b)) * KLEN);
    const int limit = i + MEMLEN;
    const int shift = QLEN - 1 - i;

    __shared__ float red[256];
    float v[4];
    float m = -1e30f;
#pragma unroll
    for (int k = 0; k < 4; k++) {
        int j = t + k * 256;
        float x = -1e30f;
        if (j <= limit) x = (row[j] + bdr[j + shift]) * SCALE;
        v[k] = x;
        m = fmaxf(m, x);
    }
    red[t] = m; __syncthreads();
    for (int o = 128; o > 0; o >>= 1) { if (t < o) red[t] = fmaxf(red[t], red[t + o]); __syncthreads(); }
    const float M = red[0];
    __syncthreads();

    float s = 0.f;
#pragma unroll
    for (int k = 0; k < 4; k++) { float e = expf(v[k] - M); v[k] = e; s += e; }
    red[t] = s; __syncthreads();
    for (int o = 128; o > 0; o >>= 1) { if (t < o) red[t] += red[t + o]; __syncthreads(); }
    const float inv = 1.0f / red[0];
#pragma unroll
    for (int k = 0; k < 4; k++) row[t + k * 256] = v[k] * inv;
}

__global__ void ln_kernel(const float* __restrict__ x, const float* __restrict__ y,
                          const float* __restrict__ g, const float* __restrict__ b,
                          float* __restrict__ out)
{
    const int r = blockIdx.x, t = threadIdx.x;
    __shared__ float red[256];
    const float* xr = x + (long)r * DM;
    const float* yr = y + (long)r * DM;
    float loc[4];
    float s = 0.f;
#pragma unroll
    for (int k = 0; k < 4; k++) { float v = xr[t + k * 256] + yr[t + k * 256]; loc[k] = v; s += v; }
    red[t] = s; __syncthreads();
    for (int o = 128; o > 0; o >>= 1) { if (t < o) red[t] += red[t + o]; __syncthreads(); }
    const float mu = red[0] * (1.0f / DM);
    __syncthreads();
    float s2 = 0.f;
#pragma unroll
    for (int k = 0; k < 4; k++) { float d = loc[k] - mu; s2 += d * d; }
    red[t] = s2; __syncthreads();
    for (int o = 128; o > 0; o >>= 1) { if (t < o) red[t] += red[t + o]; __syncthreads(); }
    const float rstd = rsqrtf(red[0] * (1.0f / DM) + 1e-5f);
#pragma unroll
    for (int k = 0; k < 4; k++) {
        int d = t + k * 256;
        out[(long)r * DM + d] = (loc[k] - mu) * rstd * g[d] + b[d];
    }
}

// single-pass online logsumexp loss
__global__ void loss_kernel(const float* __restrict__ logits, const int* __restrict__ target,
                            float* __restrict__ out)
{
    const int r = blockIdx.x, t = threadIdx.x;
    __shared__ float rm[256], rs[256];
    const float* lr = logits + (long)r * NTOK;
    float m = -1e30f, s = 0.f;
    for (int j = t; j < NTOK; j += 256) {
        float x = lr[j];
        if (x > m) { s = s * expf(m - x) + 1.f; m = x; }
        else       { s += expf(x - m); }
    }
    rm[t] = m; rs[t] = s; __syncthreads();
    for (int o = 128; o > 0; o >>= 1) {
        if (t < o) {
            float m2 = rm[t + o], s2 = rs[t + o];
            float M = fmaxf(rm[t], m2);
            rs[t] = rs[t] * expf(rm[t] - M) + s2 * expf(m2 - M);
            rm[t] = M;
        }
        __syncthreads();
    }
    if (t == 0) out[r] = (logf(rs[0]) + rm[0]) - lr[target[r]];
}

// ---------------- host orchestration ----------------

#define SMEM_GEMM (4 * SSTR * 4)   // 73728 bytes

static inline dim3 gt(int N, int M, int bz, int ntile) {
    return dim3(N / ntile, M / 128, bz);
}

extern "C" void kernel_launch(void* const* d_in, const int* in_sizes, int n_in,
                              void* d_out, int out_size)
{
    const int*   data   = (const int*)  d_in[0];
    const int*   target = (const int*)  d_in[1];
    const float* memory = (const float*)d_in[2];
    const float* embW   = (const float*)d_in[3];
    const float* rwb    = (const float*)d_in[4];
    const float* rrb    = (const float*)d_in[5];
    const float* Wq     = (const float*)d_in[6];
    const float* Wkv    = (const float*)d_in[7];
    const float* Wr     = (const float*)d_in[8];
    const float* Wo     = (const float*)d_in[9];
    const float* W1     = (const float*)d_in[10];
    const float* b1     = (const float*)d_in[11];
    const float* W2     = (const float*)d_in[12];
    const float* b2     = (const float*)d_in[13];
    const float* ln1g   = (const float*)d_in[14];
    const float* ln1b   = (const float*)d_in[15];
    const float* ln2g   = (const float*)d_in[16];
    const float* ln2b   = (const float*)d_in[17];

    float* out      = (float*)d_out;
    float* out_loss = out;
    float* out_mems = out + ROWS;

    float *core, *qrw, *qrr, *kv, *pos, *rk, *sc, *bd, *vec, *tmp, *ffh, *logit;
    cudaGetSymbolAddress((void**)&core,  g_core);
    cudaGetSymbolAddress((void**)&qrw,   g_qrw);
    cudaGetSymbolAddress((void**)&qrr,   g_qrr);
    cudaGetSymbolAddress((void**)&kv,    g_kv);
    cudaGetSymbolAddress((void**)&pos,   g_pos);
    cudaGetSymbolAddress((void**)&rk,    g_rk);
    cudaGetSymbolAddress((void**)&sc,    g_sc);
    cudaGetSymbolAddress((void**)&bd,    g_bd);
    cudaGetSymbolAddress((void**)&vec,   g_vec);
    cudaGetSymbolAddress((void**)&tmp,   g_tmp);
    cudaGetSymbolAddress((void**)&ffh,   g_ffh);
    cudaGetSymbolAddress((void**)&logit, g_logit);

    cudaFuncSetAttribute(tgemm<0,128>, cudaFuncAttributeMaxDynamicSharedMemorySize, SMEM_GEMM);
    cudaFuncSetAttribute(tgemm<1,128>, cudaFuncAttributeMaxDynamicSharedMemorySize, SMEM_GEMM);
    cudaFuncSetAttribute(tgemm<0,64>,  cudaFuncAttributeMaxDynamicSharedMemorySize, SMEM_GEMM);

    const size_t coreBytes = (size_t)ROWS * DM * sizeof(float);

    embed_kernel<<<(ROWS * DM + 255) / 256, 256>>>(data, embW, core);
    pos_kernel  <<<(KLEN * DM + 255) / 256, 256>>>(pos);

    cudaMemcpyAsync(out_mems, core, coreBytes, cudaMemcpyDeviceToDevice);

    for (int l = 0; l < NL; l++) {
        const float* Wkvl = Wkv + (size_t)l * DM * 2 * HD;

        // kv rows [0,4096): from memory[l];  rows [4096,8192): from core
        tgemm<0,128><<<gt(2*HD, ROWS, 1, 128), 512, SMEM_GEMM>>>(
            memory + (size_t)l * ROWS * DM, Wkvl, kv,
            DM, DM, 2*HD, 2*HD, 0,0,0,0,0,0, 1, nullptr, 0, nullptr, nullptr);
        tgemm<0,128><<<gt(2*HD, ROWS, 1, 128), 512, SMEM_GEMM>>>(
            core, Wkvl, kv + (size_t)ROWS * 2 * HD,
            DM, DM, 2*HD, 2*HD, 0,0,0,0,0,0, 1, nullptr, 0, nullptr, nullptr);

        // qrw / qrr = core @ Wq + {rwb, rrb}  (dual-output epilogue)
        tgemm<0,128><<<gt(HD, ROWS, 1, 128), 512, SMEM_GEMM>>>(
            core, Wq + (size_t)l * DM * HD, qrw,
            DM, DM, HD, HD, 0,0,0,0,0,0, 1, rwb, 3, qrr, rrb);

        // r_k = pos @ Wr
        tgemm<0,128><<<gt(HD, KLEN, 1, 128), 512, SMEM_GEMM>>>(
            pos, Wr + (size_t)l * DM * HD, rk,
            DM, DM, HD, HD, 0,0,0,0,0,0, 1, nullptr, 0, nullptr, nullptr);

        // AC (NT, batched over b*n)
        tgemm<1,128><<<gt(KLEN, QLEN, BSZ*NH, 128), 512, SMEM_GEMM>>>(
            qrw, kv, sc,
            DH, BSZ * DM, BSZ * 2 * HD, KLEN,
            (long)DM, (long)DH,
            (long)2 * HD, (long)DH,
            (long)NH * QLEN * KLEN, (long)QLEN * KLEN,
            NH, nullptr, 0, nullptr, nullptr);

        // BD raw (NT, batched over n)
        tgemm<1,128><<<gt(KLEN, ROWS, NH, 128), 512, SMEM_GEMM>>>(
            qrr, rk, bd,
            DH, DM, DM, KLEN,
            0, (long)DH,
            0, (long)DH,
            0, (long)ROWS * KLEN,
            NH, nullptr, 0, nullptr, nullptr);

        attn_softmax_kernel<<<dim3(QLEN, NH, BSZ), 256>>>(sc, bd);

        // PV (NN, N=64 tiles, batched over b*n)
        tgemm<0,64><<<gt(DH, QLEN, BSZ*NH, 64), 256, SMEM_GEMM>>>(
            sc, kv + HD, vec,
            KLEN, KLEN, BSZ * 2 * HD, BSZ * DM,
            (long)NH * QLEN * KLEN, (long)QLEN * KLEN,
            (long)2 * HD, (long)DH,
            (long)DM, (long)DH,
            NH, nullptr, 0, nullptr, nullptr);

        // attn_out = vec @ Wo
        tgemm<0,128><<<gt(DM, ROWS, 1, 128), 512, SMEM_GEMM>>>(
            vec, Wo + (size_t)l * HD * DM, tmp,
            HD, HD, DM, DM, 0,0,0,0,0,0, 1, nullptr, 0, nullptr, nullptr);
        ln_kernel<<<ROWS, 256>>>(core, tmp, ln1g + (size_t)l * DM, ln1b + (size_t)l * DM, core);

        // ffh = relu(core @ W1 + b1)
        tgemm<0,128><<<gt(DI, ROWS, 1, 128), 512, SMEM_GEMM>>>(
            core, W1 + (size_t)l * DM * DI, ffh,
            DM, DM, DI, DI, 0,0,0,0,0,0, 1, b1 + (size_t)l * DI, 2, nullptr, nullptr);
        // ff_out = ffh @ W2 + b2
        tgemm<0,128><<<gt(DM, ROWS, 1, 128), 512, SMEM_GEMM>>>(
            ffh, W2 + (size_t)l * DI * DM, tmp,
            DI, DI, DM, DM, 0,0,0,0,0,0, 1, b2 + (size_t)l * DM, 1, nullptr, nullptr);
        ln_kernel<<<ROWS, 256>>>(core, tmp, ln2g + (size_t)l * DM, ln2b + (size_t)l * DM, core);

        if (l < NL - 1)
            cudaMemcpyAsync(out_mems + (size_t)(l + 1) * ROWS * DM, core, coreBytes,
                            cudaMemcpyDeviceToDevice);
    }

    // logits = core @ emb_W^T
    tgemm<1,128><<<gt(NTOK, ROWS, 1, 128), 512, SMEM_GEMM>>>(
        core, embW, logit,
        DM, DM, DM, NTOK, 0,0,0,0,0,0, 1, nullptr, 0, nullptr, nullptr);
    loss_kernel<<<ROWS, 256>>>(logit, target, out_loss);

    (void)in_sizes; (void)n_in; (void)out_size;
}

// round 8
// speedup vs baseline: 3.1122x; 3.1122x over previous
#include <cuda_runtime.h>
#include <cuda_bf16.h>
#include <math.h>
#include <stdint.h>

typedef __nv_bfloat16 bf16;
typedef __nv_bfloat162 bf162;
typedef uint32_t u32;

#define QLEN 512
#define MEMLEN 512
#define KLEN 1024
#define BSZ 8
#define NH 16
#define DH 64
#define DM 1024
#define DI 4096
#define NL 6
#define NTOK 32000
#define HD 1024
#define ROWS (QLEN*BSZ)
#define KROWS (KLEN*BSZ)
#define SCALE 0.125f

// ---------------- fp32 scratch ----------------
__device__ float g_core [ROWS*DM];
__device__ float g_tmp  [ROWS*DM];
__device__ float g_vtmp [KROWS*HD];
__device__ float g_sc   [(size_t)BSZ*NH*QLEN*KLEN];
__device__ float g_bd   [(size_t)NH*ROWS*KLEN];
__device__ float g_logit[(size_t)ROWS*NTOK];

// ---------------- bf16 hi/lo pair scratch ----------------
#define PAIR(name, n) __device__ bf16 h_##name[n]; __device__ bf16 l_##name[n];
PAIR(core, ROWS*DM)
PAIR(mem,  (size_t)NL*ROWS*DM)
PAIR(qrw,  ROWS*DM)
PAIR(qrr,  ROWS*DM)
PAIR(kk,   KROWS*HD)
PAIR(vT,   (size_t)BSZ*NH*DH*KLEN)
PAIR(rk,   KLEN*HD)
PAIR(prob, (size_t)BSZ*NH*QLEN*KLEN)
PAIR(vec,  ROWS*HD)
PAIR(ffh,  (size_t)ROWS*DI)
PAIR(pos,  KLEN*DM)
PAIR(emb,  (size_t)NTOK*DM)
PAIR(WkvT, (size_t)NL*2*HD*DM)
PAIR(WqT,  (size_t)NL*HD*DM)
PAIR(WrT,  (size_t)NL*HD*DM)
PAIR(WoT,  (size_t)NL*DM*HD)
PAIR(W1T,  (size_t)NL*DI*DM)
PAIR(W2T,  (size_t)NL*DM*DI)

// ---------------- helpers ----------------
__device__ __forceinline__ void mma_bf16(float* d, const u32* a, const u32* b) {
    asm volatile(
        "mma.sync.aligned.m16n8k16.row.col.f32.bf16.bf16.f32 "
        "{%0,%1,%2,%3}, {%4,%5,%6,%7}, {%8,%9}, {%0,%1,%2,%3};\n"
        : "+f"(d[0]), "+f"(d[1]), "+f"(d[2]), "+f"(d[3])
        : "r"(a[0]), "r"(a[1]), "r"(a[2]), "r"(a[3]), "r"(b[0]), "r"(b[1]));
}
#define LDSM4(r0,r1,r2,r3,addr) \
    asm volatile("ldmatrix.sync.aligned.m8n8.x4.shared.b16 {%0,%1,%2,%3}, [%4];" \
        : "=r"(r0), "=r"(r1), "=r"(r2), "=r"(r3) : "r"(addr))
__device__ __forceinline__ void cp16s(u32 sdst, const void* g) {
    asm volatile("cp.async.cg.shared.global [%0], [%1], 16;\n" :: "r"(sdst), "l"(g));
}
#define CP_COMMIT() asm volatile("cp.async.commit_group;\n")
#define CP_WAIT1()  asm volatile("cp.async.wait_group 1;\n")

__device__ __forceinline__ void pairstore(bf16* H, bf16* L, long off, float v0, float v1) {
    bf16 h0 = __float2bfloat16(v0), h1 = __float2bfloat16(v1);
    bf162 hh; hh.x = h0; hh.y = h1;
    bf162 ll; ll.x = __float2bfloat16(v0 - __bfloat162float(h0));
              ll.y = __float2bfloat16(v1 - __bfloat162float(h1));
    *(bf162*)(H + off) = hh;
    *(bf162*)(L + off) = ll;
}

// ---------------- pair-bf16 NT GEMM ----------------
// C[M,N] = A[M,K] * B[N,K]^T with A,B given as hi/lo bf16 arrays (same strides).
// CTA 128 x NTILE, warp tile 64x32, K-step 32, 2-stage cp.async.
// EPI: 0 fp32  1 fp32+bias  2 pair relu(+bias)  3 dual pair(+bias/+bias2)
//      4 pair  6 kv-split (n0<HD: pair ; else fp32 Cf2 at col-HD)
template <int NTILE, int EPI>
__global__ void __launch_bounds__(NTILE == 128 ? 256 : 128, 2)
pgemm(const bf16* __restrict__ Ah, const bf16* __restrict__ Al,
      const bf16* __restrict__ Bh, const bf16* __restrict__ Bl,
      int K, int lda, int ldb,
      long sA1, long sA2, long sB1, long sB2, int batch2,
      int ldc, long sC1, long sC2,
      float* __restrict__ Cf,
      bf16* __restrict__ Ch, bf16* __restrict__ Cl,
      bf16* __restrict__ Ch2, bf16* __restrict__ Cl2,
      const float* __restrict__ bias, const float* __restrict__ bias2,
      float* __restrict__ Cf2, int ldc2)
{
    constexpr int T    = (NTILE == 128) ? 256 : 128;
    constexpr int ASTB = 128 * 144;
    constexpr int BSTB = NTILE * 144;
    extern __shared__ char smraw[];
    const u32 smS = (u32)__cvta_generic_to_shared(smraw);

    const int bz = blockIdx.z;
    const int b1 = bz / batch2, b2 = bz % batch2;
    Ah += b1 * sA1 + b2 * sA2;  Al += b1 * sA1 + b2 * sA2;
    Bh += b1 * sB1 + b2 * sB2;  Bl += b1 * sB1 + b2 * sB2;
    const long cOff = b1 * sC1 + b2 * sC2;

    const int m0 = blockIdx.y * 128, n0 = blockIdx.x * NTILE;
    const int tid = threadIdx.x, warp = tid >> 5, lane = tid & 31;
    constexpr int NWN = NTILE / 32;
    const int wm = warp / NWN, wn = warp % NWN;

    float acc[4][4][4];
#pragma unroll
    for (int mt = 0; mt < 4; mt++)
#pragma unroll
        for (int nt = 0; nt < 4; nt++)
#pragma unroll
            for (int e = 0; e < 4; e++) acc[mt][nt][e] = 0.f;

    const int KT = K >> 5;

    auto issue = [&](int kt, int st) {
        const int k0 = kt << 5;
        const u32 aB = smS + st * ASTB;
        const u32 bB = smS + 2 * ASTB + st * BSTB;
#pragma unroll
        for (int i = 0; i < 1024 / T; i++) {
            int idx = tid + i * T, r = idx >> 3, q = idx & 7;
            const bf16* src = (q < 4) ? (Ah + (long)(m0 + r) * lda + k0 + q * 8)
                                      : (Al + (long)(m0 + r) * lda + k0 + (q - 4) * 8);
            cp16s(aB + r * 144 + q * 16, src);
        }
#pragma unroll
        for (int i = 0; i < NTILE * 8 / T; i++) {
            int idx = tid + i * T, r = idx >> 3, q = idx & 7;
            const bf16* src = (q < 4) ? (Bh + (long)(n0 + r) * ldb + k0 + q * 8)
                                      : (Bl + (long)(n0 + r) * ldb + k0 + (q - 4) * 8);
            cp16s(bB + r * 144 + q * 16, src);
        }
    };

    // per-lane ldmatrix base offsets
    const u32 aLane = (u32)((lane & 15) * 144 + (lane >> 4) * 16);
    const u32 bLane = (u32)(((lane >> 4) * 8 + (lane & 7)) * 144 + ((lane >> 3) & 1) * 16);

    issue(0, 0); CP_COMMIT();
    if (KT > 1) issue(1, 1);
    CP_COMMIT();

    for (int kt = 0; kt < KT; kt++) {
        CP_WAIT1();
        __syncthreads();
        const u32 As = smS + (kt & 1) * ASTB + wm * 64 * 144 + aLane;
        const u32 Bs = smS + 2 * ASTB + (kt & 1) * BSTB + wn * 32 * 144 + bLane;

#pragma unroll
        for (int g = 0; g < 2; g++) {
            u32 ah[4][4], alr[4][4], bh[4][2], blr[4][2];
#pragma unroll
            for (int mt = 0; mt < 4; mt++) {
                const u32 ad = As + mt * 2304 + g * 32;
                LDSM4(ah[mt][0], ah[mt][1], ah[mt][2], ah[mt][3], ad);
                LDSM4(alr[mt][0], alr[mt][1], alr[mt][2], alr[mt][3], ad + 64);
            }
#pragma unroll
            for (int p = 0; p < 2; p++) {
                const u32 bd_ = Bs + p * 2304 + g * 32;
                LDSM4(bh[2*p][0], bh[2*p][1], bh[2*p+1][0], bh[2*p+1][1], bd_);
                LDSM4(blr[2*p][0], blr[2*p][1], blr[2*p+1][0], blr[2*p+1][1], bd_ + 64);
            }
#pragma unroll
            for (int mt = 0; mt < 4; mt++)
#pragma unroll
                for (int nt = 0; nt < 4; nt++) {
                    mma_bf16(acc[mt][nt], ah[mt], bh[nt]);
                    mma_bf16(acc[mt][nt], ah[mt], blr[nt]);
                    mma_bf16(acc[mt][nt], alr[mt], bh[nt]);
                }
        }
        __syncthreads();
        if (kt + 2 < KT) issue(kt + 2, kt & 1);
        CP_COMMIT();
    }

    // ---- epilogue ----
    const int gl = lane >> 2, c2 = (lane & 3) * 2;
#pragma unroll
    for (int mt = 0; mt < 4; mt++)
#pragma unroll
        for (int nt = 0; nt < 4; nt++)
#pragma unroll
            for (int h = 0; h < 2; h++) {
                const int row = m0 + wm * 64 + mt * 16 + gl + h * 8;
                const int col = n0 + wn * 32 + nt * 8 + c2;
                float v0 = acc[mt][nt][h*2], v1 = acc[mt][nt][h*2+1];
                const long off = (long)row * ldc + col + cOff;
                if (EPI == 0) {
                    float2 o = make_float2(v0, v1);
                    *(float2*)(Cf + off) = o;
                } else if (EPI == 1) {
                    float2 o = make_float2(v0 + bias[col], v1 + bias[col+1]);
                    *(float2*)(Cf + off) = o;
                } else if (EPI == 2) {
                    pairstore(Ch, Cl, off, fmaxf(v0 + bias[col], 0.f), fmaxf(v1 + bias[col+1], 0.f));
                } else if (EPI == 3) {
                    pairstore(Ch,  Cl,  off, v0 + bias[col],  v1 + bias[col+1]);
                    pairstore(Ch2, Cl2, off, v0 + bias2[col], v1 + bias2[col+1]);
                } else if (EPI == 4) {
                    pairstore(Ch, Cl, off, v0, v1);
                } else {  // 6: kv split
                    if (n0 < HD) pairstore(Ch, Cl, (long)row * ldc + col, v0, v1);
                    else {
                        float2 o = make_float2(v0, v1);
                        *(float2*)(Cf2 + (long)row * ldc2 + (col - HD)) = o;
                    }
                }
            }
}

// ---------------- converters ----------------

// fp32 [R][C] -> pair [C][R]
__global__ void transpose_pair(const float* __restrict__ in, bf16* __restrict__ oh,
                               bf16* __restrict__ ol, int R, int C)
{
    __shared__ float t[32][33];
    const int c0 = blockIdx.x * 32, r0 = blockIdx.y * 32;
    for (int i = threadIdx.y; i < 32; i += 8)
        t[i][threadIdx.x] = in[(long)(r0 + i) * C + c0 + threadIdx.x];
    __syncthreads();
    for (int i = threadIdx.y; i < 32; i += 8) {
        float x = t[threadIdx.x][i];
        bf16 h = __float2bfloat16(x);
        long o = (long)(c0 + i) * R + r0 + threadIdx.x;
        oh[o] = h;
        ol[o] = __float2bfloat16(x - __bfloat162float(h));
    }
}

__global__ void convert_pair(const float* __restrict__ in, bf16* __restrict__ oh,
                             bf16* __restrict__ ol, long n)
{
    long i = (long)blockIdx.x * 256 + threadIdx.x;
    if (i >= n) return;
    float x = in[i];
    bf16 h = __float2bfloat16(x);
    oh[i] = h;
    ol[i] = __float2bfloat16(x - __bfloat162float(h));
}

// v fp32 [j*BSZ+b][n*64+d] -> pair [(b*NH+n)][d][j]
__global__ void vtrans_kernel(const float* __restrict__ v, bf16* __restrict__ oh,
                              bf16* __restrict__ ol)
{
    __shared__ float t[32][33];
    const int bn = blockIdx.z, b = bn >> 4, n = bn & 15;
    const int j0 = blockIdx.x * 32, d0 = blockIdx.y * 32;
    for (int i = threadIdx.y; i < 32; i += 8)
        t[i][threadIdx.x] = v[((long)(j0 + i) * BSZ + b) * HD + n * 64 + d0 + threadIdx.x];
    __syncthreads();
    for (int i = threadIdx.y; i < 32; i += 8) {
        float x = t[threadIdx.x][i];
        bf16 h = __float2bfloat16(x);
        long o = ((long)bn * DH + d0 + i) * KLEN + j0 + threadIdx.x;
        oh[o] = h;
        ol[o] = __float2bfloat16(x - __bfloat162float(h));
    }
}

// ---------------- elementwise / reductions ----------------

__global__ void embed_kernel(const int* __restrict__ data, const float* __restrict__ embW,
                             float* __restrict__ core, bf16* __restrict__ ch, bf16* __restrict__ cl)
{
    long idx = (long)blockIdx.x * 256 + threadIdx.x;
    if (idx >= (long)ROWS * DM) return;
    int r = (int)(idx >> 10), d = (int)(idx & 1023);
    float x = embW[(long)data[r] * DM + d];
    core[idx] = x;
    bf16 h = __float2bfloat16(x);
    ch[idx] = h;
    cl[idx] = __float2bfloat16(x - __bfloat162float(h));
}

__global__ void pos_kernel(bf16* __restrict__ ph, bf16* __restrict__ pl)
{
    long idx = (long)blockIdx.x * 256 + threadIdx.x;
    if (idx >= (long)KLEN * DM) return;
    int j = (int)(idx >> 10), d = (int)(idx & 1023);
    float p = (float)(KLEN - 1 - j);
    int t = (d < 512) ? d : d - 512;
    float invf = expf(-((2.0f * (float)t) / (float)DM) * logf(10000.0f));
    float a = p * invf;
    float x = (d < 512) ? sinf(a) : cosf(a);
    bf16 h = __float2bfloat16(x);
    ph[idx] = h;
    pl[idx] = __float2bfloat16(x - __bfloat162float(h));
}

// softmax over j of mask((AC + shifted BD)*SCALE); writes pair prob
__global__ void attn_softmax_kernel(const float* __restrict__ sc, const float* __restrict__ bd,
                                    bf16* __restrict__ ph, bf16* __restrict__ pl)
{
    const int i = blockIdx.x, n = blockIdx.y, b = blockIdx.z;
    const int t = threadIdx.x;
    const long rbase = (((long)b * NH + n) * QLEN + i) * KLEN;
    const float* row = sc + rbase;
    const float* bdr = bd + (((long)n * ROWS + (i * BSZ + b)) * KLEN);
    const int limit = i + MEMLEN;
    const int shift = QLEN - 1 - i;

    __shared__ float red[256];
    float v[4];
    float m = -1e30f;
#pragma unroll
    for (int k = 0; k < 4; k++) {
        int j = t + k * 256;
        float x = -1e30f;
        if (j <= limit) x = (row[j] + bdr[j + shift]) * SCALE;
        v[k] = x;
        m = fmaxf(m, x);
    }
    red[t] = m; __syncthreads();
    for (int o = 128; o > 0; o >>= 1) { if (t < o) red[t] = fmaxf(red[t], red[t + o]); __syncthreads(); }
    const float M = red[0];
    __syncthreads();
    float s = 0.f;
#pragma unroll
    for (int k = 0; k < 4; k++) { float e = expf(v[k] - M); v[k] = e; s += e; }
    red[t] = s; __syncthreads();
    for (int o = 128; o > 0; o >>= 1) { if (t < o) red[t] += red[t + o]; __syncthreads(); }
    const float inv = 1.0f / red[0];
#pragma unroll
    for (int k = 0; k < 4; k++) {
        int j = t + k * 256;
        float x = v[k] * inv;
        bf16 h = __float2bfloat16(x);
        ph[rbase + j] = h;
        pl[rbase + j] = __float2bfloat16(x - __bfloat162float(h));
    }
}

// out = LN(x+y)*g+b  -> fp32 + pair
__global__ void ln_kernel(const float* __restrict__ x, const float* __restrict__ y,
                          const float* __restrict__ g, const float* __restrict__ b,
                          float* __restrict__ outf, bf16* __restrict__ oh, bf16* __restrict__ ol)
{
    const int r = blockIdx.x, t = threadIdx.x;
    __shared__ float red[256];
    const float* xr = x + (long)r * DM;
    const float* yr = y + (long)r * DM;
    float loc[4];
    float s = 0.f;
#pragma unroll
    for (int k = 0; k < 4; k++) { float v = xr[t + k*256] + yr[t + k*256]; loc[k] = v; s += v; }
    red[t] = s; __syncthreads();
    for (int o = 128; o > 0; o >>= 1) { if (t < o) red[t] += red[t + o]; __syncthreads(); }
    const float mu = red[0] * (1.0f / DM);
    __syncthreads();
    float s2 = 0.f;
#pragma unroll
    for (int k = 0; k < 4; k++) { float d = loc[k] - mu; s2 += d * d; }
    red[t] = s2; __syncthreads();
    for (int o = 128; o > 0; o >>= 1) { if (t < o) red[t] += red[t + o]; __syncthreads(); }
    const float rstd = rsqrtf(red[0] * (1.0f / DM) + 1e-5f);
#pragma unroll
    for (int k = 0; k < 4; k++) {
        int d = t + k * 256;
        float v = (loc[k] - mu) * rstd * g[d] + b[d];
        long o = (long)r * DM + d;
        outf[o] = v;
        bf16 h = __float2bfloat16(v);
        oh[o] = h;
        ol[o] = __float2bfloat16(v - __bfloat162float(h));
    }
}

__global__ void loss_kernel(const float* __restrict__ logits, const int* __restrict__ target,
                            float* __restrict__ out)
{
    const int r = blockIdx.x, t = threadIdx.x;
    __shared__ float rm[256], rs[256];
    const float* lr = logits + (long)r * NTOK;
    float m = -1e30f, s = 0.f;
    for (int j = t; j < NTOK; j += 256) {
        float x = lr[j];
        if (x > m) { s = s * expf(m - x) + 1.f; m = x; }
        else       { s += expf(x - m); }
    }
    rm[t] = m; rs[t] = s; __syncthreads();
    for (int o = 128; o > 0; o >>= 1) {
        if (t < o) {
            float m2 = rm[t + o], s2 = rs[t + o];
            float M = fmaxf(rm[t], m2);
            rs[t] = rs[t] * expf(rm[t] - M) + s2 * expf(m2 - M);
            rm[t] = M;
        }
        __syncthreads();
    }
    if (t == 0) out[r] = (logf(rs[0]) + rm[0]) - lr[target[r]];
}

// ---------------- host ----------------

#define S128 73728
#define S64  55296
#define GSA(p, s) cudaGetSymbolAddress((void**)&p, s)

static inline dim3 gt(int N, int M, int bz, int ntile) { return dim3(N / ntile, M / 128, bz); }

extern "C" void kernel_launch(void* const* d_in, const int* in_sizes, int n_in,
                              void* d_out, int out_size)
{
    const int*   data   = (const int*)  d_in[0];
    const int*   target = (const int*)  d_in[1];
    const float* memory = (const float*)d_in[2];
    const float* embW   = (const float*)d_in[3];
    const float* rwb    = (const float*)d_in[4];
    const float* rrb    = (const float*)d_in[5];
    const float* Wq     = (const float*)d_in[6];
    const float* Wkv    = (const float*)d_in[7];
    const float* Wr     = (const float*)d_in[8];
    const float* Wo     = (const float*)d_in[9];
    const float* W1     = (const float*)d_in[10];
    const float* b1     = (const float*)d_in[11];
    const float* W2     = (const float*)d_in[12];
    const float* b2     = (const float*)d_in[13];
    const float* ln1g   = (const float*)d_in[14];
    const float* ln1b   = (const float*)d_in[15];
    const float* ln2g   = (const float*)d_in[16];
    const float* ln2b   = (const float*)d_in[17];

    float* out      = (float*)d_out;
    float* out_loss = out;
    float* out_mems = out + ROWS;

    float *core, *tmp, *vtmp, *sc, *bd, *logit;
    GSA(core, g_core); GSA(tmp, g_tmp); GSA(vtmp, g_vtmp);
    GSA(sc, g_sc); GSA(bd, g_bd); GSA(logit, g_logit);

    bf16 *hcore,*lcore,*hmem,*lmem,*hqrw,*lqrw,*hqrr,*lqrr,*hk,*lk,*hvT,*lvT,*hrk,*lrk,
         *hprob,*lprob,*hvec,*lvec,*hffh,*lffh,*hpos,*lpos,*hemb,*lemb,
         *hWkvT,*lWkvT,*hWqT,*lWqT,*hWrT,*lWrT,*hWoT,*lWoT,*hW1T,*lW1T,*hW2T,*lW2T;
    GSA(hcore,h_core); GSA(lcore,l_core); GSA(hmem,h_mem); GSA(lmem,l_mem);
    GSA(hqrw,h_qrw); GSA(lqrw,l_qrw); GSA(hqrr,h_qrr); GSA(lqrr,l_qrr);
    GSA(hk,h_kk); GSA(lk,l_kk); GSA(hvT,h_vT); GSA(lvT,l_vT);
    GSA(hrk,h_rk); GSA(lrk,l_rk); GSA(hprob,h_prob); GSA(lprob,l_prob);
    GSA(hvec,h_vec); GSA(lvec,l_vec); GSA(hffh,h_ffh); GSA(lffh,l_ffh);
    GSA(hpos,h_pos); GSA(lpos,l_pos); GSA(hemb,h_emb); GSA(lemb,l_emb);
    GSA(hWkvT,h_WkvT); GSA(lWkvT,l_WkvT); GSA(hWqT,h_WqT); GSA(lWqT,l_WqT);
    GSA(hWrT,h_WrT); GSA(lWrT,l_WrT); GSA(hWoT,h_WoT); GSA(lWoT,l_WoT);
    GSA(hW1T,h_W1T); GSA(lW1T,l_W1T); GSA(hW2T,h_W2T); GSA(lW2T,l_W2T);

    cudaFuncSetAttribute(pgemm<128,0>, cudaFuncAttributeMaxDynamicSharedMemorySize, S128);
    cudaFuncSetAttribute(pgemm<128,1>, cudaFuncAttributeMaxDynamicSharedMemorySize, S128);
    cudaFuncSetAttribute(pgemm<128,2>, cudaFuncAttributeMaxDynamicSharedMemorySize, S128);
    cudaFuncSetAttribute(pgemm<128,3>, cudaFuncAttributeMaxDynamicSharedMemorySize, S128);
    cudaFuncSetAttribute(pgemm<128,6>, cudaFuncAttributeMaxDynamicSharedMemorySize, S128);
    cudaFuncSetAttribute(pgemm<64,4>,  cudaFuncAttributeMaxDynamicSharedMemorySize, S64);
    cudaFuncSetAttribute(pgemm<128,4>, cudaFuncAttributeMaxDynamicSharedMemorySize, S128);

    const dim3 tb(32, 8);
    // one-time converts (per replay; cheap)
    for (int l = 0; l < NL; l++) {
        transpose_pair<<<dim3(2*HD/32, DM/32), tb>>>(Wkv + (size_t)l*DM*2*HD, hWkvT + (size_t)l*2*HD*DM, lWkvT + (size_t)l*2*HD*DM, DM, 2*HD);
        transpose_pair<<<dim3(HD/32, DM/32), tb>>>(Wq + (size_t)l*DM*HD, hWqT + (size_t)l*HD*DM, lWqT + (size_t)l*HD*DM, DM, HD);
        transpose_pair<<<dim3(HD/32, DM/32), tb>>>(Wr + (size_t)l*DM*HD, hWrT + (size_t)l*HD*DM, lWrT + (size_t)l*HD*DM, DM, HD);
        transpose_pair<<<dim3(DM/32, HD/32), tb>>>(Wo + (size_t)l*HD*DM, hWoT + (size_t)l*DM*HD, lWoT + (size_t)l*DM*HD, HD, DM);
        transpose_pair<<<dim3(DI/32, DM/32), tb>>>(W1 + (size_t)l*DM*DI, hW1T + (size_t)l*DI*DM, lW1T + (size_t)l*DI*DM, DM, DI);
        transpose_pair<<<dim3(DM/32, DI/32), tb>>>(W2 + (size_t)l*DI*DM, hW2T + (size_t)l*DM*DI, lW2T + (size_t)l*DM*DI, DI, DM);
    }
    {
        long n1 = (long)NL*ROWS*DM;
        convert_pair<<<(int)((n1 + 255)/256), 256>>>(memory, hmem, lmem, n1);
        long n2 = (long)NTOK*DM;
        convert_pair<<<(int)((n2 + 255)/256), 256>>>(embW, hemb, lemb, n2);
    }

    embed_kernel<<<(ROWS*DM + 255)/256, 256>>>(data, embW, core, hcore, lcore);
    pos_kernel<<<(KLEN*DM + 255)/256, 256>>>(hpos, lpos);

    const size_t coreBytes = (size_t)ROWS * DM * sizeof(float);
    cudaMemcpyAsync(out_mems, core, coreBytes, cudaMemcpyDeviceToDevice);

    for (int l = 0; l < NL; l++) {
        const bf16* hWkvl = hWkvT + (size_t)l*2*HD*DM;
        const bf16* lWkvl = lWkvT + (size_t)l*2*HD*DM;

        // kv (mem half then core half): k -> pair, v -> fp32 vtmp
        pgemm<128,6><<<gt(2*HD, ROWS, 1, 128), 256, S128>>>(
            hmem + (size_t)l*ROWS*DM, lmem + (size_t)l*ROWS*DM, hWkvl, lWkvl,
            DM, DM, DM, 0,0,0,0, 1, HD, 0,0,
            nullptr, hk, lk, nullptr, nullptr, nullptr, nullptr, vtmp, HD);
        pgemm<128,6><<<gt(2*HD, ROWS, 1, 128), 256, S128>>>(
            hcore, lcore, hWkvl, lWkvl,
            DM, DM, DM, 0,0,0,0, 1, HD, 0,0,
            nullptr, hk + (size_t)ROWS*HD, lk + (size_t)ROWS*HD, nullptr, nullptr,
            nullptr, nullptr, vtmp + (size_t)ROWS*HD, HD);

        // v transpose -> pair vT
        vtrans_kernel<<<dim3(KLEN/32, DH/32, BSZ*NH), tb>>>(vtmp, hvT, lvT);

        // q dual: qrw = core@Wq + rwb ; qrr = ... + rrb
        pgemm<128,3><<<gt(HD, ROWS, 1, 128), 256, S128>>>(
            hcore, lcore, hWqT + (size_t)l*HD*DM, lWqT + (size_t)l*HD*DM,
            DM, DM, DM, 0,0,0,0, 1, DM, 0,0,
            nullptr, hqrw, lqrw, hqrr, lqrr, rwb, rrb, nullptr, 0);

        // rk = pos@Wr -> pair
        pgemm<128,4><<<gt(HD, KLEN, 1, 128), 256, S128>>>(
            hpos, lpos, hWrT + (size_t)l*HD*DM, lWrT + (size_t)l*HD*DM,
            DM, DM, DM, 0,0,0,0, 1, HD, 0,0,
            nullptr, hrk, lrk, nullptr, nullptr, nullptr, nullptr, nullptr, 0);

        // AC -> sc fp32 (batched b*n)
        pgemm<128,0><<<gt(KLEN, QLEN, BSZ*NH, 128), 256, S128>>>(
            hqrw, lqrw, hk, lk,
            DH, BSZ*DM, BSZ*HD,
            (long)DM, (long)DH, (long)HD, (long)DH, NH,
            KLEN, (long)NH*QLEN*KLEN, (long)QLEN*KLEN,
            sc, nullptr, nullptr, nullptr, nullptr, nullptr, nullptr, nullptr, 0);

        // BD -> bd fp32 (batched n)
        pgemm<128,0><<<gt(KLEN, ROWS, NH, 128), 256, S128>>>(
            hqrr, lqrr, hrk, lrk,
            DH, DM, HD,
            0, (long)DH, 0, (long)DH, NH,
            KLEN, 0, (long)ROWS*KLEN,
            bd, nullptr, nullptr, nullptr, nullptr, nullptr, nullptr, nullptr, 0);

        attn_softmax_kernel<<<dim3(QLEN, NH, BSZ), 256>>>(sc, bd, hprob, lprob);

        // PV: vec = prob @ vT^T -> pair vec (batched b*n, N=64)
        pgemm<64,4><<<gt(DH, QLEN, BSZ*NH, 64), 128, S64>>>(
            hprob, lprob, hvT, lvT,
            KLEN, KLEN, KLEN,
            (long)NH*QLEN*KLEN, (long)QLEN*KLEN, (long)NH*DH*KLEN, (long)DH*KLEN, NH,
            BSZ*HD, (long)HD, (long)DH,
            nullptr, hvec, lvec, nullptr, nullptr, nullptr, nullptr, nullptr, 0);

        // attn_out = vec @ Wo -> tmp fp32
        pgemm<128,0><<<gt(DM, ROWS, 1, 128), 256, S128>>>(
            hvec, lvec, hWoT + (size_t)l*DM*HD, lWoT + (size_t)l*DM*HD,
            HD, HD, HD, 0,0,0,0, 1, DM, 0,0,
            tmp, nullptr, nullptr, nullptr, nullptr, nullptr, nullptr, nullptr, 0);

        ln_kernel<<<ROWS, 256>>>(core, tmp, ln1g + (size_t)l*DM, ln1b + (size_t)l*DM,
                                 core, hcore, lcore);

        // ffh = relu(core@W1 + b1) -> pair
        pgemm<128,2><<<gt(DI, ROWS, 1, 128), 256, S128>>>(
            hcore, lcore, hW1T + (size_t)l*DI*DM, lW1T + (size_t)l*DI*DM,
            DM, DM, DM, 0,0,0,0, 1, DI, 0,0,
            nullptr, hffh, lffh, nullptr, nullptr, b1 + (size_t)l*DI, nullptr, nullptr, 0);

        // ff = ffh@W2 + b2 -> tmp fp32
        pgemm<128,1><<<gt(DM, ROWS, 1, 128), 256, S128>>>(
            hffh, lffh, hW2T + (size_t)l*DM*DI, lW2T + (size_t)l*DM*DI,
            DI, DI, DI, 0,0,0,0, 1, DM, 0,0,
            tmp, nullptr, nullptr, nullptr, nullptr, b2 + (size_t)l*DM, nullptr, nullptr, 0);

        ln_kernel<<<ROWS, 256>>>(core, tmp, ln2g + (size_t)l*DM, ln2b + (size_t)l*DM,
                                 core, hcore, lcore);

        if (l < NL - 1)
            cudaMemcpyAsync(out_mems + (size_t)(l + 1)*ROWS*DM, core, coreBytes,
                            cudaMemcpyDeviceToDevice);
    }

    // logits = core @ embW^T -> fp32
    pgemm<128,0><<<gt(NTOK, ROWS, 1, 128), 256, S128>>>(
        hcore, lcore, hemb, lemb,
        DM, DM, DM, 0,0,0,0, 1, NTOK, 0,0,
        logit, nullptr, nullptr, nullptr, nullptr, nullptr, nullptr, nullptr, 0);
    loss_kernel<<<ROWS, 256>>>(logit, target, out_loss);

    (void)in_sizes; (void)n_in; (void)out_size;
}

// round 10
// speedup vs baseline: 3.2375x; 1.0402x over previous
#include <cuda_runtime.h>
#include <cuda_bf16.h>
#include <math.h>
#include <stdint.h>

typedef __nv_bfloat16 bf16;
typedef __nv_bfloat162 bf162;
typedef uint32_t u32;

#define QLEN 512
#define MEMLEN 512
#define KLEN 1024
#define BSZ 8
#define NH 16
#define DH 64
#define DM 1024
#define DI 4096
#define NL 6
#define NTOK 32000
#define HD 1024
#define ROWS (QLEN*BSZ)
#define KROWS (KLEN*BSZ)
#define SCALE 0.125f
#define NLSP 256          // padded partial count per row (250 used)

// ---------------- fp32 scratch ----------------
__device__ float g_core [ROWS*DM];
__device__ float g_tmp  [ROWS*DM];
__device__ float g_vtmp [KROWS*HD];
__device__ float g_sc   [(size_t)BSZ*NH*QLEN*KLEN];
__device__ float g_bd   [(size_t)NH*ROWS*KLEN];
__device__ float2 g_lsp [(size_t)ROWS*NLSP];   // per-row (max,sumexp) partials

// ---------------- bf16 hi/lo pair scratch ----------------
#define PAIR(name, n) __device__ bf16 h_##name[n]; __device__ bf16 l_##name[n];
PAIR(core, ROWS*DM)
PAIR(mem,  (size_t)NL*ROWS*DM)
PAIR(qrw,  ROWS*DM)
PAIR(qrr,  ROWS*DM)
PAIR(kk,   KROWS*HD)
PAIR(vT,   (size_t)BSZ*NH*DH*KLEN)
PAIR(rk,   KLEN*HD)
PAIR(prob, (size_t)BSZ*NH*QLEN*KLEN)
PAIR(vec,  ROWS*HD)
PAIR(ffh,  (size_t)ROWS*DI)
PAIR(pos,  KLEN*DM)
PAIR(emb,  (size_t)NTOK*DM)
PAIR(WkvT, (size_t)NL*2*HD*DM)
PAIR(WqT,  (size_t)NL*HD*DM)
PAIR(WrT,  (size_t)NL*HD*DM)
PAIR(WoT,  (size_t)NL*DM*HD)
PAIR(W1T,  (size_t)NL*DI*DM)
PAIR(W2T,  (size_t)NL*DM*DI)

// ---------------- helpers ----------------
__device__ __forceinline__ void mma_bf16(float* d, const u32* a, const u32* b) {
    asm volatile(
        "mma.sync.aligned.m16n8k16.row.col.f32.bf16.bf16.f32 "
        "{%0,%1,%2,%3}, {%4,%5,%6,%7}, {%8,%9}, {%0,%1,%2,%3};\n"
        : "+f"(d[0]), "+f"(d[1]), "+f"(d[2]), "+f"(d[3])
        : "r"(a[0]), "r"(a[1]), "r"(a[2]), "r"(a[3]), "r"(b[0]), "r"(b[1]));
}
#define LDSM4(r0,r1,r2,r3,addr) \
    asm volatile("ldmatrix.sync.aligned.m8n8.x4.shared.b16 {%0,%1,%2,%3}, [%4];" \
        : "=r"(r0), "=r"(r1), "=r"(r2), "=r"(r3) : "r"(addr))
__device__ __forceinline__ void cp16s(u32 sdst, const void* g) {
    asm volatile("cp.async.cg.shared.global [%0], [%1], 16;\n" :: "r"(sdst), "l"(g));
}
#define CP_COMMIT() asm volatile("cp.async.commit_group;\n")
#define CP_WAIT1()  asm volatile("cp.async.wait_group 1;\n")

__device__ __forceinline__ u32 pk2(float a, float b) {
    bf162 t = __floats2bfloat162_rn(a, b);
    return *(u32*)&t;
}
__device__ __forceinline__ float bres(float x) {   // x - bf16(x)
    return x - __bfloat162float(__float2bfloat16(x));
}
__device__ __forceinline__ void pairstore(bf16* H, bf16* L, long off, float v0, float v1) {
    *(u32*)(H + off) = pk2(v0, v1);
    *(u32*)(L + off) = pk2(bres(v0), bres(v1));
}
__device__ __forceinline__ void pairstore4(bf16* H, bf16* L, long off,
                                           float a, float b, float c, float d) {
    uint2 hh = { pk2(a, b), pk2(c, d) };
    uint2 ll = { pk2(bres(a), bres(b)), pk2(bres(c), bres(d)) };
    *(uint2*)(H + off) = hh;
    *(uint2*)(L + off) = ll;
}
__device__ __forceinline__ void lse_comb(float& m, float& s, float m2, float s2) {
    float M = fmaxf(m, m2);
    s = s * expf(m - M) + s2 * expf(m2 - M);
    m = M;
}

// ---------------- pair-bf16 NT GEMM ----------------
// C[M,N] = A[M,K]*B[N,K]^T, A/B as hi/lo bf16 arrays. CTA 128xNTILE, warp 64x32,
// K-step 32, 2-stage cp.async.
// EPI: 0 fp32  1 fp32+bias  2 pair relu(+bias)  3 dual pair  4 pair
//      6 kv-split  7 logsumexp partials (no C write)
template <int NTILE, int EPI>
__global__ void __launch_bounds__(NTILE == 128 ? 256 : 128, 2)
pgemm(const bf16* __restrict__ Ah, const bf16* __restrict__ Al,
      const bf16* __restrict__ Bh, const bf16* __restrict__ Bl,
      int K, int lda, int ldb,
      long sA1, long sA2, long sB1, long sB2, int batch2,
      int ldc, long sC1, long sC2,
      float* __restrict__ Cf,
      bf16* __restrict__ Ch, bf16* __restrict__ Cl,
      bf16* __restrict__ Ch2, bf16* __restrict__ Cl2,
      const float* __restrict__ bias, const float* __restrict__ bias2,
      float* __restrict__ Cf2, int ldc2)
{
    constexpr int T    = (NTILE == 128) ? 256 : 128;
    constexpr int ASTB = 128 * 144;
    constexpr int BSTB = NTILE * 144;
    extern __shared__ char smraw[];
    const u32 smS = (u32)__cvta_generic_to_shared(smraw);

    const int bz = blockIdx.z;
    const int b1 = bz / batch2, b2 = bz % batch2;
    Ah += b1 * sA1 + b2 * sA2;  Al += b1 * sA1 + b2 * sA2;
    Bh += b1 * sB1 + b2 * sB2;  Bl += b1 * sB1 + b2 * sB2;
    const long cOff = b1 * sC1 + b2 * sC2;

    const int m0 = blockIdx.y * 128, n0 = blockIdx.x * NTILE;
    const int tid = threadIdx.x, warp = tid >> 5, lane = tid & 31;
    constexpr int NWN = NTILE / 32;
    const int wm = warp / NWN, wn = warp % NWN;

    float acc[4][4][4];
#pragma unroll
    for (int mt = 0; mt < 4; mt++)
#pragma unroll
        for (int nt = 0; nt < 4; nt++)
#pragma unroll
            for (int e = 0; e < 4; e++) acc[mt][nt][e] = 0.f;

    const int KT = K >> 5;

    auto issue = [&](int kt, int st) {
        const int k0 = kt << 5;
        const u32 aB = smS + st * ASTB;
        const u32 bB = smS + 2 * ASTB + st * BSTB;
#pragma unroll
        for (int i = 0; i < 1024 / T; i++) {
            int idx = tid + i * T, r = idx >> 3, q = idx & 7;
            const bf16* src = (q < 4) ? (Ah + (long)(m0 + r) * lda + k0 + q * 8)
                                      : (Al + (long)(m0 + r) * lda + k0 + (q - 4) * 8);
            cp16s(aB + r * 144 + q * 16, src);
        }
#pragma unroll
        for (int i = 0; i < NTILE * 8 / T; i++) {
            int idx = tid + i * T, r = idx >> 3, q = idx & 7;
            const bf16* src = (q < 4) ? (Bh + (long)(n0 + r) * ldb + k0 + q * 8)
                                      : (Bl + (long)(n0 + r) * ldb + k0 + (q - 4) * 8);
            cp16s(bB + r * 144 + q * 16, src);
        }
    };

    const u32 aLane = (u32)((lane & 15) * 144 + (lane >> 4) * 16);
    const u32 bLane = (u32)(((lane >> 4) * 8 + (lane & 7)) * 144 + ((lane >> 3) & 1) * 16);

    issue(0, 0); CP_COMMIT();
    if (KT > 1) issue(1, 1);
    CP_COMMIT();

    for (int kt = 0; kt < KT; kt++) {
        CP_WAIT1();
        __syncthreads();
        const u32 As = smS + (kt & 1) * ASTB + wm * 64 * 144 + aLane;
        const u32 Bs = smS + 2 * ASTB + (kt & 1) * BSTB + wn * 32 * 144 + bLane;

#pragma unroll
        for (int g = 0; g < 2; g++) {
            u32 ah[4][4], alr[4][4], bh[4][2], blr[4][2];
#pragma unroll
            for (int mt = 0; mt < 4; mt++) {
                const u32 ad = As + mt * 2304 + g * 32;
                LDSM4(ah[mt][0], ah[mt][1], ah[mt][2], ah[mt][3], ad);
                LDSM4(alr[mt][0], alr[mt][1], alr[mt][2], alr[mt][3], ad + 64);
            }
#pragma unroll
            for (int p = 0; p < 2; p++) {
                const u32 bd_ = Bs + p * 2304 + g * 32;
                LDSM4(bh[2*p][0], bh[2*p][1], bh[2*p+1][0], bh[2*p+1][1], bd_);
                LDSM4(blr[2*p][0], blr[2*p][1], blr[2*p+1][0], blr[2*p+1][1], bd_ + 64);
            }
#pragma unroll
            for (int mt = 0; mt < 4; mt++)
#pragma unroll
                for (int nt = 0; nt < 4; nt++) {
                    mma_bf16(acc[mt][nt], ah[mt], bh[nt]);
                    mma_bf16(acc[mt][nt], ah[mt], blr[nt]);
                    mma_bf16(acc[mt][nt], alr[mt], bh[nt]);
                }
        }
        __syncthreads();
        if (kt + 2 < KT) issue(kt + 2, kt & 1);
        CP_COMMIT();
    }

    const int gl = lane >> 2, c2 = (lane & 3) * 2;

    if (EPI == 7) {
        // per-row logsumexp partial over this CTA's 128 cols
        float2* red = (float2*)smraw;   // [128 rows][NWN]
        __syncthreads();
#pragma unroll
        for (int mt = 0; mt < 4; mt++)
#pragma unroll
            for (int h = 0; h < 2; h++) {
                float m = -1e30f, s = 0.f;
#pragma unroll
                for (int nt = 0; nt < 4; nt++) {
                    m = fmaxf(m, fmaxf(acc[mt][nt][h*2], acc[mt][nt][h*2+1]));
                }
#pragma unroll
                for (int nt = 0; nt < 4; nt++) {
                    s += expf(acc[mt][nt][h*2] - m) + expf(acc[mt][nt][h*2+1] - m);
                }
#pragma unroll
                for (int o = 1; o < 4; o <<= 1) {
                    float m2 = __shfl_xor_sync(0xffffffff, m, o);
                    float s2 = __shfl_xor_sync(0xffffffff, s, o);
                    lse_comb(m, s, m2, s2);
                }
                if ((lane & 3) == 0) {
                    int r = wm * 64 + mt * 16 + h * 8 + gl;
                    red[r * NWN + wn] = make_float2(m, s);
                }
            }
        __syncthreads();
        if (tid < 128) {
            float m = -1e30f, s = 0.f;
#pragma unroll
            for (int w = 0; w < NWN; w++) {
                float2 p = red[tid * NWN + w];
                lse_comb(m, s, p.x, p.y);
            }
            ((float2*)Cf)[(long)(m0 + tid) * NLSP + blockIdx.x] = make_float2(m, s);
        }
        return;
    }

#pragma unroll
    for (int mt = 0; mt < 4; mt++)
#pragma unroll
        for (int nt = 0; nt < 4; nt++)
#pragma unroll
            for (int h = 0; h < 2; h++) {
                const int row = m0 + wm * 64 + mt * 16 + gl + h * 8;
                const int col = n0 + wn * 32 + nt * 8 + c2;
                float v0 = acc[mt][nt][h*2], v1 = acc[mt][nt][h*2+1];
                const long off = (long)row * ldc + col + cOff;
                if (EPI == 0) {
                    *(float2*)(Cf + off) = make_float2(v0, v1);
                } else if (EPI == 1) {
                    *(float2*)(Cf + off) = make_float2(v0 + bias[col], v1 + bias[col+1]);
                } else if (EPI == 2) {
                    pairstore(Ch, Cl, off, fmaxf(v0 + bias[col], 0.f), fmaxf(v1 + bias[col+1], 0.f));
                } else if (EPI == 3) {
                    pairstore(Ch,  Cl,  off, v0 + bias[col],  v1 + bias[col+1]);
                    pairstore(Ch2, Cl2, off, v0 + bias2[col], v1 + bias2[col+1]);
                } else if (EPI == 4) {
                    pairstore(Ch, Cl, off, v0, v1);
                } else {  // 6: kv split
                    if (n0 < HD) pairstore(Ch, Cl, (long)row * ldc + col, v0, v1);
                    else *(float2*)(Cf2 + (long)row * ldc2 + (col - HD)) = make_float2(v0, v1);
                }
            }
}

// ---------------- converters (vectorized) ----------------

// batched over layers: fp32 in[z][R][C] -> pair out[z][C][R]
__global__ void transpose_pair(const float* __restrict__ in, bf16* __restrict__ oh,
                               bf16* __restrict__ ol, int R, int C)
{
    __shared__ float t[32][33];
    const long zo = (long)blockIdx.z * R * C;
    in += zo; oh += zo; ol += zo;
    const int c0 = blockIdx.x * 32, r0 = blockIdx.y * 32;
    const int tx = threadIdx.x, ty = threadIdx.y;   // (8, 32)
    {
        float4 v = *(const float4*)(in + (long)(r0 + ty) * C + c0 + tx * 4);
        t[ty][tx*4+0] = v.x; t[ty][tx*4+1] = v.y; t[ty][tx*4+2] = v.z; t[ty][tx*4+3] = v.w;
    }
    __syncthreads();
    {
        float a = t[tx*4+0][ty], b = t[tx*4+1][ty], c = t[tx*4+2][ty], d = t[tx*4+3][ty];
        long o = (long)(c0 + ty) * R + r0 + tx * 4;
        pairstore4(oh, ol, o, a, b, c, d);
    }
}

__global__ void convert_pair(const float* __restrict__ in, bf16* __restrict__ oh,
                             bf16* __restrict__ ol, long n4)
{
    long i = (long)blockIdx.x * 256 + threadIdx.x;
    if (i >= n4) return;
    float4 v = *(const float4*)(in + i * 4);
    pairstore4(oh, ol, i * 4, v.x, v.y, v.z, v.w);
}

// v fp32 [j*BSZ+b][n*64+d] -> pair [(b*NH+n)][d][j]
__global__ void vtrans_kernel(const float* __restrict__ v, bf16* __restrict__ oh,
                              bf16* __restrict__ ol)
{
    __shared__ float t[32][33];
    const int bn = blockIdx.z, b = bn >> 4, n = bn & 15;
    const int j0 = blockIdx.x * 32, d0 = blockIdx.y * 32;
    const int tx = threadIdx.x, ty = threadIdx.y;   // (8, 32)
    {
        float4 x = *(const float4*)(v + ((long)(j0 + ty) * BSZ + b) * HD + n * 64 + d0 + tx * 4);
        t[ty][tx*4+0] = x.x; t[ty][tx*4+1] = x.y; t[ty][tx*4+2] = x.z; t[ty][tx*4+3] = x.w;
    }
    __syncthreads();
    {
        float a = t[tx*4+0][ty], c = t[tx*4+1][ty], d = t[tx*4+2][ty], e = t[tx*4+3][ty];
        long o = ((long)bn * DH + d0 + ty) * KLEN + j0 + tx * 4;
        pairstore4(oh, ol, o, a, c, d, e);
    }
}

// ---------------- elementwise / reductions ----------------

__global__ void embed_kernel(const int* __restrict__ data, const float* __restrict__ embW,
                             float* __restrict__ core, bf16* __restrict__ ch,
                             bf16* __restrict__ cl, float* __restrict__ outm)
{
    long i = (long)blockIdx.x * 256 + threadIdx.x;   // float4 index
    if (i >= (long)ROWS * DM / 4) return;
    int r = (int)(i >> 8);
    float4 v = *(const float4*)(embW + (long)data[r] * DM + (i & 255) * 4);
    *(float4*)(core + i * 4) = v;
    *(float4*)(outm + i * 4) = v;
    pairstore4(ch, cl, i * 4, v.x, v.y, v.z, v.w);
}

__global__ void pos_kernel(bf16* __restrict__ ph, bf16* __restrict__ pl)
{
    long idx = (long)blockIdx.x * 256 + threadIdx.x;
    if (idx >= (long)KLEN * DM) return;
    int j = (int)(idx >> 10), d = (int)(idx & 1023);
    float p = (float)(KLEN - 1 - j);
    int t = (d < 512) ? d : d - 512;
    float invf = expf(-((2.0f * (float)t) / (float)DM) * logf(10000.0f));
    float a = p * invf;
    float x = (d < 512) ? sinf(a) : cosf(a);
    ph[idx] = __float2bfloat16(x);
    pl[idx] = __float2bfloat16(bres(x));
}

// softmax over j of mask((AC + shifted BD)*SCALE); writes pair prob
__global__ void attn_softmax_kernel(const float* __restrict__ sc, const float* __restrict__ bd,
                                    bf16* __restrict__ ph, bf16* __restrict__ pl)
{
    const int i = blockIdx.x, n = blockIdx.y, b = blockIdx.z;
    const int t = threadIdx.x;
    const long rbase = (((long)b * NH + n) * QLEN + i) * KLEN;
    const float* row = sc + rbase;
    const float* bdr = bd + (((long)n * ROWS + (i * BSZ + b)) * KLEN);
    const int limit = i + MEMLEN;
    const int shift = QLEN - 1 - i;
    const int j0 = t * 4;

    __shared__ float red[256];
    float4 rv = *(const float4*)(row + j0);
    float v[4] = { rv.x, rv.y, rv.z, rv.w };
    float m = -1e30f;
#pragma unroll
    for (int k = 0; k < 4; k++) {
        int j = j0 + k;
        float x = -1e30f;
        if (j <= limit) x = (v[k] + bdr[j + shift]) * SCALE;
        v[k] = x;
        m = fmaxf(m, x);
    }
    red[t] = m; __syncthreads();
    for (int o = 128; o > 0; o >>= 1) { if (t < o) red[t] = fmaxf(red[t], red[t + o]); __syncthreads(); }
    const float M = red[0];
    __syncthreads();
    float s = 0.f;
#pragma unroll
    for (int k = 0; k < 4; k++) { float e = expf(v[k] - M); v[k] = e; s += e; }
    red[t] = s; __syncthreads();
    for (int o = 128; o > 0; o >>= 1) { if (t < o) red[t] += red[t + o]; __syncthreads(); }
    const float inv = 1.0f / red[0];
    pairstore4(ph, pl, rbase + j0, v[0]*inv, v[1]*inv, v[2]*inv, v[3]*inv);
}

// out = LN(x+y)*g+b -> fp32 + pair (+ optional mems copy)
__global__ void ln_kernel(const float* __restrict__ x, const float* __restrict__ y,
                          const float* __restrict__ g, const float* __restrict__ b,
                          float* __restrict__ outf, bf16* __restrict__ oh,
                          bf16* __restrict__ ol, float* __restrict__ memsf)
{
    const int r = blockIdx.x, t = threadIdx.x;
    __shared__ float red[256];
    const long base = (long)r * DM + t * 4;
    float4 xv = *(const float4*)(x + base);
    float4 yv = *(const float4*)(y + base);
    float loc[4] = { xv.x + yv.x, xv.y + yv.y, xv.z + yv.z, xv.w + yv.w };
    float s = loc[0] + loc[1] + loc[2] + loc[3];
    red[t] = s; __syncthreads();
    for (int o = 128; o > 0; o >>= 1) { if (t < o) red[t] += red[t + o]; __syncthreads(); }
    const float mu = red[0] * (1.0f / DM);
    __syncthreads();
    float s2 = 0.f;
#pragma unroll
    for (int k = 0; k < 4; k++) { float d = loc[k] - mu; s2 += d * d; }
    red[t] = s2; __syncthreads();
    for (int o = 128; o > 0; o >>= 1) { if (t < o) red[t] += red[t + o]; __syncthreads(); }
    const float rstd = rsqrtf(red[0] * (1.0f / DM) + 1e-5f);
    float4 gv = *(const float4*)(g + t * 4);
    float4 bv = *(const float4*)(b + t * 4);
    float4 o4;
    o4.x = (loc[0] - mu) * rstd * gv.x + bv.x;
    o4.y = (loc[1] - mu) * rstd * gv.y + bv.y;
    o4.z = (loc[2] - mu) * rstd * gv.z + bv.z;
    o4.w = (loc[3] - mu) * rstd * gv.w + bv.w;
    *(float4*)(outf + base) = o4;
    if (memsf) *(float4*)(memsf + base) = o4;
    pairstore4(oh, ol, base, o4.x, o4.y, o4.z, o4.w);
}

// final loss: combine 250 lse partials + exact fp32 target logit
__global__ void loss_final_kernel(const float2* __restrict__ lsp,
                                  const float* __restrict__ core,
                                  const float* __restrict__ embW,
                                  const int* __restrict__ target,
                                  float* __restrict__ out)
{
    const int r = blockIdx.x, t = threadIdx.x;   // 128 threads
    __shared__ float rm[128], rs[128], rd[128];
    float m = -1e30f, s = 0.f;
    for (int j = t; j < NTOK / 128; j += 128) {
        float2 p = lsp[(long)r * NLSP + j];
        lse_comb(m, s, p.x, p.y);
    }
    const float* cr = core + (long)r * DM;
    const float* er = embW + (long)target[r] * DM;
    float d = 0.f;
    for (int j = t; j < DM / 4; j += 128) {
        float4 a = *(const float4*)(cr + j * 4);
        float4 b = *(const float4*)(er + j * 4);
        d += a.x * b.x + a.y * b.y + a.z * b.z + a.w * b.w;
    }
    rm[t] = m; rs[t] = s; rd[t] = d; __syncthreads();
    for (int o = 64; o > 0; o >>= 1) {
        if (t < o) {
            lse_comb(rm[t], rs[t], rm[t + o], rs[t + o]);
            rd[t] += rd[t + o];
        }
        __syncthreads();
    }
    if (t == 0) out[r] = (logf(rs[0]) + rm[0]) - rd[0];
}

// ---------------- host ----------------

#define S128 73728
#define S64  55296
#define GSA(p, s) cudaGetSymbolAddress((void**)&p, s)

static inline dim3 gt(int N, int M, int bz, int ntile) { return dim3(N / ntile, M / 128, bz); }

extern "C" void kernel_launch(void* const* d_in, const int* in_sizes, int n_in,
                              void* d_out, int out_size)
{
    const int*   data   = (const int*)  d_in[0];
    const int*   target = (const int*)  d_in[1];
    const float* memory = (const float*)d_in[2];
    const float* embW   = (const float*)d_in[3];
    const float* rwb    = (const float*)d_in[4];
    const float* rrb    = (const float*)d_in[5];
    const float* Wq     = (const float*)d_in[6];
    const float* Wkv    = (const float*)d_in[7];
    const float* Wr     = (const float*)d_in[8];
    const float* Wo     = (const float*)d_in[9];
    const float* W1     = (const float*)d_in[10];
    const float* b1     = (const float*)d_in[11];
    const float* W2     = (const float*)d_in[12];
    const float* b2     = (const float*)d_in[13];
    const float* ln1g   = (const float*)d_in[14];
    const float* ln1b   = (const float*)d_in[15];
    const float* ln2g   = (const float*)d_in[16];
    const float* ln2b   = (const float*)d_in[17];

    float* out      = (float*)d_out;
    float* out_loss = out;
    float* out_mems = out + ROWS;

    float *core, *tmp, *vtmp, *sc, *bd;
    float2* lsp;
    GSA(core, g_core); GSA(tmp, g_tmp); GSA(vtmp, g_vtmp);
    GSA(sc, g_sc); GSA(bd, g_bd); GSA(lsp, g_lsp);

    bf16 *hcore,*lcore,*hmem,*lmem,*hqrw,*lqrw,*hqrr,*lqrr,*hk,*lk,*hvT,*lvT,*hrk,*lrk,
         *hprob,*lprob,*hvec,*lvec,*hffh,*lffh,*hpos,*lpos,*hemb,*lemb,
         *hWkvT,*lWkvT,*hWqT,*lWqT,*hWrT,*lWrT,*hWoT,*lWoT,*hW1T,*lW1T,*hW2T,*lW2T;
    GSA(hcore,h_core); GSA(lcore,l_core); GSA(hmem,h_mem); GSA(lmem,l_mem);
    GSA(hqrw,h_qrw); GSA(lqrw,l_qrw); GSA(hqrr,h_qrr); GSA(lqrr,l_qrr);
    GSA(hk,h_kk); GSA(lk,l_kk); GSA(hvT,h_vT); GSA(lvT,l_vT);
    GSA(hrk,h_rk); GSA(lrk,l_rk); GSA(hprob,h_prob); GSA(lprob,l_prob);
    GSA(hvec,h_vec); GSA(lvec,l_vec); GSA(hffh,h_ffh); GSA(lffh,l_ffh);
    GSA(hpos,h_pos); GSA(lpos,l_pos); GSA(hemb,h_emb); GSA(lemb,l_emb);
    GSA(hWkvT,h_WkvT); GSA(lWkvT,l_WkvT); GSA(hWqT,h_WqT); GSA(lWqT,l_WqT);
    GSA(hWrT,h_WrT); GSA(lWrT,l_WrT); GSA(hWoT,h_WoT); GSA(lWoT,l_WoT);
    GSA(hW1T,h_W1T); GSA(lW1T,l_W1T); GSA(hW2T,h_W2T); GSA(lW2T,l_W2T);

    // every launched instantiation needs the smem opt-in (R9 failure: <128,4> missing)
    cudaFuncSetAttribute(pgemm<128,0>, cudaFuncAttributeMaxDynamicSharedMemorySize, S128);
    cudaFuncSetAttribute(pgemm<128,1>, cudaFuncAttributeMaxDynamicSharedMemorySize, S128);
    cudaFuncSetAttribute(pgemm<128,2>, cudaFuncAttributeMaxDynamicSharedMemorySize, S128);
    cudaFuncSetAttribute(pgemm<128,3>, cudaFuncAttributeMaxDynamicSharedMemorySize, S128);
    cudaFuncSetAttribute(pgemm<128,4>, cudaFuncAttributeMaxDynamicSharedMemorySize, S128);
    cudaFuncSetAttribute(pgemm<128,6>, cudaFuncAttributeMaxDynamicSharedMemorySize, S128);
    cudaFuncSetAttribute(pgemm<128,7>, cudaFuncAttributeMaxDynamicSharedMemorySize, S128);
    cudaFuncSetAttribute(pgemm<64,4>,  cudaFuncAttributeMaxDynamicSharedMemorySize, S64);

    const dim3 tb(8, 32);
    // batched weight conversions (6 launches, z = layer)
    transpose_pair<<<dim3(2*HD/32, DM/32, NL), tb>>>(Wkv, hWkvT, lWkvT, DM, 2*HD);
    transpose_pair<<<dim3(HD/32, DM/32, NL), tb>>>(Wq, hWqT, lWqT, DM, HD);
    transpose_pair<<<dim3(HD/32, DM/32, NL), tb>>>(Wr, hWrT, lWrT, DM, HD);
    transpose_pair<<<dim3(DM/32, HD/32, NL), tb>>>(Wo, hWoT, lWoT, HD, DM);
    transpose_pair<<<dim3(DI/32, DM/32, NL), tb>>>(W1, hW1T, lW1T, DM, DI);
    transpose_pair<<<dim3(DM/32, DI/32, NL), tb>>>(W2, hW2T, lW2T, DI, DM);
    {
        long n1 = (long)NL*ROWS*DM/4;
        convert_pair<<<(int)((n1 + 255)/256), 256>>>(memory, hmem, lmem, n1);
        long n2 = (long)NTOK*DM/4;
        convert_pair<<<(int)((n2 + 255)/256), 256>>>(embW, hemb, lemb, n2);
    }

    embed_kernel<<<(ROWS*DM/4 + 255)/256, 256>>>(data, embW, core, hcore, lcore, out_mems);
    pos_kernel<<<(KLEN*DM + 255)/256, 256>>>(hpos, lpos);

    for (int l = 0; l < NL; l++) {
        const bf16* hWkvl = hWkvT + (size_t)l*2*HD*DM;
        const bf16* lWkvl = lWkvT + (size_t)l*2*HD*DM;

        pgemm<128,6><<<gt(2*HD, ROWS, 1, 128), 256, S128>>>(
            hmem + (size_t)l*ROWS*DM, lmem + (size_t)l*ROWS*DM, hWkvl, lWkvl,
            DM, DM, DM, 0,0,0,0, 1, HD, 0,0,
            nullptr, hk, lk, nullptr, nullptr, nullptr, nullptr, vtmp, HD);
        pgemm<128,6><<<gt(2*HD, ROWS, 1, 128), 256, S128>>>(
            hcore, lcore, hWkvl, lWkvl,
            DM, DM, DM, 0,0,0,0, 1, HD, 0,0,
            nullptr, hk + (size_t)ROWS*HD, lk + (size_t)ROWS*HD, nullptr, nullptr,
            nullptr, nullptr, vtmp + (size_t)ROWS*HD, HD);

        vtrans_kernel<<<dim3(KLEN/32, DH/32, BSZ*NH), tb>>>(vtmp, hvT, lvT);

        pgemm<128,3><<<gt(HD, ROWS, 1, 128), 256, S128>>>(
            hcore, lcore, hWqT + (size_t)l*HD*DM, lWqT + (size_t)l*HD*DM,
            DM, DM, DM, 0,0,0,0, 1, DM, 0,0,
            nullptr, hqrw, lqrw, hqrr, lqrr, rwb, rrb, nullptr, 0);

        pgemm<128,4><<<gt(HD, KLEN, 1, 128), 256, S128>>>(
            hpos, lpos, hWrT + (size_t)l*HD*DM, lWrT + (size_t)l*HD*DM,
            DM, DM, DM, 0,0,0,0, 1, HD, 0,0,
            nullptr, hrk, lrk, nullptr, nullptr, nullptr, nullptr, nullptr, 0);

        pgemm<128,0><<<gt(KLEN, QLEN, BSZ*NH, 128), 256, S128>>>(
            hqrw, lqrw, hk, lk,
            DH, BSZ*DM, BSZ*HD,
            (long)DM, (long)DH, (long)HD, (long)DH, NH,
            KLEN, (long)NH*QLEN*KLEN, (long)QLEN*KLEN,
            sc, nullptr, nullptr, nullptr, nullptr, nullptr, nullptr, nullptr, 0);

        pgemm<128,0><<<gt(KLEN, ROWS, NH, 128), 256, S128>>>(
            hqrr, lqrr, hrk, lrk,
            DH, DM, HD,
            0, (long)DH, 0, (long)DH, NH,
            KLEN, 0, (long)ROWS*KLEN,
            bd, nullptr, nullptr, nullptr, nullptr, nullptr, nullptr, nullptr, 0);

        attn_softmax_kernel<<<dim3(QLEN, NH, BSZ), 256>>>(sc, bd, hprob, lprob);

        pgemm<64,4><<<gt(DH, QLEN, BSZ*NH, 64), 128, S64>>>(
            hprob, lprob, hvT, lvT,
            KLEN, KLEN, KLEN,
            (long)NH*QLEN*KLEN, (long)QLEN*KLEN, (long)NH*DH*KLEN, (long)DH*KLEN, NH,
            BSZ*HD, (long)HD, (long)DH,
            nullptr, hvec, lvec, nullptr, nullptr, nullptr, nullptr, nullptr, 0);

        pgemm<128,0><<<gt(DM, ROWS, 1, 128), 256, S128>>>(
            hvec, lvec, hWoT + (size_t)l*DM*HD, lWoT + (size_t)l*DM*HD,
            HD, HD, HD, 0,0,0,0, 1, DM, 0,0,
            tmp, nullptr, nullptr, nullptr, nullptr, nullptr, nullptr, nullptr, 0);

        ln_kernel<<<ROWS, 256>>>(core, tmp, ln1g + (size_t)l*DM, ln1b + (size_t)l*DM,
                                 core, hcore, lcore, nullptr);

        pgemm<128,2><<<gt(DI, ROWS, 1, 128), 256, S128>>>(
            hcore, lcore, hW1T + (size_t)l*DI*DM, lW1T + (size_t)l*DI*DM,
            DM, DM, DM, 0,0,0,0, 1, DI, 0,0,
            nullptr, hffh, lffh, nullptr, nullptr, b1 + (size_t)l*DI, nullptr, nullptr, 0);

        pgemm<128,1><<<gt(DM, ROWS, 1, 128), 256, S128>>>(
            hffh, lffh, hW2T + (size_t)l*DM*DI, lW2T + (size_t)l*DM*DI,
            DI, DI, DI, 0,0,0,0, 1, DM, 0,0,
            tmp, nullptr, nullptr, nullptr, nullptr, b2 + (size_t)l*DM, nullptr, nullptr, 0);

        ln_kernel<<<ROWS, 256>>>(core, tmp, ln2g + (size_t)l*DM, ln2b + (size_t)l*DM,
                                 core, hcore, lcore,
                                 (l < NL - 1) ? (out_mems + (size_t)(l + 1)*ROWS*DM) : nullptr);
    }

    // logits -> per-tile logsumexp partials (no logits buffer)
    pgemm<128,7><<<gt(NTOK, ROWS, 1, 128), 256, S128>>>(
        hcore, lcore, hemb, lemb,
        DM, DM, DM, 0,0,0,0, 1, 0, 0,0,
        (float*)lsp, nullptr, nullptr, nullptr, nullptr, nullptr, nullptr, nullptr, 0);
    loss_final_kernel<<<ROWS, 128>>>(lsp, core, embW, target, out_loss);

    (void)in_sizes; (void)n_in; (void)out_size;
}

// round 14
// speedup vs baseline: 3.3162x; 1.0243x over previous
#include <cuda_runtime.h>
#include <cuda_bf16.h>
#include <math.h>
#include <stdint.h>

typedef __nv_bfloat16 bf16;
typedef __nv_bfloat162 bf162;
typedef uint32_t u32;

#define QLEN 512
#define MEMLEN 512
#define KLEN 1024
#define BSZ 8
#define NH 16
#define DH 64
#define DM 1024
#define DI 4096
#define NL 6
#define NTOK 32000
#define HD 1024
#define ROWS (QLEN*BSZ)
#define KROWS (KLEN*BSZ)
#define SCALE 0.125f
#define NLSP 256

// ---------------- fp32 scratch ----------------
__device__ float g_core [ROWS*DM];
__device__ float g_tmp  [ROWS*DM];
__device__ float g_vtmp [KROWS*HD];
__device__ float g_bd   [(size_t)NH*ROWS*KLEN];
__device__ float2 g_lsp [(size_t)ROWS*NLSP];

// ---------------- bf16 hi/lo pair scratch ----------------
#define PAIR(name, n) __device__ bf16 h_##name[n]; __device__ bf16 l_##name[n];
PAIR(core, ROWS*DM)
PAIR(mem,  (size_t)NL*ROWS*DM)
PAIR(qrw,  ROWS*DM)
PAIR(qrr,  ROWS*DM)
PAIR(kk,   KROWS*HD)
PAIR(vT,   (size_t)BSZ*NH*DH*KLEN)
PAIR(rk,   KLEN*HD)
PAIR(vec,  ROWS*HD)
PAIR(ffh,  (size_t)ROWS*DI)
PAIR(pos,  KLEN*DM)
PAIR(emb,  (size_t)NTOK*DM)
PAIR(WkvT, (size_t)NL*2*HD*DM)
PAIR(WqT,  (size_t)NL*HD*DM)
PAIR(WrT,  (size_t)NL*HD*DM)
PAIR(WoT,  (size_t)NL*DM*HD)
PAIR(W1T,  (size_t)NL*DI*DM)
PAIR(W2T,  (size_t)NL*DM*DI)

// ---------------- helpers ----------------
__device__ __forceinline__ void mma_bf16(float* d, const u32* a, const u32* b) {
    asm volatile(
        "mma.sync.aligned.m16n8k16.row.col.f32.bf16.bf16.f32 "
        "{%0,%1,%2,%3}, {%4,%5,%6,%7}, {%8,%9}, {%0,%1,%2,%3};\n"
        : "+f"(d[0]), "+f"(d[1]), "+f"(d[2]), "+f"(d[3])
        : "r"(a[0]), "r"(a[1]), "r"(a[2]), "r"(a[3]), "r"(b[0]), "r"(b[1]));
}
#define LDSM4(r0,r1,r2,r3,addr) \
    asm volatile("ldmatrix.sync.aligned.m8n8.x4.shared.b16 {%0,%1,%2,%3}, [%4];" \
        : "=r"(r0), "=r"(r1), "=r"(r2), "=r"(r3) : "r"(addr))
__device__ __forceinline__ void cp16s(u32 sdst, const void* g) {
    asm volatile("cp.async.cg.shared.global [%0], [%1], 16;\n" :: "r"(sdst), "l"(g));
}
#define CP_COMMIT() asm volatile("cp.async.commit_group;\n")
#define CP_WAIT1()  asm volatile("cp.async.wait_group 1;\n")
#define CP_WAIT0()  asm volatile("cp.async.wait_group 0;\n")

__device__ __forceinline__ u32 pk2(float a, float b) {
    bf162 t = __floats2bfloat162_rn(a, b);
    return *(u32*)&t;
}
__device__ __forceinline__ float bres(float x) {
    return x - __bfloat162float(__float2bfloat16(x));
}
__device__ __forceinline__ void pairstore(bf16* H, bf16* L, long off, float v0, float v1) {
    *(u32*)(H + off) = pk2(v0, v1);
    *(u32*)(L + off) = pk2(bres(v0), bres(v1));
}
__device__ __forceinline__ void pairstore4(bf16* H, bf16* L, long off,
                                           float a, float b, float c, float d) {
    uint2 hh = { pk2(a, b), pk2(c, d) };
    uint2 ll = { pk2(bres(a), bres(b)), pk2(bres(c), bres(d)) };
    *(uint2*)(H + off) = hh;
    *(uint2*)(L + off) = ll;
}
__device__ __forceinline__ void lse_comb(float& m, float& s, float m2, float s2) {
    float M = fmaxf(m, m2);
    s = s * expf(m - M) + s2 * expf(m2 - M);
    m = M;
}

// ---------------- pair-bf16 NT GEMM (mma.sync) ----------------
// EPI: 0 fp32  1 fp32+bias  2 pair relu(+bias)  3 dual pair  4 pair
//      6 kv-split  7 logsumexp partials
template <int NTILE, int EPI>
__global__ void __launch_bounds__(NTILE == 128 ? 256 : 128, 2)
pgemm(const bf16* __restrict__ Ah, const bf16* __restrict__ Al,
      const bf16* __restrict__ Bh, const bf16* __restrict__ Bl,
      int K, int lda, int ldb,
      long sA1, long sA2, long sB1, long sB2, int batch2,
      int ldc, long sC1, long sC2,
      float* __restrict__ Cf,
      bf16* __restrict__ Ch, bf16* __restrict__ Cl,
      bf16* __restrict__ Ch2, bf16* __restrict__ Cl2,
      const float* __restrict__ bias, const float* __restrict__ bias2,
      float* __restrict__ Cf2, int ldc2)
{
    constexpr int T    = (NTILE == 128) ? 256 : 128;
    constexpr int ASTB = 128 * 144;
    constexpr int BSTB = NTILE * 144;
    extern __shared__ char smraw[];
    const u32 smS = (u32)__cvta_generic_to_shared(smraw);

    const int bz = blockIdx.z;
    const int b1 = bz / batch2, b2 = bz % batch2;
    Ah += b1 * sA1 + b2 * sA2;  Al += b1 * sA1 + b2 * sA2;
    Bh += b1 * sB1 + b2 * sB2;  Bl += b1 * sB1 + b2 * sB2;
    const long cOff = b1 * sC1 + b2 * sC2;

    const int m0 = blockIdx.y * 128, n0 = blockIdx.x * NTILE;
    const int tid = threadIdx.x, warp = tid >> 5, lane = tid & 31;
    constexpr int NWN = NTILE / 32;
    const int wm = warp / NWN, wn = warp % NWN;

    float acc[4][4][4];
#pragma unroll
    for (int mt = 0; mt < 4; mt++)
#pragma unroll
        for (int nt = 0; nt < 4; nt++)
#pragma unroll
            for (int e = 0; e < 4; e++) acc[mt][nt][e] = 0.f;

    const int KT = K >> 5;

    auto issue = [&](int kt, int st) {
        const int k0 = kt << 5;
        const u32 aB = smS + st * ASTB;
        const u32 bB = smS + 2 * ASTB + st * BSTB;
#pragma unroll
        for (int i = 0; i < 1024 / T; i++) {
            int idx = tid + i * T, r = idx >> 3, q = idx & 7;
            const bf16* src = (q < 4) ? (Ah + (long)(m0 + r) * lda + k0 + q * 8)
                                      : (Al + (long)(m0 + r) * lda + k0 + (q - 4) * 8);
            cp16s(aB + r * 144 + q * 16, src);
        }
#pragma unroll
        for (int i = 0; i < NTILE * 8 / T; i++) {
            int idx = tid + i * T, r = idx >> 3, q = idx & 7;
            const bf16* src = (q < 4) ? (Bh + (long)(n0 + r) * ldb + k0 + q * 8)
                                      : (Bl + (long)(n0 + r) * ldb + k0 + (q - 4) * 8);
            cp16s(bB + r * 144 + q * 16, src);
        }
    };

    const u32 aLane = (u32)((lane & 15) * 144 + (lane >> 4) * 16);
    const u32 bLane = (u32)(((lane >> 4) * 8 + (lane & 7)) * 144 + ((lane >> 3) & 1) * 16);

    issue(0, 0); CP_COMMIT();
    if (KT > 1) issue(1, 1);
    CP_COMMIT();

    for (int kt = 0; kt < KT; kt++) {
        CP_WAIT1();
        __syncthreads();
        const u32 As = smS + (kt & 1) * ASTB + wm * 64 * 144 + aLane;
        const u32 Bs = smS + 2 * ASTB + (kt & 1) * BSTB + wn * 32 * 144 + bLane;

#pragma unroll
        for (int g = 0; g < 2; g++) {
            u32 ah[4][4], alr[4][4], bh[4][2], blr[4][2];
#pragma unroll
            for (int mt = 0; mt < 4; mt++) {
                const u32 ad = As + mt * 2304 + g * 32;
                LDSM4(ah[mt][0], ah[mt][1], ah[mt][2], ah[mt][3], ad);
                LDSM4(alr[mt][0], alr[mt][1], alr[mt][2], alr[mt][3], ad + 64);
            }
#pragma unroll
            for (int p = 0; p < 2; p++) {
                const u32 bd_ = Bs + p * 2304 + g * 32;
                LDSM4(bh[2*p][0], bh[2*p][1], bh[2*p+1][0], bh[2*p+1][1], bd_);
                LDSM4(blr[2*p][0], blr[2*p][1], blr[2*p+1][0], blr[2*p+1][1], bd_ + 64);
            }
#pragma unroll
            for (int mt = 0; mt < 4; mt++)
#pragma unroll
                for (int nt = 0; nt < 4; nt++) {
                    mma_bf16(acc[mt][nt], ah[mt], bh[nt]);
                    mma_bf16(acc[mt][nt], ah[mt], blr[nt]);
                    mma_bf16(acc[mt][nt], alr[mt], bh[nt]);
                }
        }
        __syncthreads();
        if (kt + 2 < KT) issue(kt + 2, kt & 1);
        CP_COMMIT();
    }

    const int gl = lane >> 2, c2 = (lane & 3) * 2;

    if (EPI == 7) {
        float2* red = (float2*)smraw;
        __syncthreads();
#pragma unroll
        for (int mt = 0; mt < 4; mt++)
#pragma unroll
            for (int h = 0; h < 2; h++) {
                float m = -1e30f, s = 0.f;
#pragma unroll
                for (int nt = 0; nt < 4; nt++)
                    m = fmaxf(m, fmaxf(acc[mt][nt][h*2], acc[mt][nt][h*2+1]));
#pragma unroll
                for (int nt = 0; nt < 4; nt++)
                    s += expf(acc[mt][nt][h*2] - m) + expf(acc[mt][nt][h*2+1] - m);
#pragma unroll
                for (int o = 1; o < 4; o <<= 1) {
                    float m2 = __shfl_xor_sync(0xffffffff, m, o);
                    float s2 = __shfl_xor_sync(0xffffffff, s, o);
                    lse_comb(m, s, m2, s2);
                }
                if ((lane & 3) == 0) {
                    int r = wm * 64 + mt * 16 + h * 8 + gl;
                    red[r * NWN + wn] = make_float2(m, s);
                }
            }
        __syncthreads();
        if (tid < 128) {
            float m = -1e30f, s = 0.f;
#pragma unroll
            for (int w = 0; w < NWN; w++) {
                float2 p = red[tid * NWN + w];
                lse_comb(m, s, p.x, p.y);
            }
            ((float2*)Cf)[(long)(m0 + tid) * NLSP + blockIdx.x] = make_float2(m, s);
        }
        return;
    }

#pragma unroll
    for (int mt = 0; mt < 4; mt++)
#pragma unroll
        for (int nt = 0; nt < 4; nt++)
#pragma unroll
            for (int h = 0; h < 2; h++) {
                const int row = m0 + wm * 64 + mt * 16 + gl + h * 8;
                const int col = n0 + wn * 32 + nt * 8 + c2;
                float v0 = acc[mt][nt][h*2], v1 = acc[mt][nt][h*2+1];
                const long off = (long)row * ldc + col + cOff;
                if (EPI == 0) {
                    *(float2*)(Cf + off) = make_float2(v0, v1);
                } else if (EPI == 1) {
                    *(float2*)(Cf + off) = make_float2(v0 + bias[col], v1 + bias[col+1]);
                } else if (EPI == 2) {
                    pairstore(Ch, Cl, off, fmaxf(v0 + bias[col], 0.f), fmaxf(v1 + bias[col+1], 0.f));
                } else if (EPI == 3) {
                    pairstore(Ch,  Cl,  off, v0 + bias[col],  v1 + bias[col+1]);
                    pairstore(Ch2, Cl2, off, v0 + bias2[col], v1 + bias2[col+1]);
                } else if (EPI == 4) {
                    pairstore(Ch, Cl, off, v0, v1);
                } else {  // 6: kv split
                    if (n0 < HD) pairstore(Ch, Cl, (long)row * ldc + col, v0, v1);
                    else *(float2*)(Cf2 + (long)row * ldc2 + (col - HD)) = make_float2(v0, v1);
                }
            }
}

// ---------------- fused attention: S=QK^T(+BD,mask) -> softmax -> PV ----------------
// grid (QLEN/128, BSZ*NH), 256 thr. Warp = 16 q-rows x full 128-j tile.
#define FA_KPITCH 272
#define FA_VPITCH 528
#define FA_KSZ (128*FA_KPITCH)    // 34816
#define FA_VSZ (64*FA_VPITCH)     // 33792
#define FA_STG (FA_KSZ + FA_VSZ)  // 68608
#define FA_SMEM (2*FA_STG)        // 137216

__global__ void __launch_bounds__(256, 1)
fattn(const bf16* __restrict__ Qh, const bf16* __restrict__ Ql,
      const bf16* __restrict__ Kh, const bf16* __restrict__ Kl,
      const bf16* __restrict__ Vh, const bf16* __restrict__ Vl,
      const float* __restrict__ bd,
      bf16* __restrict__ Oh, bf16* __restrict__ Ol)
{
    extern __shared__ char smraw[];
    const u32 smS = (u32)__cvta_generic_to_shared(smraw);
    const int tid = threadIdx.x, warp = tid >> 5, lane = tid & 31;
    const int qt = blockIdx.x, bn = blockIdx.y;
    const int b = bn >> 4, n = bn & 15;
    const int i_base = qt * 128;
    const int i0 = i_base + warp * 16;
    const int jmax = (qt + 5 < 8) ? qt + 5 : 8;   // causal tile skip

    // ---- stage Q through stage-0 K region, hoist A-fragments ----
#pragma unroll
    for (int i = 0; i < 8; i++) {
        int idx = tid + i * 256;
        int r = idx >> 4, q = idx & 15;
        const bf16* src = (q < 8)
            ? (Qh + ((long)(i_base + r) * BSZ + b) * DM + n * 64 + q * 8)
            : (Ql + ((long)(i_base + r) * BSZ + b) * DM + n * 64 + (q - 8) * 8);
        cp16s(smS + r * FA_KPITCH + ((q < 8) ? q * 16 : 128 + (q - 8) * 16), src);
    }
    CP_COMMIT();
    CP_WAIT0();
    __syncthreads();
    u32 qfh[4][4], qfl[4][4];
    {
        const u32 aQ = smS + (u32)((warp * 16 + (lane & 15)) * FA_KPITCH + (lane >> 4) * 16);
#pragma unroll
        for (int g = 0; g < 4; g++) {
            LDSM4(qfh[g][0], qfh[g][1], qfh[g][2], qfh[g][3], aQ + g * 32);
            LDSM4(qfl[g][0], qfl[g][1], qfl[g][2], qfl[g][3], aQ + g * 32 + 128);
        }
    }
    __syncthreads();

    auto loadKV = [&](int jt, int st) {
        const int j0 = jt << 7;
        const u32 kb = smS + (u32)st * FA_STG;
        const u32 vb = kb + FA_KSZ;
#pragma unroll
        for (int i = 0; i < 8; i++) {
            int idx = tid + i * 256;
            int r = idx >> 4, q = idx & 15;
            const bf16* src = (q < 8)
                ? (Kh + ((long)(j0 + r) * BSZ + b) * HD + n * 64 + q * 8)
                : (Kl + ((long)(j0 + r) * BSZ + b) * HD + n * 64 + (q - 8) * 8);
            cp16s(kb + r * FA_KPITCH + ((q < 8) ? q * 16 : 128 + (q - 8) * 16), src);
        }
#pragma unroll
        for (int i = 0; i < 8; i++) {
            int idx = tid + i * 256;
            int r = idx >> 5, q = idx & 31;
            const bf16* src = (q < 16)
                ? (Vh + ((long)bn * DH + r) * KLEN + j0 + q * 8)
                : (Vl + ((long)bn * DH + r) * KLEN + j0 + (q - 16) * 8);
            cp16s(vb + r * FA_VPITCH + ((q < 16) ? q * 16 : 256 + (q - 16) * 16), src);
        }
        CP_COMMIT();
    };

    float acc_o[8][4];
#pragma unroll
    for (int d = 0; d < 8; d++)
#pragma unroll
        for (int e = 0; e < 4; e++) acc_o[d][e] = 0.f;
    float mrow[2] = { -1e30f, -1e30f }, srow[2] = { 0.f, 0.f };

    loadKV(0, 0);
    if (jmax > 1) loadKV(1, 1);

    const int g = lane >> 2, c2 = (lane & 3) * 2;
    const int irow0 = i0 + g, irow1 = i0 + g + 8;

    for (int jt = 0; jt < jmax; jt++) {
        CP_WAIT1();
        __syncthreads();
        const int j0 = jt << 7;
        const u32 kb = smS + (u32)(jt & 1) * FA_STG;
        const u32 vb = kb + FA_KSZ;

        // ---- S tile (3-term pair) ----
        float acc_s[16][4];
#pragma unroll
        for (int nt = 0; nt < 16; nt++)
#pragma unroll
            for (int e = 0; e < 4; e++) acc_s[nt][e] = 0.f;

        const u32 bK = kb + (u32)(((lane >> 4) * 8 + (lane & 7)) * FA_KPITCH + ((lane >> 3) & 1) * 16);
#pragma unroll
        for (int ntp = 0; ntp < 8; ntp++) {
#pragma unroll
            for (int gg = 0; gg < 4; gg++) {
                u32 h0, h1, h2, h3, l0, l1, l2, l3;
                const u32 ad = bK + (u32)(ntp * 16 * FA_KPITCH + gg * 32);
                LDSM4(h0, h1, h2, h3, ad);
                LDSM4(l0, l1, l2, l3, ad + 128);
                u32 bhA[2] = { h0, h1 }, bhB[2] = { h2, h3 };
                u32 blA[2] = { l0, l1 }, blB[2] = { l2, l3 };
                mma_bf16(acc_s[2*ntp],   qfh[gg], bhA);
                mma_bf16(acc_s[2*ntp],   qfh[gg], blA);
                mma_bf16(acc_s[2*ntp],   qfl[gg], bhA);
                mma_bf16(acc_s[2*ntp+1], qfh[gg], bhB);
                mma_bf16(acc_s[2*ntp+1], qfh[gg], blB);
                mma_bf16(acc_s[2*ntp+1], qfl[gg], bhB);
            }
        }

        // ---- +BD, mask, scale; online softmax ----
        float scl[2];
#pragma unroll
        for (int h = 0; h < 2; h++) {
            const int i = (h == 0) ? irow0 : irow1;
            const int shift = QLEN - 1 - i;
            const int limit = i + MEMLEN;
            const float* bdr = bd + ((long)n * ROWS + ((long)i * BSZ + b)) * KLEN + shift;
            float tm = -1e30f;
#pragma unroll
            for (int nt = 0; nt < 16; nt++) {
#pragma unroll
                for (int e = 0; e < 2; e++) {
                    int jg = j0 + nt * 8 + c2 + e;
                    float v = (jg <= limit) ? (acc_s[nt][h*2+e] + bdr[jg]) * SCALE : -1e30f;
                    acc_s[nt][h*2+e] = v;
                    tm = fmaxf(tm, v);
                }
            }
            tm = fmaxf(tm, __shfl_xor_sync(0xffffffff, tm, 1));
            tm = fmaxf(tm, __shfl_xor_sync(0xffffffff, tm, 2));
            float mn = fmaxf(mrow[h], tm);
            scl[h] = expf(mrow[h] - mn);
            mrow[h] = mn;
            float ps = 0.f;
#pragma unroll
            for (int nt = 0; nt < 16; nt++) {
#pragma unroll
                for (int e = 0; e < 2; e++) {
                    float p = expf(acc_s[nt][h*2+e] - mn);
                    acc_s[nt][h*2+e] = p;
                    ps += p;
                }
            }
            ps += __shfl_xor_sync(0xffffffff, ps, 1);
            ps += __shfl_xor_sync(0xffffffff, ps, 2);
            srow[h] = srow[h] * scl[h] + ps;
        }
#pragma unroll
        for (int d = 0; d < 8; d++) {
            acc_o[d][0] *= scl[0]; acc_o[d][1] *= scl[0];
            acc_o[d][2] *= scl[1]; acc_o[d][3] *= scl[1];
        }

        // ---- PV: P (register pair) x V (smem pair) ----
        const u32 bV = vb + (u32)(((lane >> 4) * 8 + (lane & 7)) * FA_VPITCH + ((lane >> 3) & 1) * 16);
#pragma unroll
        for (int kk = 0; kk < 8; kk++) {
            u32 aPh[4], aPl[4];
            aPh[0] = pk2(acc_s[2*kk][0], acc_s[2*kk][1]);
            aPh[1] = pk2(acc_s[2*kk][2], acc_s[2*kk][3]);
            aPh[2] = pk2(acc_s[2*kk+1][0], acc_s[2*kk+1][1]);
            aPh[3] = pk2(acc_s[2*kk+1][2], acc_s[2*kk+1][3]);
            aPl[0] = pk2(bres(acc_s[2*kk][0]), bres(acc_s[2*kk][1]));
            aPl[1] = pk2(bres(acc_s[2*kk][2]), bres(acc_s[2*kk][3]));
            aPl[2] = pk2(bres(acc_s[2*kk+1][0]), bres(acc_s[2*kk+1][1]));
            aPl[3] = pk2(bres(acc_s[2*kk+1][2]), bres(acc_s[2*kk+1][3]));
#pragma unroll
            for (int dp = 0; dp < 4; dp++) {
                u32 h0, h1, h2, h3, l0, l1, l2, l3;
                const u32 ad = bV + (u32)(dp * 16 * FA_VPITCH + kk * 32);
                LDSM4(h0, h1, h2, h3, ad);
                LDSM4(l0, l1, l2, l3, ad + 256);
                u32 vhA[2] = { h0, h1 }, vhB[2] = { h2, h3 };
                u32 vlA[2] = { l0, l1 }, vlB[2] = { l2, l3 };
                mma_bf16(acc_o[2*dp],   aPh, vhA);
                mma_bf16(acc_o[2*dp],   aPh, vlA);
                mma_bf16(acc_o[2*dp],   aPl, vhA);
                mma_bf16(acc_o[2*dp+1], aPh, vhB);
                mma_bf16(acc_o[2*dp+1], aPh, vlB);
                mma_bf16(acc_o[2*dp+1], aPl, vhB);
            }
        }
        __syncthreads();
        if (jt + 2 < jmax) loadKV(jt + 2, jt & 1);
    }

    // ---- normalize + pair store ----
    const float inv0 = 1.f / srow[0], inv1 = 1.f / srow[1];
#pragma unroll
    for (int d = 0; d < 8; d++) {
        const int col = n * 64 + d * 8 + c2;
        const long off0 = ((long)irow0 * BSZ + b) * HD + col;
        const long off1 = ((long)irow1 * BSZ + b) * HD + col;
        pairstore(Oh, Ol, off0, acc_o[d][0] * inv0, acc_o[d][1] * inv0);
        pairstore(Oh, Ol, off1, acc_o[d][2] * inv1, acc_o[d][3] * inv1);
    }
}

// ---------------- converters ----------------

__global__ void transpose_pair(const float* __restrict__ in, bf16* __restrict__ oh,
                               bf16* __restrict__ ol, int R, int C)
{
    __shared__ float t[32][33];
    const long zo = (long)blockIdx.z * R * C;
    in += zo; oh += zo; ol += zo;
    const int c0 = blockIdx.x * 32, r0 = blockIdx.y * 32;
    const int tx = threadIdx.x, ty = threadIdx.y;   // (8, 32)
    {
        float4 v = *(const float4*)(in + (long)(r0 + ty) * C + c0 + tx * 4);
        t[ty][tx*4+0] = v.x; t[ty][tx*4+1] = v.y; t[ty][tx*4+2] = v.z; t[ty][tx*4+3] = v.w;
    }
    __syncthreads();
    {
        float a = t[tx*4+0][ty], b = t[tx*4+1][ty], c = t[tx*4+2][ty], d = t[tx*4+3][ty];
        long o = (long)(c0 + ty) * R + r0 + tx * 4;
        pairstore4(oh, ol, o, a, b, c, d);
    }
}

__global__ void convert_pair(const float* __restrict__ in, bf16* __restrict__ oh,
                             bf16* __restrict__ ol, long n4)
{
    long i = (long)blockIdx.x * 256 + threadIdx.x;
    if (i >= n4) return;
    float4 v = *(const float4*)(in + i * 4);
    pairstore4(oh, ol, i * 4, v.x, v.y, v.z, v.w);
}

__global__ void vtrans_kernel(const float* __restrict__ v, bf16* __restrict__ oh,
                              bf16* __restrict__ ol)
{
    __shared__ float t[32][33];
    const int bn = blockIdx.z, b = bn >> 4, n = bn & 15;
    const int j0 = blockIdx.x * 32, d0 = blockIdx.y * 32;
    const int tx = threadIdx.x, ty = threadIdx.y;   // (8, 32)
    {
        float4 x = *(const float4*)(v + ((long)(j0 + ty) * BSZ + b) * HD + n * 64 + d0 + tx * 4);
        t[ty][tx*4+0] = x.x; t[ty][tx*4+1] = x.y; t[ty][tx*4+2] = x.z; t[ty][tx*4+3] = x.w;
    }
    __syncthreads();
    {
        float a = t[tx*4+0][ty], c = t[tx*4+1][ty], d = t[tx*4+2][ty], e = t[tx*4+3][ty];
        long o = ((long)bn * DH + d0 + ty) * KLEN + j0 + tx * 4;
        pairstore4(oh, ol, o, a, c, d, e);
    }
}

// ---------------- elementwise / reductions ----------------

__global__ void embed_kernel(const int* __restrict__ data, const float* __restrict__ embW,
                             float* __restrict__ core, bf16* __restrict__ ch,
                             bf16* __restrict__ cl, float* __restrict__ outm)
{
    long i = (long)blockIdx.x * 256 + threadIdx.x;
    if (i >= (long)ROWS * DM / 4) return;
    int r = (int)(i >> 8);
    float4 v = *(const float4*)(embW + (long)data[r] * DM + (i & 255) * 4);
    *(float4*)(core + i * 4) = v;
    *(float4*)(outm + i * 4) = v;
    pairstore4(ch, cl, i * 4, v.x, v.y, v.z, v.w);
}

__global__ void pos_kernel(bf16* __restrict__ ph, bf16* __restrict__ pl)
{
    long idx = (long)blockIdx.x * 256 + threadIdx.x;
    if (idx >= (long)KLEN * DM) return;
    int j = (int)(idx >> 10), d = (int)(idx & 1023);
    float p = (float)(KLEN - 1 - j);
    int t = (d < 512) ? d : d - 512;
    float invf = expf(-((2.0f * (float)t) / (float)DM) * logf(10000.0f));
    float a = p * invf;
    float x = (d < 512) ? sinf(a) : cosf(a);
    ph[idx] = __float2bfloat16(x);
    pl[idx] = __float2bfloat16(bres(x));
}

__global__ void ln_kernel(const float* __restrict__ x, const float* __restrict__ y,
                          const float* __restrict__ g, const float* __restrict__ b,
                          float* __restrict__ outf, bf16* __restrict__ oh,
                          bf16* __restrict__ ol, float* __restrict__ memsf)
{
    const int r = blockIdx.x, t = threadIdx.x;
    __shared__ float red[256];
    const long base = (long)r * DM + t * 4;
    float4 xv = *(const float4*)(x + base);
    float4 yv = *(const float4*)(y + base);
    float loc[4] = { xv.x + yv.x, xv.y + yv.y, xv.z + yv.z, xv.w + yv.w };
    float s = loc[0] + loc[1] + loc[2] + loc[3];
    red[t] = s; __syncthreads();
    for (int o = 128; o > 0; o >>= 1) { if (t < o) red[t] += red[t + o]; __syncthreads(); }
    const float mu = red[0] * (1.0f / DM);
    __syncthreads();
    float s2 = 0.f;
#pragma unroll
    for (int k = 0; k < 4; k++) { float d = loc[k] - mu; s2 += d * d; }
    red[t] = s2; __syncthreads();
    for (int o = 128; o > 0; o >>= 1) { if (t < o) red[t] += red[t + o]; __syncthreads(); }
    const float rstd = rsqrtf(red[0] * (1.0f / DM) + 1e-5f);
    float4 gv = *(const float4*)(g + t * 4);
    float4 bv = *(const float4*)(b + t * 4);
    float4 o4;
    o4.x = (loc[0] - mu) * rstd * gv.x + bv.x;
    o4.y = (loc[1] - mu) * rstd * gv.y + bv.y;
    o4.z = (loc[2] - mu) * rstd * gv.z + bv.z;
    o4.w = (loc[3] - mu) * rstd * gv.w + bv.w;
    *(float4*)(outf + base) = o4;
    if (memsf) *(float4*)(memsf + base) = o4;
    pairstore4(oh, ol, base, o4.x, o4.y, o4.z, o4.w);
}

__global__ void loss_final_kernel(const float2* __restrict__ lsp,
                                  const float* __restrict__ core,
                                  const float* __restrict__ embW,
                                  const int* __restrict__ target,
                                  float* __restrict__ out)
{
    const int r = blockIdx.x, t = threadIdx.x;
    __shared__ float rm[128], rs[128], rd[128];
    float m = -1e30f, s = 0.f;
    for (int j = t; j < NTOK / 128; j += 128) {
        float2 p = lsp[(long)r * NLSP + j];
        lse_comb(m, s, p.x, p.y);
    }
    const float* cr = core + (long)r * DM;
    const float* er = embW + (long)target[r] * DM;
    float d = 0.f;
    for (int j = t; j < DM / 4; j += 128) {
        float4 a = *(const float4*)(cr + j * 4);
        float4 b = *(const float4*)(er + j * 4);
        d += a.x * b.x + a.y * b.y + a.z * b.z + a.w * b.w;
    }
    rm[t] = m; rs[t] = s; rd[t] = d; __syncthreads();
    for (int o = 64; o > 0; o >>= 1) {
        if (t < o) {
            lse_comb(rm[t], rs[t], rm[t + o], rs[t + o]);
            rd[t] += rd[t + o];
        }
        __syncthreads();
    }
    if (t == 0) out[r] = (logf(rs[0]) + rm[0]) - rd[0];
}

// ---------------- host ----------------

#define S128 73728
#define GSA(p, s) cudaGetSymbolAddress((void**)&p, s)

static inline dim3 gt(int N, int M, int bz, int ntile) { return dim3(N / ntile, M / 128, bz); }

extern "C" void kernel_launch(void* const* d_in, const int* in_sizes, int n_in,
                              void* d_out, int out_size)
{
    const int*   data   = (const int*)  d_in[0];
    const int*   target = (const int*)  d_in[1];
    const float* memory = (const float*)d_in[2];
    const float* embW   = (const float*)d_in[3];
    const float* rwb    = (const float*)d_in[4];
    const float* rrb    = (const float*)d_in[5];
    const float* Wq     = (const float*)d_in[6];
    const float* Wkv    = (const float*)d_in[7];
    const float* Wr     = (const float*)d_in[8];
    const float* Wo     = (const float*)d_in[9];
    const float* W1     = (const float*)d_in[10];
    const float* b1     = (const float*)d_in[11];
    const float* W2     = (const float*)d_in[12];
    const float* b2     = (const float*)d_in[13];
    const float* ln1g   = (const float*)d_in[14];
    const float* ln1b   = (const float*)d_in[15];
    const float* ln2g   = (const float*)d_in[16];
    const float* ln2b   = (const float*)d_in[17];

    float* out      = (float*)d_out;
    float* out_loss = out;
    float* out_mems = out + ROWS;

    float *core, *tmp, *vtmp, *bd;
    float2* lsp;
    GSA(core, g_core); GSA(tmp, g_tmp); GSA(vtmp, g_vtmp);
    GSA(bd, g_bd); GSA(lsp, g_lsp);

    bf16 *hcore,*lcore,*hmem,*lmem,*hqrw,*lqrw,*hqrr,*lqrr,*hk,*lk,*hvT,*lvT,*hrk,*lrk,
         *hvec,*lvec,*hffh,*lffh,*hpos,*lpos,*hemb,*lemb,
         *hWkvT,*lWkvT,*hWqT,*lWqT,*hWrT,*lWrT,*hWoT,*lWoT,*hW1T,*lW1T,*hW2T,*lW2T;
    GSA(hcore,h_core); GSA(lcore,l_core); GSA(hmem,h_mem); GSA(lmem,l_mem);
    GSA(hqrw,h_qrw); GSA(lqrw,l_qrw); GSA(hqrr,h_qrr); GSA(lqrr,l_qrr);
    GSA(hk,h_kk); GSA(lk,l_kk); GSA(hvT,h_vT); GSA(lvT,l_vT);
    GSA(hrk,h_rk); GSA(lrk,l_rk);
    GSA(hvec,h_vec); GSA(lvec,l_vec); GSA(hffh,h_ffh); GSA(lffh,l_ffh);
    GSA(hpos,h_pos); GSA(lpos,l_pos); GSA(hemb,h_emb); GSA(lemb,l_emb);
    GSA(hWkvT,h_WkvT); GSA(lWkvT,l_WkvT); GSA(hWqT,h_WqT); GSA(lWqT,l_WqT);
    GSA(hWrT,h_WrT); GSA(lWrT,l_WrT); GSA(hWoT,h_WoT); GSA(lWoT,l_WoT);
    GSA(hW1T,h_W1T); GSA(lW1T,l_W1T); GSA(hW2T,h_W2T); GSA(lW2T,l_W2T);

    // smem opt-in for EVERY launched instantiation
    cudaFuncSetAttribute(pgemm<128,0>, cudaFuncAttributeMaxDynamicSharedMemorySize, S128);
    cudaFuncSetAttribute(pgemm<128,1>, cudaFuncAttributeMaxDynamicSharedMemorySize, S128);
    cudaFuncSetAttribute(pgemm<128,2>, cudaFuncAttributeMaxDynamicSharedMemorySize, S128);
    cudaFuncSetAttribute(pgemm<128,3>, cudaFuncAttributeMaxDynamicSharedMemorySize, S128);
    cudaFuncSetAttribute(pgemm<128,4>, cudaFuncAttributeMaxDynamicSharedMemorySize, S128);
    cudaFuncSetAttribute(pgemm<128,6>, cudaFuncAttributeMaxDynamicSharedMemorySize, S128);
    cudaFuncSetAttribute(pgemm<128,7>, cudaFuncAttributeMaxDynamicSharedMemorySize, S128);
    cudaFuncSetAttribute(fattn, cudaFuncAttributeMaxDynamicSharedMemorySize, FA_SMEM);

    const dim3 tb(8, 32);
    transpose_pair<<<dim3(2*HD/32, DM/32, NL), tb>>>(Wkv, hWkvT, lWkvT, DM, 2*HD);
    transpose_pair<<<dim3(HD/32, DM/32, NL), tb>>>(Wq, hWqT, lWqT, DM, HD);
    transpose_pair<<<dim3(HD/32, DM/32, NL), tb>>>(Wr, hWrT, lWrT, DM, HD);
    transpose_pair<<<dim3(DM/32, HD/32, NL), tb>>>(Wo, hWoT, lWoT, HD, DM);
    transpose_pair<<<dim3(DI/32, DM/32, NL), tb>>>(W1, hW1T, lW1T, DM, DI);
    transpose_pair<<<dim3(DM/32, DI/32, NL), tb>>>(W2, hW2T, lW2T, DI, DM);
    {
        long n1 = (long)NL*ROWS*DM/4;
        convert_pair<<<(int)((n1 + 255)/256), 256>>>(memory, hmem, lmem, n1);
        long n2 = (long)NTOK*DM/4;
        convert_pair<<<(int)((n2 + 255)/256), 256>>>(embW, hemb, lemb, n2);
    }

    embed_kernel<<<(ROWS*DM/4 + 255)/256, 256>>>(data, embW, core, hcore, lcore, out_mems);
    pos_kernel<<<(KLEN*DM + 255)/256, 256>>>(hpos, lpos);

    for (int l = 0; l < NL; l++) {
        const bf16* hWkvl = hWkvT + (size_t)l*2*HD*DM;
        const bf16* lWkvl = lWkvT + (size_t)l*2*HD*DM;

        pgemm<128,6><<<gt(2*HD, ROWS, 1, 128), 256, S128>>>(
            hmem + (size_t)l*ROWS*DM, lmem + (size_t)l*ROWS*DM, hWkvl, lWkvl,
            DM, DM, DM, 0,0,0,0, 1, HD, 0,0,
            nullptr, hk, lk, nullptr, nullptr, nullptr, nullptr, vtmp, HD);
        pgemm<128,6><<<gt(2*HD, ROWS, 1, 128), 256, S128>>>(
            hcore, lcore, hWkvl, lWkvl,
            DM, DM, DM, 0,0,0,0, 1, HD, 0,0,
            nullptr, hk + (size_t)ROWS*HD, lk + (size_t)ROWS*HD, nullptr, nullptr,
            nullptr, nullptr, vtmp + (size_t)ROWS*HD, HD);

        vtrans_kernel<<<dim3(KLEN/32, DH/32, BSZ*NH), tb>>>(vtmp, hvT, lvT);

        pgemm<128,3><<<gt(HD, ROWS, 1, 128), 256, S128>>>(
            hcore, lcore, hWqT + (size_t)l*HD*DM, lWqT + (size_t)l*HD*DM,
            DM, DM, DM, 0,0,0,0, 1, DM, 0,0,
            nullptr, hqrw, lqrw, hqrr, lqrr, rwb, rrb, nullptr, 0);

        pgemm<128,4><<<gt(HD, KLEN, 1, 128), 256, S128>>>(
            hpos, lpos, hWrT + (size_t)l*HD*DM, lWrT + (size_t)l*HD*DM,
            DM, DM, DM, 0,0,0,0, 1, HD, 0,0,
            nullptr, hrk, lrk, nullptr, nullptr, nullptr, nullptr, nullptr, 0);

        // BD raw (batched over heads)
        pgemm<128,0><<<gt(KLEN, ROWS, NH, 128), 256, S128>>>(
            hqrr, lqrr, hrk, lrk,
            DH, DM, HD,
            0, (long)DH, 0, (long)DH, NH,
            KLEN, 0, (long)ROWS*KLEN,
            bd, nullptr, nullptr, nullptr, nullptr, nullptr, nullptr, nullptr, 0);

        // fused attention: AC + BD-add + mask + softmax + PV -> vec pair
        fattn<<<dim3(QLEN/128, BSZ*NH), 256, FA_SMEM>>>(
            hqrw, lqrw, hk, lk, hvT, lvT, bd, hvec, lvec);

        pgemm<128,0><<<gt(DM, ROWS, 1, 128), 256, S128>>>(
            hvec, lvec, hWoT + (size_t)l*DM*HD, lWoT + (size_t)l*DM*HD,
            HD, HD, HD, 0,0,0,0, 1, DM, 0,0,
            tmp, nullptr, nullptr, nullptr, nullptr, nullptr, nullptr, nullptr, 0);

        ln_kernel<<<ROWS, 256>>>(core, tmp, ln1g + (size_t)l*DM, ln1b + (size_t)l*DM,
                                 core, hcore, lcore, nullptr);

        pgemm<128,2><<<gt(DI, ROWS, 1, 128), 256, S128>>>(
            hcore, lcore, hW1T + (size_t)l*DI*DM, lW1T + (size_t)l*DI*DM,
            DM, DM, DM, 0,0,0,0, 1, DI, 0,0,
            nullptr, hffh, lffh, nullptr, nullptr, b1 + (size_t)l*DI, nullptr, nullptr, 0);

        pgemm<128,1><<<gt(DM, ROWS, 1, 128), 256, S128>>>(
            hffh, lffh, hW2T + (size_t)l*DM*DI, lW2T + (size_t)l*DM*DI,
            DI, DI, DI, 0,0,0,0, 1, DM, 0,0,
            tmp, nullptr, nullptr, nullptr, nullptr, b2 + (size_t)l*DM, nullptr, nullptr, 0);

        ln_kernel<<<ROWS, 256>>>(core, tmp, ln2g + (size_t)l*DM, ln2b + (size_t)l*DM,
                                 core, hcore, lcore,
                                 (l < NL - 1) ? (out_mems + (size_t)(l + 1)*ROWS*DM) : nullptr);
    }

    pgemm<128,7><<<gt(NTOK, ROWS, 1, 128), 256, S128>>>(
        hcore, lcore, hemb, lemb,
        DM, DM, DM, 0,0,0,0, 1, 0, 0,0,
        (float*)lsp, nullptr, nullptr, nullptr, nullptr, nullptr, nullptr, nullptr, 0);
    loss_final_kernel<<<ROWS, 128>>>(lsp, core, embW, target, out_loss);

    (void)in_sizes; (void)n_in; (void)out_size;
}

// round 15
// speedup vs baseline: 3.3891x; 1.0220x over previous
#include <cuda_runtime.h>
#include <cuda_bf16.h>
#include <cuda_fp16.h>
#include <math.h>
#include <stdint.h>

typedef __nv_bfloat16 bf16;
typedef __nv_bfloat162 bf162;
typedef uint32_t u32;

#define QLEN 512
#define MEMLEN 512
#define KLEN 1024
#define BSZ 8
#define NH 16
#define DH 64
#define DM 1024
#define DI 4096
#define NL 6
#define NTOK 32000
#define HD 1024
#define ROWS (QLEN*BSZ)
#define KROWS (KLEN*BSZ)
#define SCALE 0.125f
#define NLSP 256

// ---------------- fp32 scratch ----------------
__device__ float g_core [ROWS*DM];
__device__ float g_tmp  [ROWS*DM];
__device__ __half g_bd  [(size_t)NH*ROWS*KLEN];
__device__ float2 g_lsp [(size_t)ROWS*NLSP];

// ---------------- bf16 hi/lo pair scratch ----------------
#define PAIR(name, n) __device__ bf16 h_##name[n]; __device__ bf16 l_##name[n];
PAIR(core, ROWS*DM)
PAIR(mem,  (size_t)NL*ROWS*DM)
PAIR(qrw,  ROWS*DM)
PAIR(qrr,  ROWS*DM)
PAIR(kk,   KROWS*HD)
PAIR(vv,   KROWS*HD)
PAIR(rk,   KLEN*HD)
PAIR(vec,  ROWS*HD)
PAIR(ffh,  (size_t)ROWS*DI)
PAIR(pos,  KLEN*DM)
PAIR(emb,  (size_t)NTOK*DM)
PAIR(WkvT, (size_t)NL*2*HD*DM)
PAIR(WqT,  (size_t)NL*HD*DM)
PAIR(WrT,  (size_t)NL*HD*DM)
PAIR(WoT,  (size_t)NL*DM*HD)
PAIR(W1T,  (size_t)NL*DI*DM)
PAIR(W2T,  (size_t)NL*DM*DI)

// ---------------- helpers ----------------
__device__ __forceinline__ void mma_bf16(float* d, const u32* a, const u32* b) {
    asm volatile(
        "mma.sync.aligned.m16n8k16.row.col.f32.bf16.bf16.f32 "
        "{%0,%1,%2,%3}, {%4,%5,%6,%7}, {%8,%9}, {%0,%1,%2,%3};\n"
        : "+f"(d[0]), "+f"(d[1]), "+f"(d[2]), "+f"(d[3])
        : "r"(a[0]), "r"(a[1]), "r"(a[2]), "r"(a[3]), "r"(b[0]), "r"(b[1]));
}
#define LDSM4(r0,r1,r2,r3,addr) \
    asm volatile("ldmatrix.sync.aligned.m8n8.x4.shared.b16 {%0,%1,%2,%3}, [%4];" \
        : "=r"(r0), "=r"(r1), "=r"(r2), "=r"(r3) : "r"(addr))
#define LDSM4T(r0,r1,r2,r3,addr) \
    asm volatile("ldmatrix.sync.aligned.m8n8.x4.trans.shared.b16 {%0,%1,%2,%3}, [%4];" \
        : "=r"(r0), "=r"(r1), "=r"(r2), "=r"(r3) : "r"(addr))
__device__ __forceinline__ void cp16s(u32 sdst, const void* g) {
    asm volatile("cp.async.cg.shared.global [%0], [%1], 16;\n" :: "r"(sdst), "l"(g));
}
#define CP_COMMIT() asm volatile("cp.async.commit_group;\n")
#define CP_WAIT1()  asm volatile("cp.async.wait_group 1;\n")
#define CP_WAIT0()  asm volatile("cp.async.wait_group 0;\n")

__device__ __forceinline__ u32 pk2(float a, float b) {
    bf162 t = __floats2bfloat162_rn(a, b);
    return *(u32*)&t;
}
__device__ __forceinline__ float bres(float x) {
    return x - __bfloat162float(__float2bfloat16(x));
}
__device__ __forceinline__ void pairstore(bf16* H, bf16* L, long off, float v0, float v1) {
    *(u32*)(H + off) = pk2(v0, v1);
    *(u32*)(L + off) = pk2(bres(v0), bres(v1));
}
__device__ __forceinline__ void pairstore4(bf16* H, bf16* L, long off,
                                           float a, float b, float c, float d) {
    uint2 hh = { pk2(a, b), pk2(c, d) };
    uint2 ll = { pk2(bres(a), bres(b)), pk2(bres(c), bres(d)) };
    *(uint2*)(H + off) = hh;
    *(uint2*)(L + off) = ll;
}
__device__ __forceinline__ void lse_comb(float& m, float& s, float m2, float s2) {
    float M = fmaxf(m, m2);
    s = s * expf(m - M) + s2 * expf(m2 - M);
    m = M;
}

// ---------------- pair-bf16 NT GEMM (mma.sync) ----------------
// EPI: 0 fp32  1 fp32+bias  2 pair relu(+bias)  3 dual pair  4 pair
//      6 kv-split (k pair | v pair at col-HD)  7 logsumexp partials  8 fp16 store
template <int NTILE, int EPI>
__global__ void __launch_bounds__(NTILE == 128 ? 256 : 128, 2)
pgemm(const bf16* __restrict__ Ah, const bf16* __restrict__ Al,
      const bf16* __restrict__ Bh, const bf16* __restrict__ Bl,
      int K, int lda, int ldb,
      long sA1, long sA2, long sB1, long sB2, int batch2,
      int ldc, long sC1, long sC2,
      float* __restrict__ Cf,
      bf16* __restrict__ Ch, bf16* __restrict__ Cl,
      bf16* __restrict__ Ch2, bf16* __restrict__ Cl2,
      const float* __restrict__ bias, const float* __restrict__ bias2,
      float* __restrict__ Cf2, int ldc2)
{
    constexpr int T    = (NTILE == 128) ? 256 : 128;
    constexpr int ASTB = 128 * 144;
    constexpr int BSTB = NTILE * 144;
    extern __shared__ char smraw[];
    const u32 smS = (u32)__cvta_generic_to_shared(smraw);

    const int bz = blockIdx.z;
    const int b1 = bz / batch2, b2 = bz % batch2;
    Ah += b1 * sA1 + b2 * sA2;  Al += b1 * sA1 + b2 * sA2;
    Bh += b1 * sB1 + b2 * sB2;  Bl += b1 * sB1 + b2 * sB2;
    const long cOff = b1 * sC1 + b2 * sC2;

    const int m0 = blockIdx.y * 128, n0 = blockIdx.x * NTILE;
    const int tid = threadIdx.x, warp = tid >> 5, lane = tid & 31;
    constexpr int NWN = NTILE / 32;
    const int wm = warp / NWN, wn = warp % NWN;

    float acc[4][4][4];
#pragma unroll
    for (int mt = 0; mt < 4; mt++)
#pragma unroll
        for (int nt = 0; nt < 4; nt++)
#pragma unroll
            for (int e = 0; e < 4; e++) acc[mt][nt][e] = 0.f;

    const int KT = K >> 5;

    auto issue = [&](int kt, int st) {
        const int k0 = kt << 5;
        const u32 aB = smS + st * ASTB;
        const u32 bB = smS + 2 * ASTB + st * BSTB;
#pragma unroll
        for (int i = 0; i < 1024 / T; i++) {
            int idx = tid + i * T, r = idx >> 3, q = idx & 7;
            const bf16* src = (q < 4) ? (Ah + (long)(m0 + r) * lda + k0 + q * 8)
                                      : (Al + (long)(m0 + r) * lda + k0 + (q - 4) * 8);
            cp16s(aB + r * 144 + q * 16, src);
        }
#pragma unroll
        for (int i = 0; i < NTILE * 8 / T; i++) {
            int idx = tid + i * T, r = idx >> 3, q = idx & 7;
            const bf16* src = (q < 4) ? (Bh + (long)(n0 + r) * ldb + k0 + q * 8)
                                      : (Bl + (long)(n0 + r) * ldb + k0 + (q - 4) * 8);
            cp16s(bB + r * 144 + q * 16, src);
        }
    };

    const u32 aLane = (u32)((lane & 15) * 144 + (lane >> 4) * 16);
    const u32 bLane = (u32)(((lane >> 4) * 8 + (lane & 7)) * 144 + ((lane >> 3) & 1) * 16);

    issue(0, 0); CP_COMMIT();
    if (KT > 1) issue(1, 1);
    CP_COMMIT();

    for (int kt = 0; kt < KT; kt++) {
        CP_WAIT1();
        __syncthreads();
        const u32 As = smS + (kt & 1) * ASTB + wm * 64 * 144 + aLane;
        const u32 Bs = smS + 2 * ASTB + (kt & 1) * BSTB + wn * 32 * 144 + bLane;

#pragma unroll
        for (int g = 0; g < 2; g++) {
            u32 ah[4][4], alr[4][4], bh[4][2], blr[4][2];
#pragma unroll
            for (int mt = 0; mt < 4; mt++) {
                const u32 ad = As + mt * 2304 + g * 32;
                LDSM4(ah[mt][0], ah[mt][1], ah[mt][2], ah[mt][3], ad);
                LDSM4(alr[mt][0], alr[mt][1], alr[mt][2], alr[mt][3], ad + 64);
            }
#pragma unroll
            for (int p = 0; p < 2; p++) {
                const u32 bd_ = Bs + p * 2304 + g * 32;
                LDSM4(bh[2*p][0], bh[2*p][1], bh[2*p+1][0], bh[2*p+1][1], bd_);
                LDSM4(blr[2*p][0], blr[2*p][1], blr[2*p+1][0], blr[2*p+1][1], bd_ + 64);
            }
#pragma unroll
            for (int mt = 0; mt < 4; mt++)
#pragma unroll
                for (int nt = 0; nt < 4; nt++) {
                    mma_bf16(acc[mt][nt], ah[mt], bh[nt]);
                    mma_bf16(acc[mt][nt], ah[mt], blr[nt]);
                    mma_bf16(acc[mt][nt], alr[mt], bh[nt]);
                }
        }
        __syncthreads();
        if (kt + 2 < KT) issue(kt + 2, kt & 1);
        CP_COMMIT();
    }

    const int gl = lane >> 2, c2 = (lane & 3) * 2;

    if (EPI == 7) {
        float2* red = (float2*)smraw;
        __syncthreads();
#pragma unroll
        for (int mt = 0; mt < 4; mt++)
#pragma unroll
            for (int h = 0; h < 2; h++) {
                float m = -1e30f, s = 0.f;
#pragma unroll
                for (int nt = 0; nt < 4; nt++)
                    m = fmaxf(m, fmaxf(acc[mt][nt][h*2], acc[mt][nt][h*2+1]));
#pragma unroll
                for (int nt = 0; nt < 4; nt++)
                    s += expf(acc[mt][nt][h*2] - m) + expf(acc[mt][nt][h*2+1] - m);
#pragma unroll
                for (int o = 1; o < 4; o <<= 1) {
                    float m2 = __shfl_xor_sync(0xffffffff, m, o);
                    float s2 = __shfl_xor_sync(0xffffffff, s, o);
                    lse_comb(m, s, m2, s2);
                }
                if ((lane & 3) == 0) {
                    int r = wm * 64 + mt * 16 + h * 8 + gl;
                    red[r * NWN + wn] = make_float2(m, s);
                }
            }
        __syncthreads();
        if (tid < 128) {
            float m = -1e30f, s = 0.f;
#pragma unroll
            for (int w = 0; w < NWN; w++) {
                float2 p = red[tid * NWN + w];
                lse_comb(m, s, p.x, p.y);
            }
            ((float2*)Cf)[(long)(m0 + tid) * NLSP + blockIdx.x] = make_float2(m, s);
        }
        return;
    }

#pragma unroll
    for (int mt = 0; mt < 4; mt++)
#pragma unroll
        for (int nt = 0; nt < 4; nt++)
#pragma unroll
            for (int h = 0; h < 2; h++) {
                const int row = m0 + wm * 64 + mt * 16 + gl + h * 8;
                const int col = n0 + wn * 32 + nt * 8 + c2;
                float v0 = acc[mt][nt][h*2], v1 = acc[mt][nt][h*2+1];
                const long off = (long)row * ldc + col + cOff;
                if (EPI == 0) {
                    *(float2*)(Cf + off) = make_float2(v0, v1);
                } else if (EPI == 1) {
                    *(float2*)(Cf + off) = make_float2(v0 + bias[col], v1 + bias[col+1]);
                } else if (EPI == 2) {
                    pairstore(Ch, Cl, off, fmaxf(v0 + bias[col], 0.f), fmaxf(v1 + bias[col+1], 0.f));
                } else if (EPI == 3) {
                    pairstore(Ch,  Cl,  off, v0 + bias[col],  v1 + bias[col+1]);
                    pairstore(Ch2, Cl2, off, v0 + bias2[col], v1 + bias2[col+1]);
                } else if (EPI == 4) {
                    pairstore(Ch, Cl, off, v0, v1);
                } else if (EPI == 8) {
                    *(__half2*)((__half*)Cf + off) = __floats2half2_rn(v0, v1);
                } else {  // 6: kv split, both halves pair
                    if (n0 < HD) pairstore(Ch, Cl, (long)row * ldc + col, v0, v1);
                    else         pairstore(Ch2, Cl2, (long)row * ldc2 + (col - HD), v0, v1);
                }
            }
}

// ---------------- fused attention ----------------
// grid (QLEN/128, BSZ*NH), 256 thr. Warp = 16 q-rows x full 128-j tile.
// K and V both staged as [row j][64 hi | 64 lo] bf16, pitch 272 B.
// PV B-fragments via ldmatrix.trans of V rows.
#define FA_KPITCH 272
#define FA_TILE  (128*FA_KPITCH)   // 34816
#define FA_STG   (2*FA_TILE)       // 69632 (K + V)
#define FA_SMEM  (2*FA_STG)        // 139264

__global__ void __launch_bounds__(256, 1)
fattn(const bf16* __restrict__ Qh, const bf16* __restrict__ Ql,
      const bf16* __restrict__ Kh, const bf16* __restrict__ Kl,
      const bf16* __restrict__ Vh, const bf16* __restrict__ Vl,
      const __half* __restrict__ bd,
      bf16* __restrict__ Oh, bf16* __restrict__ Ol)
{
    extern __shared__ char smraw[];
    const u32 smS = (u32)__cvta_generic_to_shared(smraw);
    const int tid = threadIdx.x, warp = tid >> 5, lane = tid & 31;
    const int qt = blockIdx.x, bn = blockIdx.y;
    const int b = bn >> 4, n = bn & 15;
    const int i_base = qt * 128;
    const int i0 = i_base + warp * 16;
    const int jmax = (qt + 5 < 8) ? qt + 5 : 8;   // causal tile skip

    // ---- stage Q through stage-0 K region, hoist A-fragments ----
#pragma unroll
    for (int i = 0; i < 8; i++) {
        int idx = tid + i * 256;
        int r = idx >> 4, q = idx & 15;
        const bf16* src = (q < 8)
            ? (Qh + ((long)(i_base + r) * BSZ + b) * DM + n * 64 + q * 8)
            : (Ql + ((long)(i_base + r) * BSZ + b) * DM + n * 64 + (q - 8) * 8);
        cp16s(smS + r * FA_KPITCH + ((q < 8) ? q * 16 : 128 + (q - 8) * 16), src);
    }
    CP_COMMIT();
    CP_WAIT0();
    __syncthreads();
    u32 qfh[4][4], qfl[4][4];
    {
        const u32 aQ = smS + (u32)((warp * 16 + (lane & 15)) * FA_KPITCH + (lane >> 4) * 16);
#pragma unroll
        for (int g = 0; g < 4; g++) {
            LDSM4(qfh[g][0], qfh[g][1], qfh[g][2], qfh[g][3], aQ + g * 32);
            LDSM4(qfl[g][0], qfl[g][1], qfl[g][2], qfl[g][3], aQ + g * 32 + 128);
        }
    }
    __syncthreads();

    auto loadKV = [&](int jt, int st) {
        const int j0 = jt << 7;
        const u32 kb = smS + (u32)st * FA_STG;
        const u32 vb = kb + FA_TILE;
#pragma unroll
        for (int i = 0; i < 8; i++) {
            int idx = tid + i * 256;
            int r = idx >> 4, q = idx & 15;
            const long src = ((long)(j0 + r) * BSZ + b) * HD + n * 64 + ((q < 8) ? q * 8 : (q - 8) * 8);
            const u32 doff = (u32)(r * FA_KPITCH + ((q < 8) ? q * 16 : 128 + (q - 8) * 16));
            cp16s(kb + doff, ((q < 8) ? Kh : Kl) + src);
            cp16s(vb + doff, ((q < 8) ? Vh : Vl) + src);
        }
        CP_COMMIT();
    };

    float acc_o[8][4];
#pragma unroll
    for (int d = 0; d < 8; d++)
#pragma unroll
        for (int e = 0; e < 4; e++) acc_o[d][e] = 0.f;
    float mrow[2] = { -1e30f, -1e30f }, srow[2] = { 0.f, 0.f };

    loadKV(0, 0);
    if (jmax > 1) loadKV(1, 1);

    const int g = lane >> 2, c2 = (lane & 3) * 2;
    const int irow0 = i0 + g, irow1 = i0 + g + 8;

    for (int jt = 0; jt < jmax; jt++) {
        CP_WAIT1();
        __syncthreads();
        const int j0 = jt << 7;
        const u32 kb = smS + (u32)(jt & 1) * FA_STG;
        const u32 vb = kb + FA_TILE;

        // ---- S tile (3-term pair) ----
        float acc_s[16][4];
#pragma unroll
        for (int nt = 0; nt < 16; nt++)
#pragma unroll
            for (int e = 0; e < 4; e++) acc_s[nt][e] = 0.f;

        const u32 bK = kb + (u32)(((lane >> 4) * 8 + (lane & 7)) * FA_KPITCH + ((lane >> 3) & 1) * 16);
#pragma unroll
        for (int ntp = 0; ntp < 8; ntp++) {
#pragma unroll
            for (int gg = 0; gg < 4; gg++) {
                u32 h0, h1, h2, h3, l0, l1, l2, l3;
                const u32 ad = bK + (u32)(ntp * 16 * FA_KPITCH + gg * 32);
                LDSM4(h0, h1, h2, h3, ad);
                LDSM4(l0, l1, l2, l3, ad + 128);
                u32 bhA[2] = { h0, h1 }, bhB[2] = { h2, h3 };
                u32 blA[2] = { l0, l1 }, blB[2] = { l2, l3 };
                mma_bf16(acc_s[2*ntp],   qfh[gg], bhA);
                mma_bf16(acc_s[2*ntp],   qfh[gg], blA);
                mma_bf16(acc_s[2*ntp],   qfl[gg], bhA);
                mma_bf16(acc_s[2*ntp+1], qfh[gg], bhB);
                mma_bf16(acc_s[2*ntp+1], qfh[gg], blB);
                mma_bf16(acc_s[2*ntp+1], qfl[gg], bhB);
            }
        }

        // ---- +BD, mask, scale; online softmax ----
        float scl[2];
#pragma unroll
        for (int h = 0; h < 2; h++) {
            const int i = (h == 0) ? irow0 : irow1;
            const int shift = QLEN - 1 - i;
            const int limit = i + MEMLEN;
            const __half* bdr = bd + ((long)n * ROWS + ((long)i * BSZ + b)) * KLEN + shift;
            float tm = -1e30f;
#pragma unroll
            for (int nt = 0; nt < 16; nt++) {
#pragma unroll
                for (int e = 0; e < 2; e++) {
                    int jg = j0 + nt * 8 + c2 + e;
                    float v = (jg <= limit) ? (acc_s[nt][h*2+e] + __half2float(bdr[jg])) * SCALE : -1e30f;
                    acc_s[nt][h*2+e] = v;
                    tm = fmaxf(tm, v);
                }
            }
            tm = fmaxf(tm, __shfl_xor_sync(0xffffffff, tm, 1));
            tm = fmaxf(tm, __shfl_xor_sync(0xffffffff, tm, 2));
            float mn = fmaxf(mrow[h], tm);
            scl[h] = expf(mrow[h] - mn);
            mrow[h] = mn;
            float ps = 0.f;
#pragma unroll
            for (int nt = 0; nt < 16; nt++) {
#pragma unroll
                for (int e = 0; e < 2; e++) {
                    float p = expf(acc_s[nt][h*2+e] - mn);
                    acc_s[nt][h*2+e] = p;
                    ps += p;
                }
            }
            ps += __shfl_xor_sync(0xffffffff, ps, 1);
            ps += __shfl_xor_sync(0xffffffff, ps, 2);
            srow[h] = srow[h] * scl[h] + ps;
        }
#pragma unroll
        for (int d = 0; d < 8; d++) {
            acc_o[d][0] *= scl[0]; acc_o[d][1] *= scl[0];
            acc_o[d][2] *= scl[1]; acc_o[d][3] *= scl[1];
        }

        // ---- PV: P (register pair) x V rows via ldmatrix.trans ----
        const u32 bV = vb + (u32)((lane & 15) * FA_KPITCH + (lane >> 4) * 16);
#pragma unroll
        for (int kk = 0; kk < 8; kk++) {
            u32 aPh[4], aPl[4];
            aPh[0] = pk2(acc_s[2*kk][0], acc_s[2*kk][1]);
            aPh[1] = pk2(acc_s[2*kk][2], acc_s[2*kk][3]);
            aPh[2] = pk2(acc_s[2*kk+1][0], acc_s[2*kk+1][1]);
            aPh[3] = pk2(acc_s[2*kk+1][2], acc_s[2*kk+1][3]);
            aPl[0] = pk2(bres(acc_s[2*kk][0]), bres(acc_s[2*kk][1]));
            aPl[1] = pk2(bres(acc_s[2*kk][2]), bres(acc_s[2*kk][3]));
            aPl[2] = pk2(bres(acc_s[2*kk+1][0]), bres(acc_s[2*kk+1][1]));
            aPl[3] = pk2(bres(acc_s[2*kk+1][2]), bres(acc_s[2*kk+1][3]));
#pragma unroll
            for (int dp = 0; dp < 4; dp++) {
                u32 h0, h1, h2, h3, l0, l1, l2, l3;
                const u32 ad = bV + (u32)(kk * 16 * FA_KPITCH + dp * 32);
                LDSM4T(h0, h1, h2, h3, ad);
                LDSM4T(l0, l1, l2, l3, ad + 128);
                u32 vhA[2] = { h0, h1 }, vhB[2] = { h2, h3 };
                u32 vlA[2] = { l0, l1 }, vlB[2] = { l2, l3 };
                mma_bf16(acc_o[2*dp],   aPh, vhA);
                mma_bf16(acc_o[2*dp],   aPh, vlA);
                mma_bf16(acc_o[2*dp],   aPl, vhA);
                mma_bf16(acc_o[2*dp+1], aPh, vhB);
                mma_bf16(acc_o[2*dp+1], aPh, vlB);
                mma_bf16(acc_o[2*dp+1], aPl, vhB);
            }
        }
        __syncthreads();
        if (jt + 2 < jmax) loadKV(jt + 2, jt & 1);
    }

    // ---- normalize + pair store ----
    const float inv0 = 1.f / srow[0], inv1 = 1.f / srow[1];
#pragma unroll
    for (int d = 0; d < 8; d++) {
        const int col = n * 64 + d * 8 + c2;
        const long off0 = ((long)irow0 * BSZ + b) * HD + col;
        const long off1 = ((long)irow1 * BSZ + b) * HD + col;
        pairstore(Oh, Ol, off0, acc_o[d][0] * inv0, acc_o[d][1] * inv0);
        pairstore(Oh, Ol, off1, acc_o[d][2] * inv1, acc_o[d][3] * inv1);
    }
}

// ---------------- converters ----------------

// all 6 weight groups in one launch: blockIdx.y = layer, blockIdx.x = flat tile
__global__ void transpose_all(const float* __restrict__ Wkv, const float* __restrict__ Wq,
                              const float* __restrict__ Wr,  const float* __restrict__ Wo,
                              const float* __restrict__ W1,  const float* __restrict__ W2,
                              bf16* hWkv, bf16* lWkv, bf16* hWq, bf16* lWq,
                              bf16* hWr, bf16* lWr, bf16* hWo, bf16* lWo,
                              bf16* hW1, bf16* lW1, bf16* hW2, bf16* lW2)
{
    __shared__ float t[32][33];
    const int l = blockIdx.y;
    int tt = blockIdx.x;
    const float* in; bf16 *oh, *ol; int R, C;
    if (tt < 2048)      { in = Wkv; oh = hWkv; ol = lWkv; R = DM; C = 2*HD; }
    else if (tt < 3072) { in = Wq;  oh = hWq;  ol = lWq;  R = DM; C = HD; tt -= 2048; }
    else if (tt < 4096) { in = Wr;  oh = hWr;  ol = lWr;  R = DM; C = HD; tt -= 3072; }
    else if (tt < 5120) { in = Wo;  oh = hWo;  ol = lWo;  R = HD; C = DM; tt -= 4096; }
    else if (tt < 9216) { in = W1;  oh = hW1;  ol = lW1;  R = DM; C = DI; tt -= 5120; }
    else                { in = W2;  oh = hW2;  ol = lW2;  R = DI; C = DM; tt -= 9216; }
    const long zo = (long)l * R * C;
    in += zo; oh += zo; ol += zo;
    const int ct = C / 32;
    const int c0 = (tt % ct) * 32, r0 = (tt / ct) * 32;
    const int tx = threadIdx.x, ty = threadIdx.y;   // (8, 32)
    {
        float4 v = *(const float4*)(in + (long)(r0 + ty) * C + c0 + tx * 4);
        t[ty][tx*4+0] = v.x; t[ty][tx*4+1] = v.y; t[ty][tx*4+2] = v.z; t[ty][tx*4+3] = v.w;
    }
    __syncthreads();
    {
        float a = t[tx*4+0][ty], b = t[tx*4+1][ty], c = t[tx*4+2][ty], d = t[tx*4+3][ty];
        long o = (long)(c0 + ty) * R + r0 + tx * 4;
        pairstore4(oh, ol, o, a, b, c, d);
    }
}

__global__ void convert_pair(const float* __restrict__ in, bf16* __restrict__ oh,
                             bf16* __restrict__ ol, long n4)
{
    long i = (long)blockIdx.x * 256 + threadIdx.x;
    if (i >= n4) return;
    float4 v = *(const float4*)(in + i * 4);
    pairstore4(oh, ol, i * 4, v.x, v.y, v.z, v.w);
}

// ---------------- elementwise / reductions ----------------

__global__ void embed_kernel(const int* __restrict__ data, const float* __restrict__ embW,
                             float* __restrict__ core, bf16* __restrict__ ch,
                             bf16* __restrict__ cl, float* __restrict__ outm)
{
    long i = (long)blockIdx.x * 256 + threadIdx.x;
    if (i >= (long)ROWS * DM / 4) return;
    int r = (int)(i >> 8);
    float4 v = *(const float4*)(embW + (long)data[r] * DM + (i & 255) * 4);
    *(float4*)(core + i * 4) = v;
    *(float4*)(outm + i * 4) = v;
    pairstore4(ch, cl, i * 4, v.x, v.y, v.z, v.w);
}

__global__ void pos_kernel(bf16* __restrict__ ph, bf16* __restrict__ pl)
{
    long idx = (long)blockIdx.x * 256 + threadIdx.x;
    if (idx >= (long)KLEN * DM) return;
    int j = (int)(idx >> 10), d = (int)(idx & 1023);
    float p = (float)(KLEN - 1 - j);
    int t = (d < 512) ? d : d - 512;
    float invf = expf(-((2.0f * (float)t) / (float)DM) * logf(10000.0f));
    float a = p * invf;
    float x = (d < 512) ? sinf(a) : cosf(a);
    ph[idx] = __float2bfloat16(x);
    pl[idx] = __float2bfloat16(bres(x));
}

__global__ void ln_kernel(const float* __restrict__ x, const float* __restrict__ y,
                          const float* __restrict__ g, const float* __restrict__ b,
                          float* __restrict__ outf, bf16* __restrict__ oh,
                          bf16* __restrict__ ol, float* __restrict__ memsf)
{
    const int r = blockIdx.x, t = threadIdx.x;
    __shared__ float red[256];
    const long base = (long)r * DM + t * 4;
    float4 xv = *(const float4*)(x + base);
    float4 yv = *(const float4*)(y + base);
    float loc[4] = { xv.x + yv.x, xv.y + yv.y, xv.z + yv.z, xv.w + yv.w };
    float s = loc[0] + loc[1] + loc[2] + loc[3];
    red[t] = s; __syncthreads();
    for (int o = 128; o > 0; o >>= 1) { if (t < o) red[t] += red[t + o]; __syncthreads(); }
    const float mu = red[0] * (1.0f / DM);
    __syncthreads();
    float s2 = 0.f;
#pragma unroll
    for (int k = 0; k < 4; k++) { float d = loc[k] - mu; s2 += d * d; }
    red[t] = s2; __syncthreads();
    for (int o = 128; o > 0; o >>= 1) { if (t < o) red[t] += red[t + o]; __syncthreads(); }
    const float rstd = rsqrtf(red[0] * (1.0f / DM) + 1e-5f);
    float4 gv = *(const float4*)(g + t * 4);
    float4 bv = *(const float4*)(b + t * 4);
    float4 o4;
    o4.x = (loc[0] - mu) * rstd * gv.x + bv.x;
    o4.y = (loc[1] - mu) * rstd * gv.y + bv.y;
    o4.z = (loc[2] - mu) * rstd * gv.z + bv.z;
    o4.w = (loc[3] - mu) * rstd * gv.w + bv.w;
    *(float4*)(outf + base) = o4;
    if (memsf) *(float4*)(memsf + base) = o4;
    pairstore4(oh, ol, base, o4.x, o4.y, o4.z, o4.w);
}

__global__ void loss_final_kernel(const float2* __restrict__ lsp,
                                  const float* __restrict__ core,
                                  const float* __restrict__ embW,
                                  const int* __restrict__ target,
                                  float* __restrict__ out)
{
    const int r = blockIdx.x, t = threadIdx.x;
    __shared__ float rm[128], rs[128], rd[128];
    float m = -1e30f, s = 0.f;
    for (int j = t; j < NTOK / 128; j += 128) {
        float2 p = lsp[(long)r * NLSP + j];
        lse_comb(m, s, p.x, p.y);
    }
    const float* cr = core + (long)r * DM;
    const float* er = embW + (long)target[r] * DM;
    float d = 0.f;
    for (int j = t; j < DM / 4; j += 128) {
        float4 a = *(const float4*)(cr + j * 4);
        float4 b = *(const float4*)(er + j * 4);
        d += a.x * b.x + a.y * b.y + a.z * b.z + a.w * b.w;
    }
    rm[t] = m; rs[t] = s; rd[t] = d; __syncthreads();
    for (int o = 64; o > 0; o >>= 1) {
        if (t < o) {
            lse_comb(rm[t], rs[t], rm[t + o], rs[t + o]);
            rd[t] += rd[t + o];
        }
        __syncthreads();
    }
    if (t == 0) out[r] = (logf(rs[0]) + rm[0]) - rd[0];
}

// ---------------- host ----------------

#define S128 73728
#define GSA(p, s) cudaGetSymbolAddress((void**)&p, s)

static inline dim3 gt(int N, int M, int bz, int ntile) { return dim3(N / ntile, M / 128, bz); }

extern "C" void kernel_launch(void* const* d_in, const int* in_sizes, int n_in,
                              void* d_out, int out_size)
{
    const int*   data   = (const int*)  d_in[0];
    const int*   target = (const int*)  d_in[1];
    const float* memory = (const float*)d_in[2];
    const float* embW   = (const float*)d_in[3];
    const float* rwb    = (const float*)d_in[4];
    const float* rrb    = (const float*)d_in[5];
    const float* Wq     = (const float*)d_in[6];
    const float* Wkv    = (const float*)d_in[7];
    const float* Wr     = (const float*)d_in[8];
    const float* Wo     = (const float*)d_in[9];
    const float* W1     = (const float*)d_in[10];
    const float* b1     = (const float*)d_in[11];
    const float* W2     = (const float*)d_in[12];
    const float* b2     = (const float*)d_in[13];
    const float* ln1g   = (const float*)d_in[14];
    const float* ln1b   = (const float*)d_in[15];
    const float* ln2g   = (const float*)d_in[16];
    const float* ln2b   = (const float*)d_in[17];

    float* out      = (float*)d_out;
    float* out_loss = out;
    float* out_mems = out + ROWS;

    float *core, *tmp;
    __half* bd;
    float2* lsp;
    GSA(core, g_core); GSA(tmp, g_tmp); GSA(bd, g_bd); GSA(lsp, g_lsp);

    bf16 *hcore,*lcore,*hmem,*lmem,*hqrw,*lqrw,*hqrr,*lqrr,*hk,*lk,*hv,*lv,*hrk,*lrk,
         *hvec,*lvec,*hffh,*lffh,*hpos,*lpos,*hemb,*lemb,
         *hWkvT,*lWkvT,*hWqT,*lWqT,*hWrT,*lWrT,*hWoT,*lWoT,*hW1T,*lW1T,*hW2T,*lW2T;
    GSA(hcore,h_core); GSA(lcore,l_core); GSA(hmem,h_mem); GSA(lmem,l_mem);
    GSA(hqrw,h_qrw); GSA(lqrw,l_qrw); GSA(hqrr,h_qrr); GSA(lqrr,l_qrr);
    GSA(hk,h_kk); GSA(lk,l_kk); GSA(hv,h_vv); GSA(lv,l_vv);
    GSA(hrk,h_rk); GSA(lrk,l_rk);
    GSA(hvec,h_vec); GSA(lvec,l_vec); GSA(hffh,h_ffh); GSA(lffh,l_ffh);
    GSA(hpos,h_pos); GSA(lpos,l_pos); GSA(hemb,h_emb); GSA(lemb,l_emb);
    GSA(hWkvT,h_WkvT); GSA(lWkvT,l_WkvT); GSA(hWqT,h_WqT); GSA(lWqT,l_WqT);
    GSA(hWrT,h_WrT); GSA(lWrT,l_WrT); GSA(hWoT,h_WoT); GSA(lWoT,l_WoT);
    GSA(hW1T,h_W1T); GSA(lW1T,l_W1T); GSA(hW2T,h_W2T); GSA(lW2T,l_W2T);

    // smem opt-in for EVERY launched instantiation
    cudaFuncSetAttribute(pgemm<128,0>, cudaFuncAttributeMaxDynamicSharedMemorySize, S128);
    cudaFuncSetAttribute(pgemm<128,1>, cudaFuncAttributeMaxDynamicSharedMemorySize, S128);
    cudaFuncSetAttribute(pgemm<128,2>, cudaFuncAttributeMaxDynamicSharedMemorySize, S128);
    cudaFuncSetAttribute(pgemm<128,3>, cudaFuncAttributeMaxDynamicSharedMemorySize, S128);
    cudaFuncSetAttribute(pgemm<128,4>, cudaFuncAttributeMaxDynamicSharedMemorySize, S128);
    cudaFuncSetAttribute(pgemm<128,6>, cudaFuncAttributeMaxDynamicSharedMemorySize, S128);
    cudaFuncSetAttribute(pgemm<128,7>, cudaFuncAttributeMaxDynamicSharedMemorySize, S128);
    cudaFuncSetAttribute(pgemm<128,8>, cudaFuncAttributeMaxDynamicSharedMemorySize, S128);
    cudaFuncSetAttribute(fattn, cudaFuncAttributeMaxDynamicSharedMemorySize, FA_SMEM);

    const dim3 tb(8, 32);
    // exactly 5 launches before the first pgemm (ncu -s 5 lands on kv pgemm)
    {
        long n1 = (long)NL*ROWS*DM/4;
        convert_pair<<<(int)((n1 + 255)/256), 256>>>(memory, hmem, lmem, n1);
        long n2 = (long)NTOK*DM/4;
        convert_pair<<<(int)((n2 + 255)/256), 256>>>(embW, hemb, lemb, n2);
    }
    embed_kernel<<<(ROWS*DM/4 + 255)/256, 256>>>(data, embW, core, hcore, lcore, out_mems);
    pos_kernel<<<(KLEN*DM + 255)/256, 256>>>(hpos, lpos);
    transpose_all<<<dim3(13312, NL), tb>>>(Wkv, Wq, Wr, Wo, W1, W2,
        hWkvT, lWkvT, hWqT, lWqT, hWrT, lWrT, hWoT, lWoT, hW1T, lW1T, hW2T, lW2T);

    for (int l = 0; l < NL; l++) {
        const bf16* hWkvl = hWkvT + (size_t)l*2*HD*DM;
        const bf16* lWkvl = lWkvT + (size_t)l*2*HD*DM;

        // kv halves: k pair + v pair (row layout [j*BSZ+b][d])
        pgemm<128,6><<<gt(2*HD, ROWS, 1, 128), 256, S128>>>(
            hmem + (size_t)l*ROWS*DM, lmem + (size_t)l*ROWS*DM, hWkvl, lWkvl,
            DM, DM, DM, 0,0,0,0, 1, HD, 0,0,
            nullptr, hk, lk, hv, lv, nullptr, nullptr, nullptr, HD);
        pgemm<128,6><<<gt(2*HD, ROWS, 1, 128), 256, S128>>>(
            hcore, lcore, hWkvl, lWkvl,
            DM, DM, DM, 0,0,0,0, 1, HD, 0,0,
            nullptr, hk + (size_t)ROWS*HD, lk + (size_t)ROWS*HD,
            hv + (size_t)ROWS*HD, lv + (size_t)ROWS*HD, nullptr, nullptr, nullptr, HD);

        pgemm<128,3><<<gt(HD, ROWS, 1, 128), 256, S128>>>(
            hcore, lcore, hWqT + (size_t)l*HD*DM, lWqT + (size_t)l*HD*DM,
            DM, DM, DM, 0,0,0,0, 1, DM, 0,0,
            nullptr, hqrw, lqrw, hqrr, lqrr, rwb, rrb, nullptr, 0);

        pgemm<128,4><<<gt(HD, KLEN, 1, 128), 256, S128>>>(
            hpos, lpos, hWrT + (size_t)l*HD*DM, lWrT + (size_t)l*HD*DM,
            DM, DM, DM, 0,0,0,0, 1, HD, 0,0,
            nullptr, hrk, lrk, nullptr, nullptr, nullptr, nullptr, nullptr, 0);

        // BD raw -> fp16 (batched over heads)
        pgemm<128,8><<<gt(KLEN, ROWS, NH, 128), 256, S128>>>(
            hqrr, lqrr, hrk, lrk,
            DH, DM, HD,
            0, (long)DH, 0, (long)DH, NH,
            KLEN, 0, (long)ROWS*KLEN,
            (float*)bd, nullptr, nullptr, nullptr, nullptr, nullptr, nullptr, nullptr, 0);

        // fused attention
        fattn<<<dim3(QLEN/128, BSZ*NH), 256, FA_SMEM>>>(
            hqrw, lqrw, hk, lk, hv, lv, bd, hvec, lvec);

        pgemm<128,0><<<gt(DM, ROWS, 1, 128), 256, S128>>>(
            hvec, lvec, hWoT + (size_t)l*DM*HD, lWoT + (size_t)l*DM*HD,
            HD, HD, HD, 0,0,0,0, 1, DM, 0,0,
            tmp, nullptr, nullptr, nullptr, nullptr, nullptr, nullptr, nullptr, 0);

        ln_kernel<<<ROWS, 256>>>(core, tmp, ln1g + (size_t)l*DM, ln1b + (size_t)l*DM,
                                 core, hcore, lcore, nullptr);

        pgemm<128,2><<<gt(DI, ROWS, 1, 128), 256, S128>>>(
            hcore, lcore, hW1T + (size_t)l*DI*DM, lW1T + (size_t)l*DI*DM,
            DM, DM, DM, 0,0,0,0, 1, DI, 0,0,
            nullptr, hffh, lffh, nullptr, nullptr, b1 + (size_t)l*DI, nullptr, nullptr, 0);

        pgemm<128,1><<<gt(DM, ROWS, 1, 128), 256, S128>>>(
            hffh, lffh, hW2T + (size_t)l*DM*DI, lW2T + (size_t)l*DM*DI,
            DI, DI, DI, 0,0,0,0, 1, DM, 0,0,
            tmp, nullptr, nullptr, nullptr, nullptr, b2 + (size_t)l*DM, nullptr, nullptr, 0);

        ln_kernel<<<ROWS, 256>>>(core, tmp, ln2g + (size_t)l*DM, ln2b + (size_t)l*DM,
                                 core, hcore, lcore,
                                 (l < NL - 1) ? (out_mems + (size_t)(l + 1)*ROWS*DM) : nullptr);
    }

    pgemm<128,7><<<gt(NTOK, ROWS, 1, 128), 256, S128>>>(
        hcore, lcore, hemb, lemb,
        DM, DM, DM, 0,0,0,0, 1, 0, 0,0,
        (float*)lsp, nullptr, nullptr, nullptr, nullptr, nullptr, nullptr, nullptr, 0);
    loss_final_kernel<<<ROWS, 128>>>(lsp, core, embW, target, out_loss);

    (void)in_sizes; (void)n_in; (void)out_size;
}

// round 16
// speedup vs baseline: 3.9189x; 1.1563x over previous
#include <cuda_runtime.h>
#include <cuda_bf16.h>
#include <cuda_fp16.h>
#include <math.h>
#include <stdint.h>

typedef __nv_bfloat16 bf16;
typedef __nv_bfloat162 bf162;
typedef uint32_t u32;

#define QLEN 512
#define MEMLEN 512
#define KLEN 1024
#define BSZ 8
#define NH 16
#define DH 64
#define DM 1024
#define DI 4096
#define NL 6
#define NTOK 32000
#define HD 1024
#define ROWS (QLEN*BSZ)
#define KROWS (KLEN*BSZ)
#define SCALE 0.125f
#define NLSP 256

// ---------------- fp32 scratch ----------------
__device__ float g_core [ROWS*DM];
__device__ float g_tmp  [ROWS*DM];
__device__ __half g_bd  [(size_t)NH*ROWS*KLEN];
__device__ float2 g_lsp [(size_t)ROWS*NLSP];

// ---------------- bf16 hi/lo pair scratch ----------------
#define PAIR(name, n) __device__ bf16 h_##name[n]; __device__ bf16 l_##name[n];
PAIR(core, ROWS*DM)
PAIR(mem,  (size_t)NL*ROWS*DM)
PAIR(qrw,  ROWS*DM)
PAIR(qrr,  ROWS*DM)
PAIR(kk,   KROWS*HD)
PAIR(vv,   KROWS*HD)
PAIR(rk,   KLEN*HD)
PAIR(vec,  ROWS*HD)
PAIR(ffh,  (size_t)ROWS*DI)
PAIR(pos,  KLEN*DM)
PAIR(emb,  (size_t)NTOK*DM)
PAIR(WkvT, (size_t)NL*2*HD*DM)
PAIR(WqT,  (size_t)NL*HD*DM)
PAIR(WrT,  (size_t)NL*HD*DM)
PAIR(WoT,  (size_t)NL*DM*HD)
PAIR(W1T,  (size_t)NL*DI*DM)
PAIR(W2T,  (size_t)NL*DM*DI)

// ---------------- helpers ----------------
__device__ __forceinline__ void mma_bf16(float* d, const u32* a, const u32* b) {
    asm volatile(
        "mma.sync.aligned.m16n8k16.row.col.f32.bf16.bf16.f32 "
        "{%0,%1,%2,%3}, {%4,%5,%6,%7}, {%8,%9}, {%0,%1,%2,%3};\n"
        : "+f"(d[0]), "+f"(d[1]), "+f"(d[2]), "+f"(d[3])
        : "r"(a[0]), "r"(a[1]), "r"(a[2]), "r"(a[3]), "r"(b[0]), "r"(b[1]));
}
#define LDSM4(r0,r1,r2,r3,addr) \
    asm volatile("ldmatrix.sync.aligned.m8n8.x4.shared.b16 {%0,%1,%2,%3}, [%4];" \
        : "=r"(r0), "=r"(r1), "=r"(r2), "=r"(r3) : "r"(addr))
#define LDSM4T(r0,r1,r2,r3,addr) \
    asm volatile("ldmatrix.sync.aligned.m8n8.x4.trans.shared.b16 {%0,%1,%2,%3}, [%4];" \
        : "=r"(r0), "=r"(r1), "=r"(r2), "=r"(r3) : "r"(addr))
__device__ __forceinline__ void cp16s(u32 sdst, const void* g) {
    asm volatile("cp.async.cg.shared.global [%0], [%1], 16;\n" :: "r"(sdst), "l"(g));
}
#define CP_COMMIT() asm volatile("cp.async.commit_group;\n")
#define CP_WAIT1()  asm volatile("cp.async.wait_group 1;\n")
#define CP_WAIT0()  asm volatile("cp.async.wait_group 0;\n")

__device__ __forceinline__ u32 pk2(float a, float b) {
    bf162 t = __floats2bfloat162_rn(a, b);
    return *(u32*)&t;
}
__device__ __forceinline__ float bres(float x) {
    return x - __bfloat162float(__float2bfloat16(x));
}
__device__ __forceinline__ void pairstore(bf16* H, bf16* L, long off, float v0, float v1) {
    *(u32*)(H + off) = pk2(v0, v1);
    *(u32*)(L + off) = pk2(bres(v0), bres(v1));
}
__device__ __forceinline__ void pairstore4(bf16* H, bf16* L, long off,
                                           float a, float b, float c, float d) {
    uint2 hh = { pk2(a, b), pk2(c, d) };
    uint2 ll = { pk2(bres(a), bres(b)), pk2(bres(c), bres(d)) };
    *(uint2*)(H + off) = hh;
    *(uint2*)(L + off) = ll;
}
__device__ __forceinline__ void lse_comb(float& m, float& s, float m2, float s2) {
    float M = fmaxf(m, m2);
    s = s * expf(m - M) + s2 * expf(m2 - M);
    m = M;
}

// ---------------- pair-bf16 NT GEMM (mma.sync) ----------------
// TERMS=3: hi/lo pair arithmetic (ah*bh + ah*bl + al*bh), K-step 32.
// TERMS=1: single bf16 (hi only), K-step 64, 1/3 the MMAs (lse path only).
// EPI: 0 fp32  1 fp32+bias  2 pair relu(+bias)  3 dual pair  4 pair
//      6 kv-split  7 logsumexp partials  8 fp16 store
template <int NTILE, int EPI, int TERMS>
__global__ void __launch_bounds__(NTILE == 128 ? 256 : 128, 2)
pgemm(const bf16* __restrict__ Ah, const bf16* __restrict__ Al,
      const bf16* __restrict__ Bh, const bf16* __restrict__ Bl,
      int K, int lda, int ldb,
      long sA1, long sA2, long sB1, long sB2, int batch2,
      int ldc, long sC1, long sC2,
      float* __restrict__ Cf,
      bf16* __restrict__ Ch, bf16* __restrict__ Cl,
      bf16* __restrict__ Ch2, bf16* __restrict__ Cl2,
      const float* __restrict__ bias, const float* __restrict__ bias2,
      float* __restrict__ Cf2, int ldc2)
{
    constexpr int T    = (NTILE == 128) ? 256 : 128;
    constexpr int ASTB = 128 * 144;
    constexpr int BSTB = NTILE * 144;
    constexpr int KST  = (TERMS == 1) ? 64 : 32;
    constexpr int NG   = (TERMS == 1) ? 4 : 2;
    extern __shared__ char smraw[];
    const u32 smS = (u32)__cvta_generic_to_shared(smraw);

    const int bz = blockIdx.z;
    const int b1 = bz / batch2, b2 = bz % batch2;
    Ah += b1 * sA1 + b2 * sA2;  Al += b1 * sA1 + b2 * sA2;
    Bh += b1 * sB1 + b2 * sB2;  Bl += b1 * sB1 + b2 * sB2;
    const long cOff = b1 * sC1 + b2 * sC2;

    const int m0 = blockIdx.y * 128, n0 = blockIdx.x * NTILE;
    const int tid = threadIdx.x, warp = tid >> 5, lane = tid & 31;
    constexpr int NWN = NTILE / 32;
    const int wm = warp / NWN, wn = warp % NWN;

    float acc[4][4][4];
#pragma unroll
    for (int mt = 0; mt < 4; mt++)
#pragma unroll
        for (int nt = 0; nt < 4; nt++)
#pragma unroll
            for (int e = 0; e < 4; e++) acc[mt][nt][e] = 0.f;

    const int KT = K / KST;

    auto issue = [&](int kt, int st) {
        const int k0 = kt * KST;
        const u32 aB = smS + st * ASTB;
        const u32 bB = smS + 2 * ASTB + st * BSTB;
#pragma unroll
        for (int i = 0; i < 1024 / T; i++) {
            int idx = tid + i * T, r = idx >> 3, q = idx & 7;
            const bf16* src = (TERMS == 1)
                ? (Ah + (long)(m0 + r) * lda + k0 + q * 8)
                : ((q < 4) ? (Ah + (long)(m0 + r) * lda + k0 + q * 8)
                           : (Al + (long)(m0 + r) * lda + k0 + (q - 4) * 8));
            cp16s(aB + r * 144 + q * 16, src);
        }
#pragma unroll
        for (int i = 0; i < NTILE * 8 / T; i++) {
            int idx = tid + i * T, r = idx >> 3, q = idx & 7;
            const bf16* src = (TERMS == 1)
                ? (Bh + (long)(n0 + r) * ldb + k0 + q * 8)
                : ((q < 4) ? (Bh + (long)(n0 + r) * ldb + k0 + q * 8)
                           : (Bl + (long)(n0 + r) * ldb + k0 + (q - 4) * 8));
            cp16s(bB + r * 144 + q * 16, src);
        }
    };

    const u32 aLane = (u32)((lane & 15) * 144 + (lane >> 4) * 16);
    const u32 bLane = (u32)(((lane >> 4) * 8 + (lane & 7)) * 144 + ((lane >> 3) & 1) * 16);

    issue(0, 0); CP_COMMIT();
    if (KT > 1) issue(1, 1);
    CP_COMMIT();

    for (int kt = 0; kt < KT; kt++) {
        CP_WAIT1();
        __syncthreads();
        const u32 As = smS + (kt & 1) * ASTB + wm * 64 * 144 + aLane;
        const u32 Bs = smS + 2 * ASTB + (kt & 1) * BSTB + wn * 32 * 144 + bLane;

#pragma unroll
        for (int g = 0; g < NG; g++) {
            if (TERMS == 1) {
                u32 ah[4][4], bh[4][2];
#pragma unroll
                for (int mt = 0; mt < 4; mt++) {
                    const u32 ad = As + mt * 2304 + g * 32;
                    LDSM4(ah[mt][0], ah[mt][1], ah[mt][2], ah[mt][3], ad);
                }
#pragma unroll
                for (int p = 0; p < 2; p++) {
                    const u32 bd_ = Bs + p * 2304 + g * 32;
                    LDSM4(bh[2*p][0], bh[2*p][1], bh[2*p+1][0], bh[2*p+1][1], bd_);
                }
#pragma unroll
                for (int mt = 0; mt < 4; mt++)
#pragma unroll
                    for (int nt = 0; nt < 4; nt++)
                        mma_bf16(acc[mt][nt], ah[mt], bh[nt]);
            } else {
                u32 ah[4][4], alr[4][4], bh[4][2], blr[4][2];
#pragma unroll
                for (int mt = 0; mt < 4; mt++) {
                    const u32 ad = As + mt * 2304 + g * 32;
                    LDSM4(ah[mt][0], ah[mt][1], ah[mt][2], ah[mt][3], ad);
                    LDSM4(alr[mt][0], alr[mt][1], alr[mt][2], alr[mt][3], ad + 64);
                }
#pragma unroll
                for (int p = 0; p < 2; p++) {
                    const u32 bd_ = Bs + p * 2304 + g * 32;
                    LDSM4(bh[2*p][0], bh[2*p][1], bh[2*p+1][0], bh[2*p+1][1], bd_);
                    LDSM4(blr[2*p][0], blr[2*p][1], blr[2*p+1][0], blr[2*p+1][1], bd_ + 64);
                }
#pragma unroll
                for (int mt = 0; mt < 4; mt++)
#pragma unroll
                    for (int nt = 0; nt < 4; nt++) {
                        mma_bf16(acc[mt][nt], ah[mt], bh[nt]);
                        mma_bf16(acc[mt][nt], ah[mt], blr[nt]);
                        mma_bf16(acc[mt][nt], alr[mt], bh[nt]);
                    }
            }
        }
        __syncthreads();
        if (kt + 2 < KT) issue(kt + 2, kt & 1);
        CP_COMMIT();
    }

    const int gl = lane >> 2, c2 = (lane & 3) * 2;

    if (EPI == 7) {
        float2* red = (float2*)smraw;
        __syncthreads();
#pragma unroll
        for (int mt = 0; mt < 4; mt++)
#pragma unroll
            for (int h = 0; h < 2; h++) {
                float m = -1e30f, s = 0.f;
#pragma unroll
                for (int nt = 0; nt < 4; nt++)
                    m = fmaxf(m, fmaxf(acc[mt][nt][h*2], acc[mt][nt][h*2+1]));
#pragma unroll
                for (int nt = 0; nt < 4; nt++)
                    s += expf(acc[mt][nt][h*2] - m) + expf(acc[mt][nt][h*2+1] - m);
#pragma unroll
                for (int o = 1; o < 4; o <<= 1) {
                    float m2 = __shfl_xor_sync(0xffffffff, m, o);
                    float s2 = __shfl_xor_sync(0xffffffff, s, o);
                    lse_comb(m, s, m2, s2);
                }
                if ((lane & 3) == 0) {
                    int r = wm * 64 + mt * 16 + h * 8 + gl;
                    red[r * NWN + wn] = make_float2(m, s);
                }
            }
        __syncthreads();
        if (tid < 128) {
            float m = -1e30f, s = 0.f;
#pragma unroll
            for (int w = 0; w < NWN; w++) {
                float2 p = red[tid * NWN + w];
                lse_comb(m, s, p.x, p.y);
            }
            ((float2*)Cf)[(long)(m0 + tid) * NLSP + blockIdx.x] = make_float2(m, s);
        }
        return;
    }

#pragma unroll
    for (int mt = 0; mt < 4; mt++)
#pragma unroll
        for (int nt = 0; nt < 4; nt++)
#pragma unroll
            for (int h = 0; h < 2; h++) {
                const int row = m0 + wm * 64 + mt * 16 + gl + h * 8;
                const int col = n0 + wn * 32 + nt * 8 + c2;
                float v0 = acc[mt][nt][h*2], v1 = acc[mt][nt][h*2+1];
                const long off = (long)row * ldc + col + cOff;
                if (EPI == 0) {
                    *(float2*)(Cf + off) = make_float2(v0, v1);
                } else if (EPI == 1) {
                    *(float2*)(Cf + off) = make_float2(v0 + bias[col], v1 + bias[col+1]);
                } else if (EPI == 2) {
                    pairstore(Ch, Cl, off, fmaxf(v0 + bias[col], 0.f), fmaxf(v1 + bias[col+1], 0.f));
                } else if (EPI == 3) {
                    pairstore(Ch,  Cl,  off, v0 + bias[col],  v1 + bias[col+1]);
                    pairstore(Ch2, Cl2, off, v0 + bias2[col], v1 + bias2[col+1]);
                } else if (EPI == 4) {
                    pairstore(Ch, Cl, off, v0, v1);
                } else if (EPI == 8) {
                    *(__half2*)((__half*)Cf + off) = __floats2half2_rn(v0, v1);
                } else {  // 6: kv split, both halves pair
                    if (n0 < HD) pairstore(Ch, Cl, (long)row * ldc + col, v0, v1);
                    else         pairstore(Ch2, Cl2, (long)row * ldc2 + (col - HD), v0, v1);
                }
            }
}

// ---------------- fused attention ----------------
#define FA_KPITCH 272
#define FA_TILE  (128*FA_KPITCH)
#define FA_STG   (2*FA_TILE)
#define FA_SMEM  (2*FA_STG)

__global__ void __launch_bounds__(256, 1)
fattn(const bf16* __restrict__ Qh, const bf16* __restrict__ Ql,
      const bf16* __restrict__ Kh, const bf16* __restrict__ Kl,
      const bf16* __restrict__ Vh, const bf16* __restrict__ Vl,
      const __half* __restrict__ bd,
      bf16* __restrict__ Oh, bf16* __restrict__ Ol)
{
    extern __shared__ char smraw[];
    const u32 smS = (u32)__cvta_generic_to_shared(smraw);
    const int tid = threadIdx.x, warp = tid >> 5, lane = tid & 31;
    const int qt = blockIdx.x, bn = blockIdx.y;
    const int b = bn >> 4, n = bn & 15;
    const int i_base = qt * 128;
    const int i0 = i_base + warp * 16;
    const int jmax = (qt + 5 < 8) ? qt + 5 : 8;

#pragma unroll
    for (int i = 0; i < 8; i++) {
        int idx = tid + i * 256;
        int r = idx >> 4, q = idx & 15;
        const bf16* src = (q < 8)
            ? (Qh + ((long)(i_base + r) * BSZ + b) * DM + n * 64 + q * 8)
            : (Ql + ((long)(i_base + r) * BSZ + b) * DM + n * 64 + (q - 8) * 8);
        cp16s(smS + r * FA_KPITCH + ((q < 8) ? q * 16 : 128 + (q - 8) * 16), src);
    }
    CP_COMMIT();
    CP_WAIT0();
    __syncthreads();
    u32 qfh[4][4], qfl[4][4];
    {
        const u32 aQ = smS + (u32)((warp * 16 + (lane & 15)) * FA_KPITCH + (lane >> 4) * 16);
#pragma unroll
        for (int g = 0; g < 4; g++) {
            LDSM4(qfh[g][0], qfh[g][1], qfh[g][2], qfh[g][3], aQ + g * 32);
            LDSM4(qfl[g][0], qfl[g][1], qfl[g][2], qfl[g][3], aQ + g * 32 + 128);
        }
    }
    __syncthreads();

    auto loadKV = [&](int jt, int st) {
        const int j0 = jt << 7;
        const u32 kb = smS + (u32)st * FA_STG;
        const u32 vb = kb + FA_TILE;
#pragma unroll
        for (int i = 0; i < 8; i++) {
            int idx = tid + i * 256;
            int r = idx >> 4, q = idx & 15;
            const long src = ((long)(j0 + r) * BSZ + b) * HD + n * 64 + ((q < 8) ? q * 8 : (q - 8) * 8);
            const u32 doff = (u32)(r * FA_KPITCH + ((q < 8) ? q * 16 : 128 + (q - 8) * 16));
            cp16s(kb + doff, ((q < 8) ? Kh : Kl) + src);
            cp16s(vb + doff, ((q < 8) ? Vh : Vl) + src);
        }
        CP_COMMIT();
    };

    float acc_o[8][4];
#pragma unroll
    for (int d = 0; d < 8; d++)
#pragma unroll
        for (int e = 0; e < 4; e++) acc_o[d][e] = 0.f;
    float mrow[2] = { -1e30f, -1e30f }, srow[2] = { 0.f, 0.f };

    loadKV(0, 0);
    if (jmax > 1) loadKV(1, 1);

    const int g = lane >> 2, c2 = (lane & 3) * 2;
    const int irow0 = i0 + g, irow1 = i0 + g + 8;

    for (int jt = 0; jt < jmax; jt++) {
        CP_WAIT1();
        __syncthreads();
        const int j0 = jt << 7;
        const u32 kb = smS + (u32)(jt & 1) * FA_STG;
        const u32 vb = kb + FA_TILE;

        float acc_s[16][4];
#pragma unroll
        for (int nt = 0; nt < 16; nt++)
#pragma unroll
            for (int e = 0; e < 4; e++) acc_s[nt][e] = 0.f;

        const u32 bK = kb + (u32)(((lane >> 4) * 8 + (lane & 7)) * FA_KPITCH + ((lane >> 3) & 1) * 16);
#pragma unroll
        for (int ntp = 0; ntp < 8; ntp++) {
#pragma unroll
            for (int gg = 0; gg < 4; gg++) {
                u32 h0, h1, h2, h3, l0, l1, l2, l3;
                const u32 ad = bK + (u32)(ntp * 16 * FA_KPITCH + gg * 32);
                LDSM4(h0, h1, h2, h3, ad);
                LDSM4(l0, l1, l2, l3, ad + 128);
                u32 bhA[2] = { h0, h1 }, bhB[2] = { h2, h3 };
                u32 blA[2] = { l0, l1 }, blB[2] = { l2, l3 };
                mma_bf16(acc_s[2*ntp],   qfh[gg], bhA);
                mma_bf16(acc_s[2*ntp],   qfh[gg], blA);
                mma_bf16(acc_s[2*ntp],   qfl[gg], bhA);
                mma_bf16(acc_s[2*ntp+1], qfh[gg], bhB);
                mma_bf16(acc_s[2*ntp+1], qfh[gg], blB);
                mma_bf16(acc_s[2*ntp+1], qfl[gg], bhB);
            }
        }

        float scl[2];
#pragma unroll
        for (int h = 0; h < 2; h++) {
            const int i = (h == 0) ? irow0 : irow1;
            const int shift = QLEN - 1 - i;
            const int limit = i + MEMLEN;
            const __half* bdr = bd + ((long)n * ROWS + ((long)i * BSZ + b)) * KLEN + shift;
            float tm = -1e30f;
#pragma unroll
            for (int nt = 0; nt < 16; nt++) {
#pragma unroll
                for (int e = 0; e < 2; e++) {
                    int jg = j0 + nt * 8 + c2 + e;
                    float v = (jg <= limit) ? (acc_s[nt][h*2+e] + __half2float(bdr[jg])) * SCALE : -1e30f;
                    acc_s[nt][h*2+e] = v;
                    tm = fmaxf(tm, v);
                }
            }
            tm = fmaxf(tm, __shfl_xor_sync(0xffffffff, tm, 1));
            tm = fmaxf(tm, __shfl_xor_sync(0xffffffff, tm, 2));
            float mn = fmaxf(mrow[h], tm);
            scl[h] = expf(mrow[h] - mn);
            mrow[h] = mn;
            float ps = 0.f;
#pragma unroll
            for (int nt = 0; nt < 16; nt++) {
#pragma unroll
                for (int e = 0; e < 2; e++) {
                    float p = expf(acc_s[nt][h*2+e] - mn);
                    acc_s[nt][h*2+e] = p;
                    ps += p;
                }
            }
            ps += __shfl_xor_sync(0xffffffff, ps, 1);
            ps += __shfl_xor_sync(0xffffffff, ps, 2);
            srow[h] = srow[h] * scl[h] + ps;
        }
#pragma unroll
        for (int d = 0; d < 8; d++) {
            acc_o[d][0] *= scl[0]; acc_o[d][1] *= scl[0];
            acc_o[d][2] *= scl[1]; acc_o[d][3] *= scl[1];
        }

        const u32 bV = vb + (u32)((lane & 15) * FA_KPITCH + (lane >> 4) * 16);
#pragma unroll
        for (int kk = 0; kk < 8; kk++) {
            u32 aPh[4], aPl[4];
            aPh[0] = pk2(acc_s[2*kk][0], acc_s[2*kk][1]);
            aPh[1] = pk2(acc_s[2*kk][2], acc_s[2*kk][3]);
            aPh[2] = pk2(acc_s[2*kk+1][0], acc_s[2*kk+1][1]);
            aPh[3] = pk2(acc_s[2*kk+1][2], acc_s[2*kk+1][3]);
            aPl[0] = pk2(bres(acc_s[2*kk][0]), bres(acc_s[2*kk][1]));
            aPl[1] = pk2(bres(acc_s[2*kk][2]), bres(acc_s[2*kk][3]));
            aPl[2] = pk2(bres(acc_s[2*kk+1][0]), bres(acc_s[2*kk+1][1]));
            aPl[3] = pk2(bres(acc_s[2*kk+1][2]), bres(acc_s[2*kk+1][3]));
#pragma unroll
            for (int dp = 0; dp < 4; dp++) {
                u32 h0, h1, h2, h3, l0, l1, l2, l3;
                const u32 ad = bV + (u32)(kk * 16 * FA_KPITCH + dp * 32);
                LDSM4T(h0, h1, h2, h3, ad);
                LDSM4T(l0, l1, l2, l3, ad + 128);
                u32 vhA[2] = { h0, h1 }, vhB[2] = { h2, h3 };
                u32 vlA[2] = { l0, l1 }, vlB[2] = { l2, l3 };
                mma_bf16(acc_o[2*dp],   aPh, vhA);
                mma_bf16(acc_o[2*dp],   aPh, vlA);
                mma_bf16(acc_o[2*dp],   aPl, vhA);
                mma_bf16(acc_o[2*dp+1], aPh, vhB);
                mma_bf16(acc_o[2*dp+1], aPh, vlB);
                mma_bf16(acc_o[2*dp+1], aPl, vhB);
            }
        }
        __syncthreads();
        if (jt + 2 < jmax) loadKV(jt + 2, jt & 1);
    }

    const float inv0 = 1.f / srow[0], inv1 = 1.f / srow[1];
#pragma unroll
    for (int d = 0; d < 8; d++) {
        const int col = n * 64 + d * 8 + c2;
        const long off0 = ((long)irow0 * BSZ + b) * HD + col;
        const long off1 = ((long)irow1 * BSZ + b) * HD + col;
        pairstore(Oh, Ol, off0, acc_o[d][0] * inv0, acc_o[d][1] * inv0);
        pairstore(Oh, Ol, off1, acc_o[d][2] * inv1, acc_o[d][3] * inv1);
    }
}

// ---------------- converters ----------------

__global__ void transpose_all(const float* __restrict__ Wkv, const float* __restrict__ Wq,
                              const float* __restrict__ Wr,  const float* __restrict__ Wo,
                              const float* __restrict__ W1,  const float* __restrict__ W2,
                              bf16* hWkv, bf16* lWkv, bf16* hWq, bf16* lWq,
                              bf16* hWr, bf16* lWr, bf16* hWo, bf16* lWo,
                              bf16* hW1, bf16* lW1, bf16* hW2, bf16* lW2)
{
    __shared__ float t[32][33];
    const int l = blockIdx.y;
    int tt = blockIdx.x;
    const float* in; bf16 *oh, *ol; int R, C;
    if (tt < 2048)      { in = Wkv; oh = hWkv; ol = lWkv; R = DM; C = 2*HD; }
    else if (tt < 3072) { in = Wq;  oh = hWq;  ol = lWq;  R = DM; C = HD; tt -= 2048; }
    else if (tt < 4096) { in = Wr;  oh = hWr;  ol = lWr;  R = DM; C = HD; tt -= 3072; }
    else if (tt < 5120) { in = Wo;  oh = hWo;  ol = lWo;  R = HD; C = DM; tt -= 4096; }
    else if (tt < 9216) { in = W1;  oh = hW1;  ol = lW1;  R = DM; C = DI; tt -= 5120; }
    else                { in = W2;  oh = hW2;  ol = lW2;  R = DI; C = DM; tt -= 9216; }
    const long zo = (long)l * R * C;
    in += zo; oh += zo; ol += zo;
    const int ct = C / 32;
    const int c0 = (tt % ct) * 32, r0 = (tt / ct) * 32;
    const int tx = threadIdx.x, ty = threadIdx.y;
    {
        float4 v = *(const float4*)(in + (long)(r0 + ty) * C + c0 + tx * 4);
        t[ty][tx*4+0] = v.x; t[ty][tx*4+1] = v.y; t[ty][tx*4+2] = v.z; t[ty][tx*4+3] = v.w;
    }
    __syncthreads();
    {
        float a = t[tx*4+0][ty], b = t[tx*4+1][ty], c = t[tx*4+2][ty], d = t[tx*4+3][ty];
        long o = (long)(c0 + ty) * R + r0 + tx * 4;
        pairstore4(oh, ol, o, a, b, c, d);
    }
}

__global__ void convert_pair(const float* __restrict__ in, bf16* __restrict__ oh,
                             bf16* __restrict__ ol, long n4)
{
    long i = (long)blockIdx.x * 256 + threadIdx.x;
    if (i >= n4) return;
    float4 v = *(const float4*)(in + i * 4);
    pairstore4(oh, ol, i * 4, v.x, v.y, v.z, v.w);
}

// ---------------- elementwise / reductions ----------------

__global__ void embed_kernel(const int* __restrict__ data, const float* __restrict__ embW,
                             float* __restrict__ core, bf16* __restrict__ ch,
                             bf16* __restrict__ cl, float* __restrict__ outm)
{
    long i = (long)blockIdx.x * 256 + threadIdx.x;
    if (i >= (long)ROWS * DM / 4) return;
    int r = (int)(i >> 8);
    float4 v = *(const float4*)(embW + (long)data[r] * DM + (i & 255) * 4);
    *(float4*)(core + i * 4) = v;
    *(float4*)(outm + i * 4) = v;
    pairstore4(ch, cl, i * 4, v.x, v.y, v.z, v.w);
}

__global__ void pos_kernel(bf16* __restrict__ ph, bf16* __restrict__ pl)
{
    long idx = (long)blockIdx.x * 256 + threadIdx.x;
    if (idx >= (long)KLEN * DM) return;
    int j = (int)(idx >> 10), d = (int)(idx & 1023);
    float p = (float)(KLEN - 1 - j);
    int t = (d < 512) ? d : d - 512;
    float invf = expf(-((2.0f * (float)t) / (float)DM) * logf(10000.0f));
    float a = p * invf;
    float x = (d < 512) ? sinf(a) : cosf(a);
    ph[idx] = __float2bfloat16(x);
    pl[idx] = __float2bfloat16(bres(x));
}

__global__ void ln_kernel(const float* __restrict__ x, const float* __restrict__ y,
                          const float* __restrict__ g, const float* __restrict__ b,
                          float* __restrict__ outf, bf16* __restrict__ oh,
                          bf16* __restrict__ ol, float* __restrict__ memsf)
{
    const int r = blockIdx.x, t = threadIdx.x;
    __shared__ float red[256];
    const long base = (long)r * DM + t * 4;
    float4 xv = *(const float4*)(x + base);
    float4 yv = *(const float4*)(y + base);
    float loc[4] = { xv.x + yv.x, xv.y + yv.y, xv.z + yv.z, xv.w + yv.w };
    float s = loc[0] + loc[1] + loc[2] + loc[3];
    red[t] = s; __syncthreads();
    for (int o = 128; o > 0; o >>= 1) { if (t < o) red[t] += red[t + o]; __syncthreads(); }
    const float mu = red[0] * (1.0f / DM);
    __syncthreads();
    float s2 = 0.f;
#pragma unroll
    for (int k = 0; k < 4; k++) { float d = loc[k] - mu; s2 += d * d; }
    red[t] = s2; __syncthreads();
    for (int o = 128; o > 0; o >>= 1) { if (t < o) red[t] += red[t + o]; __syncthreads(); }
    const float rstd = rsqrtf(red[0] * (1.0f / DM) + 1e-5f);
    float4 gv = *(const float4*)(g + t * 4);
    float4 bv = *(const float4*)(b + t * 4);
    float4 o4;
    o4.x = (loc[0] - mu) * rstd * gv.x + bv.x;
    o4.y = (loc[1] - mu) * rstd * gv.y + bv.y;
    o4.z = (loc[2] - mu) * rstd * gv.z + bv.z;
    o4.w = (loc[3] - mu) * rstd * gv.w + bv.w;
    *(float4*)(outf + base) = o4;
    if (memsf) *(float4*)(memsf + base) = o4;
    pairstore4(oh, ol, base, o4.x, o4.y, o4.z, o4.w);
}

__global__ void loss_final_kernel(const float2* __restrict__ lsp,
                                  const float* __restrict__ core,
                                  const float* __restrict__ embW,
                                  const int* __restrict__ target,
                                  float* __restrict__ out)
{
    const int r = blockIdx.x, t = threadIdx.x;
    __shared__ float rm[128], rs[128], rd[128];
    float m = -1e30f, s = 0.f;
    for (int j = t; j < NTOK / 128; j += 128) {
        float2 p = lsp[(long)r * NLSP + j];
        lse_comb(m, s, p.x, p.y);
    }
    const float* cr = core + (long)r * DM;
    const float* er = embW + (long)target[r] * DM;
    float d = 0.f;
    for (int j = t; j < DM / 4; j += 128) {
        float4 a = *(const float4*)(cr + j * 4);
        float4 b = *(const float4*)(er + j * 4);
        d += a.x * b.x + a.y * b.y + a.z * b.z + a.w * b.w;
    }
    rm[t] = m; rs[t] = s; rd[t] = d; __syncthreads();
    for (int o = 64; o > 0; o >>= 1) {
        if (t < o) {
            lse_comb(rm[t], rs[t], rm[t + o], rs[t + o]);
            rd[t] += rd[t + o];
        }
        __syncthreads();
    }
    if (t == 0) out[r] = (logf(rs[0]) + rm[0]) - rd[0];
}

// ---------------- host ----------------

#define S128 73728
#define GSA(p, s) cudaGetSymbolAddress((void**)&p, s)

static inline dim3 gt(int N, int M, int bz, int ntile) { return dim3(N / ntile, M / 128, bz); }

extern "C" void kernel_launch(void* const* d_in, const int* in_sizes, int n_in,
                              void* d_out, int out_size)
{
    const int*   data   = (const int*)  d_in[0];
    const int*   target = (const int*)  d_in[1];
    const float* memory = (const float*)d_in[2];
    const float* embW   = (const float*)d_in[3];
    const float* rwb    = (const float*)d_in[4];
    const float* rrb    = (const float*)d_in[5];
    const float* Wq     = (const float*)d_in[6];
    const float* Wkv    = (const float*)d_in[7];
    const float* Wr     = (const float*)d_in[8];
    const float* Wo     = (const float*)d_in[9];
    const float* W1     = (const float*)d_in[10];
    const float* b1     = (const float*)d_in[11];
    const float* W2     = (const float*)d_in[12];
    const float* b2     = (const float*)d_in[13];
    const float* ln1g   = (const float*)d_in[14];
    const float* ln1b   = (const float*)d_in[15];
    const float* ln2g   = (const float*)d_in[16];
    const float* ln2b   = (const float*)d_in[17];

    float* out      = (float*)d_out;
    float* out_loss = out;
    float* out_mems = out + ROWS;

    float *core, *tmp;
    __half* bd;
    float2* lsp;
    GSA(core, g_core); GSA(tmp, g_tmp); GSA(bd, g_bd); GSA(lsp, g_lsp);

    bf16 *hcore,*lcore,*hmem,*lmem,*hqrw,*lqrw,*hqrr,*lqrr,*hk,*lk,*hv,*lv,*hrk,*lrk,
         *hvec,*lvec,*hffh,*lffh,*hpos,*lpos,*hemb,*lemb,
         *hWkvT,*lWkvT,*hWqT,*lWqT,*hWrT,*lWrT,*hWoT,*lWoT,*hW1T,*lW1T,*hW2T,*lW2T;
    GSA(hcore,h_core); GSA(lcore,l_core); GSA(hmem,h_mem); GSA(lmem,l_mem);
    GSA(hqrw,h_qrw); GSA(lqrw,l_qrw); GSA(hqrr,h_qrr); GSA(lqrr,l_qrr);
    GSA(hk,h_kk); GSA(lk,l_kk); GSA(hv,h_vv); GSA(lv,l_vv);
    GSA(hrk,h_rk); GSA(lrk,l_rk);
    GSA(hvec,h_vec); GSA(lvec,l_vec); GSA(hffh,h_ffh); GSA(lffh,l_ffh);
    GSA(hpos,h_pos); GSA(lpos,l_pos); GSA(hemb,h_emb); GSA(lemb,l_emb);
    GSA(hWkvT,h_WkvT); GSA(lWkvT,l_WkvT); GSA(hWqT,h_WqT); GSA(lWqT,l_WqT);
    GSA(hWrT,h_WrT); GSA(lWrT,l_WrT); GSA(hWoT,h_WoT); GSA(lWoT,l_WoT);
    GSA(hW1T,h_W1T); GSA(lW1T,l_W1T); GSA(hW2T,h_W2T); GSA(lW2T,l_W2T);

    // smem opt-in for EVERY launched instantiation
    cudaFuncSetAttribute(pgemm<128,0,3>, cudaFuncAttributeMaxDynamicSharedMemorySize, S128);
    cudaFuncSetAttribute(pgemm<128,1,3>, cudaFuncAttributeMaxDynamicSharedMemorySize, S128);
    cudaFuncSetAttribute(pgemm<128,2,3>, cudaFuncAttributeMaxDynamicSharedMemorySize, S128);
    cudaFuncSetAttribute(pgemm<128,3,3>, cudaFuncAttributeMaxDynamicSharedMemorySize, S128);
    cudaFuncSetAttribute(pgemm<128,4,3>, cudaFuncAttributeMaxDynamicSharedMemorySize, S128);
    cudaFuncSetAttribute(pgemm<128,6,3>, cudaFuncAttributeMaxDynamicSharedMemorySize, S128);
    cudaFuncSetAttribute(pgemm<128,7,1>, cudaFuncAttributeMaxDynamicSharedMemorySize, S128);
    cudaFuncSetAttribute(pgemm<128,8,3>, cudaFuncAttributeMaxDynamicSharedMemorySize, S128);
    cudaFuncSetAttribute(fattn, cudaFuncAttributeMaxDynamicSharedMemorySize, FA_SMEM);

    const dim3 tb(8, 32);
    {
        long n1 = (long)NL*ROWS*DM/4;
        convert_pair<<<(int)((n1 + 255)/256), 256>>>(memory, hmem, lmem, n1);
        long n2 = (long)NTOK*DM/4;
        convert_pair<<<(int)((n2 + 255)/256), 256>>>(embW, hemb, lemb, n2);
    }
    embed_kernel<<<(ROWS*DM/4 + 255)/256, 256>>>(data, embW, core, hcore, lcore, out_mems);
    pos_kernel<<<(KLEN*DM + 255)/256, 256>>>(hpos, lpos);
    transpose_all<<<dim3(13312, NL), tb>>>(Wkv, Wq, Wr, Wo, W1, W2,
        hWkvT, lWkvT, hWqT, lWqT, hWrT, lWrT, hWoT, lWoT, hW1T, lW1T, hW2T, lW2T);

    for (int l = 0; l < NL; l++) {
        const bf16* hWkvl = hWkvT + (size_t)l*2*HD*DM;
        const bf16* lWkvl = lWkvT + (size_t)l*2*HD*DM;

        pgemm<128,6,3><<<gt(2*HD, ROWS, 1, 128), 256, S128>>>(
            hmem + (size_t)l*ROWS*DM, lmem + (size_t)l*ROWS*DM, hWkvl, lWkvl,
            DM, DM, DM, 0,0,0,0, 1, HD, 0,0,
            nullptr, hk, lk, hv, lv, nullptr, nullptr, nullptr, HD);
        pgemm<128,6,3><<<gt(2*HD, ROWS, 1, 128), 256, S128>>>(
            hcore, lcore, hWkvl, lWkvl,
            DM, DM, DM, 0,0,0,0, 1, HD, 0,0,
            nullptr, hk + (size_t)ROWS*HD, lk + (size_t)ROWS*HD,
            hv + (size_t)ROWS*HD, lv + (size_t)ROWS*HD, nullptr, nullptr, nullptr, HD);

        pgemm<128,3,3><<<gt(HD, ROWS, 1, 128), 256, S128>>>(
            hcore, lcore, hWqT + (size_t)l*HD*DM, lWqT + (size_t)l*HD*DM,
            DM, DM, DM, 0,0,0,0, 1, DM, 0,0,
            nullptr, hqrw, lqrw, hqrr, lqrr, rwb, rrb, nullptr, 0);

        pgemm<128,4,3><<<gt(HD, KLEN, 1, 128), 256, S128>>>(
            hpos, lpos, hWrT + (size_t)l*HD*DM, lWrT + (size_t)l*HD*DM,
            DM, DM, DM, 0,0,0,0, 1, HD, 0,0,
            nullptr, hrk, lrk, nullptr, nullptr, nullptr, nullptr, nullptr, 0);

        pgemm<128,8,3><<<gt(KLEN, ROWS, NH, 128), 256, S128>>>(
            hqrr, lqrr, hrk, lrk,
            DH, DM, HD,
            0, (long)DH, 0, (long)DH, NH,
            KLEN, 0, (long)ROWS*KLEN,
            (float*)bd, nullptr, nullptr, nullptr, nullptr, nullptr, nullptr, nullptr, 0);

        fattn<<<dim3(QLEN/128, BSZ*NH), 256, FA_SMEM>>>(
            hqrw, lqrw, hk, lk, hv, lv, bd, hvec, lvec);

        pgemm<128,0,3><<<gt(DM, ROWS, 1, 128), 256, S128>>>(
            hvec, lvec, hWoT + (size_t)l*DM*HD, lWoT + (size_t)l*DM*HD,
            HD, HD, HD, 0,0,0,0, 1, DM, 0,0,
            tmp, nullptr, nullptr, nullptr, nullptr, nullptr, nullptr, nullptr, 0);

        ln_kernel<<<ROWS, 256>>>(core, tmp, ln1g + (size_t)l*DM, ln1b + (size_t)l*DM,
                                 core, hcore, lcore, nullptr);

        pgemm<128,2,3><<<gt(DI, ROWS, 1, 128), 256, S128>>>(
            hcore, lcore, hW1T + (size_t)l*DI*DM, lW1T + (size_t)l*DI*DM,
            DM, DM, DM, 0,0,0,0, 1, DI, 0,0,
            nullptr, hffh, lffh, nullptr, nullptr, b1 + (size_t)l*DI, nullptr, nullptr, 0);

        pgemm<128,1,3><<<gt(DM, ROWS, 1, 128), 256, S128>>>(
            hffh, lffh, hW2T + (size_t)l*DM*DI, lW2T + (size_t)l*DM*DI,
            DI, DI, DI, 0,0,0,0, 1, DM, 0,0,
            tmp, nullptr, nullptr, nullptr, nullptr, b2 + (size_t)l*DM, nullptr, nullptr, 0);

        ln_kernel<<<ROWS, 256>>>(core, tmp, ln2g + (size_t)l*DM, ln2b + (size_t)l*DM,
                                 core, hcore, lcore,
                                 (l < NL - 1) ? (out_mems + (size_t)(l + 1)*ROWS*DM) : nullptr);
    }

    // logits -> lse partials, SINGLE-term bf16 (errors average across vocab in lse)
    pgemm<128,7,1><<<gt(NTOK, ROWS, 1, 128), 256, S128>>>(
        hcore, lcore, hemb, lemb,
        DM, DM, DM, 0,0,0,0, 1, 0, 0,0,
        (float*)lsp, nullptr, nullptr, nullptr, nullptr, nullptr, nullptr, nullptr, 0);
    loss_final_kernel<<<ROWS, 128>>>(lsp, core, embW, target, out_loss);

    (void)in_sizes; (void)n_in; (void)out_size;
}

// round 17
// speedup vs baseline: 4.0387x; 1.0306x over previous
#include <cuda_runtime.h>
#include <cuda_bf16.h>
#include <cuda_fp16.h>
#include <math.h>
#include <stdint.h>

typedef __nv_bfloat16 bf16;
typedef __nv_bfloat162 bf162;
typedef uint32_t u32;

#define QLEN 512
#define MEMLEN 512
#define KLEN 1024
#define BSZ 8
#define NH 16
#define DH 64
#define DM 1024
#define DI 4096
#define NL 6
#define NTOK 32000
#define HD 1024
#define ROWS (QLEN*BSZ)
#define KROWS (KLEN*BSZ)
#define SCALE 0.125f
#define NLSP 256

// ---------------- fp32 scratch ----------------
__device__ float g_core [ROWS*DM];
__device__ float g_tmp  [ROWS*DM];
__device__ __half g_bd  [(size_t)NH*ROWS*KLEN];
__device__ float2 g_lsp [(size_t)ROWS*NLSP];

// ---------------- bf16 hi/lo pair scratch ----------------
#define PAIR(name, n) __device__ bf16 h_##name[n]; __device__ bf16 l_##name[n];
PAIR(core, ROWS*DM)
PAIR(mem,  (size_t)NL*ROWS*DM)
PAIR(qrw,  ROWS*DM)
PAIR(qrr,  ROWS*DM)
PAIR(kk,   KROWS*HD)
PAIR(vv,   KROWS*HD)
PAIR(rk,   (size_t)NL*KLEN*HD)
PAIR(vec,  ROWS*HD)
PAIR(ffh,  (size_t)ROWS*DI)
PAIR(pos,  KLEN*DM)
PAIR(emb,  (size_t)NTOK*DM)
PAIR(WkvT, (size_t)NL*2*HD*DM)
PAIR(WqT,  (size_t)NL*HD*DM)
PAIR(WrT,  (size_t)NL*HD*DM)
PAIR(WoT,  (size_t)NL*DM*HD)
PAIR(W1T,  (size_t)NL*DI*DM)
PAIR(W2T,  (size_t)NL*DM*DI)

// ---------------- helpers ----------------
__device__ __forceinline__ void mma_bf16(float* d, const u32* a, const u32* b) {
    asm volatile(
        "mma.sync.aligned.m16n8k16.row.col.f32.bf16.bf16.f32 "
        "{%0,%1,%2,%3}, {%4,%5,%6,%7}, {%8,%9}, {%0,%1,%2,%3};\n"
        : "+f"(d[0]), "+f"(d[1]), "+f"(d[2]), "+f"(d[3])
        : "r"(a[0]), "r"(a[1]), "r"(a[2]), "r"(a[3]), "r"(b[0]), "r"(b[1]));
}
#define LDSM4(r0,r1,r2,r3,addr) \
    asm volatile("ldmatrix.sync.aligned.m8n8.x4.shared.b16 {%0,%1,%2,%3}, [%4];" \
        : "=r"(r0), "=r"(r1), "=r"(r2), "=r"(r3) : "r"(addr))
#define LDSM4T(r0,r1,r2,r3,addr) \
    asm volatile("ldmatrix.sync.aligned.m8n8.x4.trans.shared.b16 {%0,%1,%2,%3}, [%4];" \
        : "=r"(r0), "=r"(r1), "=r"(r2), "=r"(r3) : "r"(addr))
__device__ __forceinline__ void cp16s(u32 sdst, const void* g) {
    asm volatile("cp.async.cg.shared.global [%0], [%1], 16;\n" :: "r"(sdst), "l"(g));
}
#define CP_COMMIT() asm volatile("cp.async.commit_group;\n")
#define CP_WAIT1()  asm volatile("cp.async.wait_group 1;\n")
#define CP_WAIT0()  asm volatile("cp.async.wait_group 0;\n")

__device__ __forceinline__ u32 pk2(float a, float b) {
    bf162 t = __floats2bfloat162_rn(a, b);
    return *(u32*)&t;
}
__device__ __forceinline__ float bres(float x) {
    return x - __bfloat162float(__float2bfloat16(x));
}
__device__ __forceinline__ void pairstore(bf16* H, bf16* L, long off, float v0, float v1) {
    *(u32*)(H + off) = pk2(v0, v1);
    *(u32*)(L + off) = pk2(bres(v0), bres(v1));
}
__device__ __forceinline__ void pairstore4(bf16* H, bf16* L, long off,
                                           float a, float b, float c, float d) {
    uint2 hh = { pk2(a, b), pk2(c, d) };
    uint2 ll = { pk2(bres(a), bres(b)), pk2(bres(c), bres(d)) };
    *(uint2*)(H + off) = hh;
    *(uint2*)(L + off) = ll;
}
__device__ __forceinline__ void lse_comb(float& m, float& s, float m2, float s2) {
    float M = fmaxf(m, m2);
    s = s * expf(m - M) + s2 * expf(m2 - M);
    m = M;
}

// ---------------- pair-bf16 NT GEMM (mma.sync) ----------------
// TERMS=3: hi/lo pair arithmetic, K-step 32. TERMS=1: hi only, K-step 64.
// EPI: 0 fp32  1 fp32+bias  2 pair relu(+bias)  3 dual pair  4 pair
//      6 kv-split  7 logsumexp partials  8 fp16 store (+BD causal tile skip)
template <int NTILE, int EPI, int TERMS>
__global__ void __launch_bounds__(NTILE == 128 ? 256 : 128, 2)
pgemm(const bf16* __restrict__ Ah, const bf16* __restrict__ Al,
      const bf16* __restrict__ Bh, const bf16* __restrict__ Bl,
      int K, int lda, int ldb,
      long sA1, long sA2, long sB1, long sB2, int batch2,
      int ldc, long sC1, long sC2,
      float* __restrict__ Cf,
      bf16* __restrict__ Ch, bf16* __restrict__ Cl,
      bf16* __restrict__ Ch2, bf16* __restrict__ Cl2,
      const float* __restrict__ bias, const float* __restrict__ bias2,
      float* __restrict__ Cf2, int ldc2)
{
    constexpr int T    = (NTILE == 128) ? 256 : 128;
    constexpr int ASTB = 128 * 144;
    constexpr int BSTB = NTILE * 144;
    constexpr int KST  = (TERMS == 1) ? 64 : 32;
    constexpr int NG   = (TERMS == 1) ? 4 : 2;
    extern __shared__ char smraw[];
    const u32 smS = (u32)__cvta_generic_to_shared(smraw);

    const int m0 = blockIdx.y * 128, n0 = blockIdx.x * NTILE;

    // BD causal tile skip: fattn reads bd[i][idx] only for idx >= QLEN-1-i.
    // Row m -> i = m>>3. Tile fully unread iff n0+128 <= 511 - i_max.
    if (EPI == 8) {
        const int imax = (m0 + 127) >> 3;
        if (n0 + 128 <= (QLEN - 1) - imax) return;
    }

    const int bz = blockIdx.z;
    const int b1 = bz / batch2, b2 = bz % batch2;
    Ah += b1 * sA1 + b2 * sA2;  Al += b1 * sA1 + b2 * sA2;
    Bh += b1 * sB1 + b2 * sB2;  Bl += b1 * sB1 + b2 * sB2;
    const long cOff = b1 * sC1 + b2 * sC2;

    const int tid = threadIdx.x, warp = tid >> 5, lane = tid & 31;
    constexpr int NWN = NTILE / 32;
    const int wm = warp / NWN, wn = warp % NWN;

    float acc[4][4][4];
#pragma unroll
    for (int mt = 0; mt < 4; mt++)
#pragma unroll
        for (int nt = 0; nt < 4; nt++)
#pragma unroll
            for (int e = 0; e < 4; e++) acc[mt][nt][e] = 0.f;

    const int KT = K / KST;

    auto issue = [&](int kt, int st) {
        const int k0 = kt * KST;
        const u32 aB = smS + st * ASTB;
        const u32 bB = smS + 2 * ASTB + st * BSTB;
#pragma unroll
        for (int i = 0; i < 1024 / T; i++) {
            int idx = tid + i * T, r = idx >> 3, q = idx & 7;
            const bf16* src = (TERMS == 1)
                ? (Ah + (long)(m0 + r) * lda + k0 + q * 8)
                : ((q < 4) ? (Ah + (long)(m0 + r) * lda + k0 + q * 8)
                           : (Al + (long)(m0 + r) * lda + k0 + (q - 4) * 8));
            cp16s(aB + r * 144 + q * 16, src);
        }
#pragma unroll
        for (int i = 0; i < NTILE * 8 / T; i++) {
            int idx = tid + i * T, r = idx >> 3, q = idx & 7;
            const bf16* src = (TERMS == 1)
                ? (Bh + (long)(n0 + r) * ldb + k0 + q * 8)
                : ((q < 4) ? (Bh + (long)(n0 + r) * ldb + k0 + q * 8)
                           : (Bl + (long)(n0 + r) * ldb + k0 + (q - 4) * 8));
            cp16s(bB + r * 144 + q * 16, src);
        }
    };

    const u32 aLane = (u32)((lane & 15) * 144 + (lane >> 4) * 16);
    const u32 bLane = (u32)(((lane >> 4) * 8 + (lane & 7)) * 144 + ((lane >> 3) & 1) * 16);

    issue(0, 0); CP_COMMIT();
    if (KT > 1) issue(1, 1);
    CP_COMMIT();

    for (int kt = 0; kt < KT; kt++) {
        CP_WAIT1();
        __syncthreads();
        const u32 As = smS + (kt & 1) * ASTB + wm * 64 * 144 + aLane;
        const u32 Bs = smS + 2 * ASTB + (kt & 1) * BSTB + wn * 32 * 144 + bLane;

#pragma unroll
        for (int g = 0; g < NG; g++) {
            if (TERMS == 1) {
                u32 ah[4][4], bh[4][2];
#pragma unroll
                for (int mt = 0; mt < 4; mt++) {
                    const u32 ad = As + mt * 2304 + g * 32;
                    LDSM4(ah[mt][0], ah[mt][1], ah[mt][2], ah[mt][3], ad);
                }
#pragma unroll
                for (int p = 0; p < 2; p++) {
                    const u32 bd_ = Bs + p * 2304 + g * 32;
                    LDSM4(bh[2*p][0], bh[2*p][1], bh[2*p+1][0], bh[2*p+1][1], bd_);
                }
#pragma unroll
                for (int mt = 0; mt < 4; mt++)
#pragma unroll
                    for (int nt = 0; nt < 4; nt++)
                        mma_bf16(acc[mt][nt], ah[mt], bh[nt]);
            } else {
                u32 ah[4][4], alr[4][4], bh[4][2], blr[4][2];
#pragma unroll
                for (int mt = 0; mt < 4; mt++) {
                    const u32 ad = As + mt * 2304 + g * 32;
                    LDSM4(ah[mt][0], ah[mt][1], ah[mt][2], ah[mt][3], ad);
                    LDSM4(alr[mt][0], alr[mt][1], alr[mt][2], alr[mt][3], ad + 64);
                }
#pragma unroll
                for (int p = 0; p < 2; p++) {
                    const u32 bd_ = Bs + p * 2304 + g * 32;
                    LDSM4(bh[2*p][0], bh[2*p][1], bh[2*p+1][0], bh[2*p+1][1], bd_);
                    LDSM4(blr[2*p][0], blr[2*p][1], blr[2*p+1][0], blr[2*p+1][1], bd_ + 64);
                }
#pragma unroll
                for (int mt = 0; mt < 4; mt++)
#pragma unroll
                    for (int nt = 0; nt < 4; nt++) {
                        mma_bf16(acc[mt][nt], ah[mt], bh[nt]);
                        mma_bf16(acc[mt][nt], ah[mt], blr[nt]);
                        mma_bf16(acc[mt][nt], alr[mt], bh[nt]);
                    }
            }
        }
        __syncthreads();
        if (kt + 2 < KT) issue(kt + 2, kt & 1);
        CP_COMMIT();
    }

    const int gl = lane >> 2, c2 = (lane & 3) * 2;

    if (EPI == 7) {
        float2* red = (float2*)smraw;
        __syncthreads();
#pragma unroll
        for (int mt = 0; mt < 4; mt++)
#pragma unroll
            for (int h = 0; h < 2; h++) {
                float m = -1e30f, s = 0.f;
#pragma unroll
                for (int nt = 0; nt < 4; nt++)
                    m = fmaxf(m, fmaxf(acc[mt][nt][h*2], acc[mt][nt][h*2+1]));
#pragma unroll
                for (int nt = 0; nt < 4; nt++)
                    s += expf(acc[mt][nt][h*2] - m) + expf(acc[mt][nt][h*2+1] - m);
#pragma unroll
                for (int o = 1; o < 4; o <<= 1) {
                    float m2 = __shfl_xor_sync(0xffffffff, m, o);
                    float s2 = __shfl_xor_sync(0xffffffff, s, o);
                    lse_comb(m, s, m2, s2);
                }
                if ((lane & 3) == 0) {
                    int r = wm * 64 + mt * 16 + h * 8 + gl;
                    red[r * NWN + wn] = make_float2(m, s);
                }
            }
        __syncthreads();
        if (tid < 128) {
            float m = -1e30f, s = 0.f;
#pragma unroll
            for (int w = 0; w < NWN; w++) {
                float2 p = red[tid * NWN + w];
                lse_comb(m, s, p.x, p.y);
            }
            ((float2*)Cf)[(long)(m0 + tid) * NLSP + blockIdx.x] = make_float2(m, s);
        }
        return;
    }

#pragma unroll
    for (int mt = 0; mt < 4; mt++)
#pragma unroll
        for (int nt = 0; nt < 4; nt++)
#pragma unroll
            for (int h = 0; h < 2; h++) {
                const int row = m0 + wm * 64 + mt * 16 + gl + h * 8;
                const int col = n0 + wn * 32 + nt * 8 + c2;
                float v0 = acc[mt][nt][h*2], v1 = acc[mt][nt][h*2+1];
                const long off = (long)row * ldc + col + cOff;
                if (EPI == 0) {
                    *(float2*)(Cf + off) = make_float2(v0, v1);
                } else if (EPI == 1) {
                    *(float2*)(Cf + off) = make_float2(v0 + bias[col], v1 + bias[col+1]);
                } else if (EPI == 2) {
                    pairstore(Ch, Cl, off, fmaxf(v0 + bias[col], 0.f), fmaxf(v1 + bias[col+1], 0.f));
                } else if (EPI == 3) {
                    pairstore(Ch,  Cl,  off, v0 + bias[col],  v1 + bias[col+1]);
                    pairstore(Ch2, Cl2, off, v0 + bias2[col], v1 + bias2[col+1]);
                } else if (EPI == 4) {
                    pairstore(Ch, Cl, off, v0, v1);
                } else if (EPI == 8) {
                    *(__half2*)((__half*)Cf + off) = __floats2half2_rn(v0, v1);
                } else {  // 6: kv split, both halves pair
                    if (n0 < HD) pairstore(Ch, Cl, (long)row * ldc + col, v0, v1);
                    else         pairstore(Ch2, Cl2, (long)row * ldc2 + (col - HD), v0, v1);
                }
            }
}

// ---------------- fused attention ----------------
#define FA_KPITCH 272
#define FA_TILE  (128*FA_KPITCH)
#define FA_STG   (2*FA_TILE)
#define FA_SMEM  (2*FA_STG)

__global__ void __launch_bounds__(256, 1)
fattn(const bf16* __restrict__ Qh, const bf16* __restrict__ Ql,
      const bf16* __restrict__ Kh, const bf16* __restrict__ Kl,
      const bf16* __restrict__ Vh, const bf16* __restrict__ Vl,
      const __half* __restrict__ bd,
      bf16* __restrict__ Oh, bf16* __restrict__ Ol)
{
    extern __shared__ char smraw[];
    const u32 smS = (u32)__cvta_generic_to_shared(smraw);
    const int tid = threadIdx.x, warp = tid >> 5, lane = tid & 31;
    const int qt = blockIdx.x, bn = blockIdx.y;
    const int b = bn >> 4, n = bn & 15;
    const int i_base = qt * 128;
    const int i0 = i_base + warp * 16;
    const int jmax = (qt + 5 < 8) ? qt + 5 : 8;

#pragma unroll
    for (int i = 0; i < 8; i++) {
        int idx = tid + i * 256;
        int r = idx >> 4, q = idx & 15;
        const bf16* src = (q < 8)
            ? (Qh + ((long)(i_base + r) * BSZ + b) * DM + n * 64 + q * 8)
            : (Ql + ((long)(i_base + r) * BSZ + b) * DM + n * 64 + (q - 8) * 8);
        cp16s(smS + r * FA_KPITCH + ((q < 8) ? q * 16 : 128 + (q - 8) * 16), src);
    }
    CP_COMMIT();
    CP_WAIT0();
    __syncthreads();
    u32 qfh[4][4], qfl[4][4];
    {
        const u32 aQ = smS + (u32)((warp * 16 + (lane & 15)) * FA_KPITCH + (lane >> 4) * 16);
#pragma unroll
        for (int g = 0; g < 4; g++) {
            LDSM4(qfh[g][0], qfh[g][1], qfh[g][2], qfh[g][3], aQ + g * 32);
            LDSM4(qfl[g][0], qfl[g][1], qfl[g][2], qfl[g][3], aQ + g * 32 + 128);
        }
    }
    __syncthreads();

    auto loadKV = [&](int jt, int st) {
        const int j0 = jt << 7;
        const u32 kb = smS + (u32)st * FA_STG;
        const u32 vb = kb + FA_TILE;
#pragma unroll
        for (int i = 0; i < 8; i++) {
            int idx = tid + i * 256;
            int r = idx >> 4, q = idx & 15;
            const long src = ((long)(j0 + r) * BSZ + b) * HD + n * 64 + ((q < 8) ? q * 8 : (q - 8) * 8);
            const u32 doff = (u32)(r * FA_KPITCH + ((q < 8) ? q * 16 : 128 + (q - 8) * 16));
            cp16s(kb + doff, ((q < 8) ? Kh : Kl) + src);
            cp16s(vb + doff, ((q < 8) ? Vh : Vl) + src);
        }
        CP_COMMIT();
    };

    float acc_o[8][4];
#pragma unroll
    for (int d = 0; d < 8; d++)
#pragma unroll
        for (int e = 0; e < 4; e++) acc_o[d][e] = 0.f;
    float mrow[2] = { -1e30f, -1e30f }, srow[2] = { 0.f, 0.f };

    loadKV(0, 0);
    if (jmax > 1) loadKV(1, 1);

    const int g = lane >> 2, c2 = (lane & 3) * 2;
    const int irow0 = i0 + g, irow1 = i0 + g + 8;

    for (int jt = 0; jt < jmax; jt++) {
        CP_WAIT1();
        __syncthreads();
        const int j0 = jt << 7;
        const u32 kb = smS + (u32)(jt & 1) * FA_STG;
        const u32 vb = kb + FA_TILE;

        float acc_s[16][4];
#pragma unroll
        for (int nt = 0; nt < 16; nt++)
#pragma unroll
            for (int e = 0; e < 4; e++) acc_s[nt][e] = 0.f;

        const u32 bK = kb + (u32)(((lane >> 4) * 8 + (lane & 7)) * FA_KPITCH + ((lane >> 3) & 1) * 16);
#pragma unroll
        for (int ntp = 0; ntp < 8; ntp++) {
#pragma unroll
            for (int gg = 0; gg < 4; gg++) {
                u32 h0, h1, h2, h3, l0, l1, l2, l3;
                const u32 ad = bK + (u32)(ntp * 16 * FA_KPITCH + gg * 32);
                LDSM4(h0, h1, h2, h3, ad);
                LDSM4(l0, l1, l2, l3, ad + 128);
                u32 bhA[2] = { h0, h1 }, bhB[2] = { h2, h3 };
                u32 blA[2] = { l0, l1 }, blB[2] = { l2, l3 };
                mma_bf16(acc_s[2*ntp],   qfh[gg], bhA);
                mma_bf16(acc_s[2*ntp],   qfh[gg], blA);
                mma_bf16(acc_s[2*ntp],   qfl[gg], bhA);
                mma_bf16(acc_s[2*ntp+1], qfh[gg], bhB);
                mma_bf16(acc_s[2*ntp+1], qfh[gg], blB);
                mma_bf16(acc_s[2*ntp+1], qfl[gg], bhB);
            }
        }

        float scl[2];
#pragma unroll
        for (int h = 0; h < 2; h++) {
            const int i = (h == 0) ? irow0 : irow1;
            const int shift = QLEN - 1 - i;
            const int limit = i + MEMLEN;
            const __half* bdr = bd + ((long)n * ROWS + ((long)i * BSZ + b)) * KLEN + shift;
            float tm = -1e30f;
#pragma unroll
            for (int nt = 0; nt < 16; nt++) {
#pragma unroll
                for (int e = 0; e < 2; e++) {
                    int jg = j0 + nt * 8 + c2 + e;
                    float v = (jg <= limit) ? (acc_s[nt][h*2+e] + __half2float(bdr[jg])) * SCALE : -1e30f;
                    acc_s[nt][h*2+e] = v;
                    tm = fmaxf(tm, v);
                }
            }
            tm = fmaxf(tm, __shfl_xor_sync(0xffffffff, tm, 1));
            tm = fmaxf(tm, __shfl_xor_sync(0xffffffff, tm, 2));
            float mn = fmaxf(mrow[h], tm);
            scl[h] = expf(mrow[h] - mn);
            mrow[h] = mn;
            float ps = 0.f;
#pragma unroll
            for (int nt = 0; nt < 16; nt++) {
#pragma unroll
                for (int e = 0; e < 2; e++) {
                    float p = expf(acc_s[nt][h*2+e] - mn);
                    acc_s[nt][h*2+e] = p;
                    ps += p;
                }
            }
            ps += __shfl_xor_sync(0xffffffff, ps, 1);
            ps += __shfl_xor_sync(0xffffffff, ps, 2);
            srow[h] = srow[h] * scl[h] + ps;
        }
#pragma unroll
        for (int d = 0; d < 8; d++) {
            acc_o[d][0] *= scl[0]; acc_o[d][1] *= scl[0];
            acc_o[d][2] *= scl[1]; acc_o[d][3] *= scl[1];
        }

        const u32 bV = vb + (u32)((lane & 15) * FA_KPITCH + (lane >> 4) * 16);
#pragma unroll
        for (int kk = 0; kk < 8; kk++) {
            u32 aPh[4], aPl[4];
            aPh[0] = pk2(acc_s[2*kk][0], acc_s[2*kk][1]);
            aPh[1] = pk2(acc_s[2*kk][2], acc_s[2*kk][3]);
            aPh[2] = pk2(acc_s[2*kk+1][0], acc_s[2*kk+1][1]);
            aPh[3] = pk2(acc_s[2*kk+1][2], acc_s[2*kk+1][3]);
            aPl[0] = pk2(bres(acc_s[2*kk][0]), bres(acc_s[2*kk][1]));
            aPl[1] = pk2(bres(acc_s[2*kk][2]), bres(acc_s[2*kk][3]));
            aPl[2] = pk2(bres(acc_s[2*kk+1][0]), bres(acc_s[2*kk+1][1]));
            aPl[3] = pk2(bres(acc_s[2*kk+1][2]), bres(acc_s[2*kk+1][3]));
#pragma unroll
            for (int dp = 0; dp < 4; dp++) {
                u32 h0, h1, h2, h3, l0, l1, l2, l3;
                const u32 ad = bV + (u32)(kk * 16 * FA_KPITCH + dp * 32);
                LDSM4T(h0, h1, h2, h3, ad);
                LDSM4T(l0, l1, l2, l3, ad + 128);
                u32 vhA[2] = { h0, h1 }, vhB[2] = { h2, h3 };
                u32 vlA[2] = { l0, l1 }, vlB[2] = { l2, l3 };
                mma_bf16(acc_o[2*dp],   aPh, vhA);
                mma_bf16(acc_o[2*dp],   aPh, vlA);
                mma_bf16(acc_o[2*dp],   aPl, vhA);
                mma_bf16(acc_o[2*dp+1], aPh, vhB);
                mma_bf16(acc_o[2*dp+1], aPh, vlB);
                mma_bf16(acc_o[2*dp+1], aPl, vhB);
            }
        }
        __syncthreads();
        if (jt + 2 < jmax) loadKV(jt + 2, jt & 1);
    }

    const float inv0 = 1.f / srow[0], inv1 = 1.f / srow[1];
#pragma unroll
    for (int d = 0; d < 8; d++) {
        const int col = n * 64 + d * 8 + c2;
        const long off0 = ((long)irow0 * BSZ + b) * HD + col;
        const long off1 = ((long)irow1 * BSZ + b) * HD + col;
        pairstore(Oh, Ol, off0, acc_o[d][0] * inv0, acc_o[d][1] * inv0);
        pairstore(Oh, Ol, off1, acc_o[d][2] * inv1, acc_o[d][3] * inv1);
    }
}

// ---------------- converters ----------------

__global__ void transpose_all(const float* __restrict__ Wkv, const float* __restrict__ Wq,
                              const float* __restrict__ Wr,  const float* __restrict__ Wo,
                              const float* __restrict__ W1,  const float* __restrict__ W2,
                              bf16* hWkv, bf16* lWkv, bf16* hWq, bf16* lWq,
                              bf16* hWr, bf16* lWr, bf16* hWo, bf16* lWo,
                              bf16* hW1, bf16* lW1, bf16* hW2, bf16* lW2)
{
    __shared__ float t[32][33];
    const int l = blockIdx.y;
    int tt = blockIdx.x;
    const float* in; bf16 *oh, *ol; int R, C;
    if (tt < 2048)      { in = Wkv; oh = hWkv; ol = lWkv; R = DM; C = 2*HD; }
    else if (tt < 3072) { in = Wq;  oh = hWq;  ol = lWq;  R = DM; C = HD; tt -= 2048; }
    else if (tt < 4096) { in = Wr;  oh = hWr;  ol = lWr;  R = DM; C = HD; tt -= 3072; }
    else if (tt < 5120) { in = Wo;  oh = hWo;  ol = lWo;  R = HD; C = DM; tt -= 4096; }
    else if (tt < 9216) { in = W1;  oh = hW1;  ol = lW1;  R = DM; C = DI; tt -= 5120; }
    else                { in = W2;  oh = hW2;  ol = lW2;  R = DI; C = DM; tt -= 9216; }
    const long zo = (long)l * R * C;
    in += zo; oh += zo; ol += zo;
    const int ct = C / 32;
    const int c0 = (tt % ct) * 32, r0 = (tt / ct) * 32;
    const int tx = threadIdx.x, ty = threadIdx.y;
    {
        float4 v = *(const float4*)(in + (long)(r0 + ty) * C + c0 + tx * 4);
        t[ty][tx*4+0] = v.x; t[ty][tx*4+1] = v.y; t[ty][tx*4+2] = v.z; t[ty][tx*4+3] = v.w;
    }
    __syncthreads();
    {
        float a = t[tx*4+0][ty], b = t[tx*4+1][ty], c = t[tx*4+2][ty], d = t[tx*4+3][ty];
        long o = (long)(c0 + ty) * R + r0 + tx * 4;
        pairstore4(oh, ol, o, a, b, c, d);
    }
}

__global__ void convert_pair(const float* __restrict__ in, bf16* __restrict__ oh,
                             bf16* __restrict__ ol, long n4)
{
    long i = (long)blockIdx.x * 256 + threadIdx.x;
    if (i >= n4) return;
    float4 v = *(const float4*)(in + i * 4);
    pairstore4(oh, ol, i * 4, v.x, v.y, v.z, v.w);
}

// ---------------- elementwise / reductions ----------------

__global__ void embed_kernel(const int* __restrict__ data, const float* __restrict__ embW,
                             float* __restrict__ core, bf16* __restrict__ ch,
                             bf16* __restrict__ cl, float* __restrict__ outm)
{
    long i = (long)blockIdx.x * 256 + threadIdx.x;
    if (i >= (long)ROWS * DM / 4) return;
    int r = (int)(i >> 8);
    float4 v = *(const float4*)(embW + (long)data[r] * DM + (i & 255) * 4);
    *(float4*)(core + i * 4) = v;
    *(float4*)(outm + i * 4) = v;
    pairstore4(ch, cl, i * 4, v.x, v.y, v.z, v.w);
}

__global__ void pos_kernel(bf16* __restrict__ ph, bf16* __restrict__ pl)
{
    long idx = (long)blockIdx.x * 256 + threadIdx.x;
    if (idx >= (long)KLEN * DM) return;
    int j = (int)(idx >> 10), d = (int)(idx & 1023);
    float p = (float)(KLEN - 1 - j);
    int t = (d < 512) ? d : d - 512;
    float invf = expf(-((2.0f * (float)t) / (float)DM) * logf(10000.0f));
    float a = p * invf;
    float x = (d < 512) ? sinf(a) : cosf(a);
    ph[idx] = __float2bfloat16(x);
    pl[idx] = __float2bfloat16(bres(x));
}

__global__ void ln_kernel(const float* __restrict__ x, const float* __restrict__ y,
                          const float* __restrict__ g, const float* __restrict__ b,
                          float* __restrict__ outf, bf16* __restrict__ oh,
                          bf16* __restrict__ ol, float* __restrict__ memsf)
{
    const int r = blockIdx.x, t = threadIdx.x;
    __shared__ float red[256];
    const long base = (long)r * DM + t * 4;
    float4 xv = *(const float4*)(x + base);
    float4 yv = *(const float4*)(y + base);
    float loc[4] = { xv.x + yv.x, xv.y + yv.y, xv.z + yv.z, xv.w + yv.w };
    float s = loc[0] + loc[1] + loc[2] + loc[3];
    red[t] = s; __syncthreads();
    for (int o = 128; o > 0; o >>= 1) { if (t < o) red[t] += red[t + o]; __syncthreads(); }
    const float mu = red[0] * (1.0f / DM);
    __syncthreads();
    float s2 = 0.f;
#pragma unroll
    for (int k = 0; k < 4; k++) { float d = loc[k] - mu; s2 += d * d; }
    red[t] = s2; __syncthreads();
    for (int o = 128; o > 0; o >>= 1) { if (t < o) red[t] += red[t + o]; __syncthreads(); }
    const float rstd = rsqrtf(red[0] * (1.0f / DM) + 1e-5f);
    float4 gv = *(const float4*)(g + t * 4);
    float4 bv = *(const float4*)(b + t * 4);
    float4 o4;
    o4.x = (loc[0] - mu) * rstd * gv.x + bv.x;
    o4.y = (loc[1] - mu) * rstd * gv.y + bv.y;
    o4.z = (loc[2] - mu) * rstd * gv.z + bv.z;
    o4.w = (loc[3] - mu) * rstd * gv.w + bv.w;
    *(float4*)(outf + base) = o4;
    if (memsf) *(float4*)(memsf + base) = o4;
    pairstore4(oh, ol, base, o4.x, o4.y, o4.z, o4.w);
}

__global__ void loss_final_kernel(const float2* __restrict__ lsp,
                                  const float* __restrict__ core,
                                  const float* __restrict__ embW,
                                  const int* __restrict__ target,
                                  float* __restrict__ out)
{
    const int r = blockIdx.x, t = threadIdx.x;
    __shared__ float rm[128], rs[128], rd[128];
    float m = -1e30f, s = 0.f;
    for (int j = t; j < NTOK / 128; j += 128) {
        float2 p = lsp[(long)r * NLSP + j];
        lse_comb(m, s, p.x, p.y);
    }
    const float* cr = core + (long)r * DM;
    const float* er = embW + (long)target[r] * DM;
    float d = 0.f;
    for (int j = t; j < DM / 4; j += 128) {
        float4 a = *(const float4*)(cr + j * 4);
        float4 b = *(const float4*)(er + j * 4);
        d += a.x * b.x + a.y * b.y + a.z * b.z + a.w * b.w;
    }
    rm[t] = m; rs[t] = s; rd[t] = d; __syncthreads();
    for (int o = 64; o > 0; o >>= 1) {
        if (t < o) {
            lse_comb(rm[t], rs[t], rm[t + o], rs[t + o]);
            rd[t] += rd[t + o];
        }
        __syncthreads();
    }
    if (t == 0) out[r] = (logf(rs[0]) + rm[0]) - rd[0];
}

// ---------------- host ----------------

#define S128 73728
#define GSA(p, s) cudaGetSymbolAddress((void**)&p, s)

static inline dim3 gt(int N, int M, int bz, int ntile) { return dim3(N / ntile, M / 128, bz); }

extern "C" void kernel_launch(void* const* d_in, const int* in_sizes, int n_in,
                              void* d_out, int out_size)
{
    const int*   data   = (const int*)  d_in[0];
    const int*   target = (const int*)  d_in[1];
    const float* memory = (const float*)d_in[2];
    const float* embW   = (const float*)d_in[3];
    const float* rwb    = (const float*)d_in[4];
    const float* rrb    = (const float*)d_in[5];
    const float* Wq     = (const float*)d_in[6];
    const float* Wkv    = (const float*)d_in[7];
    const float* Wr     = (const float*)d_in[8];
    const float* Wo     = (const float*)d_in[9];
    const float* W1     = (const float*)d_in[10];
    const float* b1     = (const float*)d_in[11];
    const float* W2     = (const float*)d_in[12];
    const float* b2     = (const float*)d_in[13];
    const float* ln1g   = (const float*)d_in[14];
    const float* ln1b   = (const float*)d_in[15];
    const float* ln2g   = (const float*)d_in[16];
    const float* ln2b   = (const float*)d_in[17];

    float* out      = (float*)d_out;
    float* out_loss = out;
    float* out_mems = out + ROWS;

    float *core, *tmp;
    __half* bd;
    float2* lsp;
    GSA(core, g_core); GSA(tmp, g_tmp); GSA(bd, g_bd); GSA(lsp, g_lsp);

    bf16 *hcore,*lcore,*hmem,*lmem,*hqrw,*lqrw,*hqrr,*lqrr,*hk,*lk,*hv,*lv,*hrk,*lrk,
         *hvec,*lvec,*hffh,*lffh,*hpos,*lpos,*hemb,*lemb,
         *hWkvT,*lWkvT,*hWqT,*lWqT,*hWrT,*lWrT,*hWoT,*lWoT,*hW1T,*lW1T,*hW2T,*lW2T;
    GSA(hcore,h_core); GSA(lcore,l_core); GSA(hmem,h_mem); GSA(lmem,l_mem);
    GSA(hqrw,h_qrw); GSA(lqrw,l_qrw); GSA(hqrr,h_qrr); GSA(lqrr,l_qrr);
    GSA(hk,h_kk); GSA(lk,l_kk); GSA(hv,h_vv); GSA(lv,l_vv);
    GSA(hrk,h_rk); GSA(lrk,l_rk);
    GSA(hvec,h_vec); GSA(lvec,l_vec); GSA(hffh,h_ffh); GSA(lffh,l_ffh);
    GSA(hpos,h_pos); GSA(lpos,l_pos); GSA(hemb,h_emb); GSA(lemb,l_emb);
    GSA(hWkvT,h_WkvT); GSA(lWkvT,l_WkvT); GSA(hWqT,h_WqT); GSA(lWqT,l_WqT);
    GSA(hWrT,h_WrT); GSA(lWrT,l_WrT); GSA(hWoT,h_WoT); GSA(lWoT,l_WoT);
    GSA(hW1T,h_W1T); GSA(lW1T,l_W1T); GSA(hW2T,h_W2T); GSA(lW2T,l_W2T);

    // smem opt-in for EVERY launched instantiation
    cudaFuncSetAttribute(pgemm<128,0,3>, cudaFuncAttributeMaxDynamicSharedMemorySize, S128);
    cudaFuncSetAttribute(pgemm<128,1,3>, cudaFuncAttributeMaxDynamicSharedMemorySize, S128);
    cudaFuncSetAttribute(pgemm<128,2,3>, cudaFuncAttributeMaxDynamicSharedMemorySize, S128);
    cudaFuncSetAttribute(pgemm<128,3,3>, cudaFuncAttributeMaxDynamicSharedMemorySize, S128);
    cudaFuncSetAttribute(pgemm<128,4,3>, cudaFuncAttributeMaxDynamicSharedMemorySize, S128);
    cudaFuncSetAttribute(pgemm<128,6,3>, cudaFuncAttributeMaxDynamicSharedMemorySize, S128);
    cudaFuncSetAttribute(pgemm<128,7,1>, cudaFuncAttributeMaxDynamicSharedMemorySize, S128);
    cudaFuncSetAttribute(pgemm<128,8,3>, cudaFuncAttributeMaxDynamicSharedMemorySize, S128);
    cudaFuncSetAttribute(fattn, cudaFuncAttributeMaxDynamicSharedMemorySize, FA_SMEM);

    const dim3 tb(8, 32);
    {
        long n1 = (long)NL*ROWS*DM/4;
        convert_pair<<<(int)((n1 + 255)/256), 256>>>(memory, hmem, lmem, n1);
        long n2 = (long)NTOK*DM/4;
        convert_pair<<<(int)((n2 + 255)/256), 256>>>(embW, hemb, lemb, n2);
    }
    embed_kernel<<<(ROWS*DM/4 + 255)/256, 256>>>(data, embW, core, hcore, lcore, out_mems);
    pos_kernel<<<(KLEN*DM + 255)/256, 256>>>(hpos, lpos);
    transpose_all<<<dim3(13312, NL), tb>>>(Wkv, Wq, Wr, Wo, W1, W2,
        hWkvT, lWkvT, hWqT, lWqT, hWrT, lWrT, hWoT, lWoT, hW1T, lW1T, hW2T, lW2T);

    // rk for ALL layers in one batched launch (z = layer): 384 CTAs vs 6x64
    pgemm<128,4,3><<<gt(HD, KLEN, NL, 128), 256, S128>>>(
        hpos, lpos, hWrT, lWrT,
        DM, DM, DM,
        0, 0, (long)HD*DM, 0, 1,
        HD, (long)KLEN*HD, 0,
        nullptr, hrk, lrk, nullptr, nullptr, nullptr, nullptr, nullptr, 0);

    for (int l = 0; l < NL; l++) {
        const bf16* hWkvl = hWkvT + (size_t)l*2*HD*DM;
        const bf16* lWkvl = lWkvT + (size_t)l*2*HD*DM;

        pgemm<128,6,3><<<gt(2*HD, ROWS, 1, 128), 256, S128>>>(
            hmem + (size_t)l*ROWS*DM, lmem + (size_t)l*ROWS*DM, hWkvl, lWkvl,
            DM, DM, DM, 0,0,0,0, 1, HD, 0,0,
            nullptr, hk, lk, hv, lv, nullptr, nullptr, nullptr, HD);
        pgemm<128,6,3><<<gt(2*HD, ROWS, 1, 128), 256, S128>>>(
            hcore, lcore, hWkvl, lWkvl,
            DM, DM, DM, 0,0,0,0, 1, HD, 0,0,
            nullptr, hk + (size_t)ROWS*HD, lk + (size_t)ROWS*HD,
            hv + (size_t)ROWS*HD, lv + (size_t)ROWS*HD, nullptr, nullptr, nullptr, HD);

        pgemm<128,3,3><<<gt(HD, ROWS, 1, 128), 256, S128>>>(
            hcore, lcore, hWqT + (size_t)l*HD*DM, lWqT + (size_t)l*HD*DM,
            DM, DM, DM, 0,0,0,0, 1, DM, 0,0,
            nullptr, hqrw, lqrw, hqrr, lqrr, rwb, rrb, nullptr, 0);

        // BD raw -> fp16 (batched over heads; causal tile skip in-kernel)
        pgemm<128,8,3><<<gt(KLEN, ROWS, NH, 128), 256, S128>>>(
            hqrr, lqrr, hrk + (size_t)l*KLEN*HD, lrk + (size_t)l*KLEN*HD,
            DH, DM, HD,
            0, (long)DH, 0, (long)DH, NH,
            KLEN, 0, (long)ROWS*KLEN,
            (float*)bd, nullptr, nullptr, nullptr, nullptr, nullptr, nullptr, nullptr, 0);

        fattn<<<dim3(QLEN/128, BSZ*NH), 256, FA_SMEM>>>(
            hqrw, lqrw, hk, lk, hv, lv, bd, hvec, lvec);

        pgemm<128,0,3><<<gt(DM, ROWS, 1, 128), 256, S128>>>(
            hvec, lvec, hWoT + (size_t)l*DM*HD, lWoT + (size_t)l*DM*HD,
            HD, HD, HD, 0,0,0,0, 1, DM, 0,0,
            tmp, nullptr, nullptr, nullptr, nullptr, nullptr, nullptr, nullptr, 0);

        ln_kernel<<<ROWS, 256>>>(core, tmp, ln1g + (size_t)l*DM, ln1b + (size_t)l*DM,
                                 core, hcore, lcore, nullptr);

        pgemm<128,2,3><<<gt(DI, ROWS, 1, 128), 256, S128>>>(
            hcore, lcore, hW1T + (size_t)l*DI*DM, lW1T + (size_t)l*DI*DM,
            DM, DM, DM, 0,0,0,0, 1, DI, 0,0,
            nullptr, hffh, lffh, nullptr, nullptr, b1 + (size_t)l*DI, nullptr, nullptr, 0);

        pgemm<128,1,3><<<gt(DM, ROWS, 1, 128), 256, S128>>>(
            hffh, lffh, hW2T + (size_t)l*DM*DI, lW2T + (size_t)l*DM*DI,
            DI, DI, DI, 0,0,0,0, 1, DM, 0,0,
            tmp, nullptr, nullptr, nullptr, nullptr, b2 + (size_t)l*DM, nullptr, nullptr, 0);

        ln_kernel<<<ROWS, 256>>>(core, tmp, ln2g + (size_t)l*DM, ln2b + (size_t)l*DM,
                                 core, hcore, lcore,
                                 (l < NL - 1) ? (out_mems + (size_t)(l + 1)*ROWS*DM) : nullptr);
    }

    pgemm<128,7,1><<<gt(NTOK, ROWS, 1, 128), 256, S128>>>(
        hcore, lcore, hemb, lemb,
        DM, DM, DM, 0,0,0,0, 1, 0, 0,0,
        (float*)lsp, nullptr, nullptr, nullptr, nullptr, nullptr, nullptr, nullptr, 0);
    loss_final_kernel<<<ROWS, 128>>>(lsp, core, embW, target, out_loss);

    (void)in_sizes; (void)n_in; (void)out_size;
}